// round 8
// baseline (speedup 1.0000x reference)
#include <cuda_runtime.h>
#include <cuda_bf16.h>
#include <math.h>
#include <stdint.h>

// ---------------------------------------------------------------------------
// RWKV-7 Tmix forward. B=4, T=2048, C=2048, H=32, N=64.
// R8: merged launches (big transposes, r/k/v GEMM batch, stage-2 batch),
// fork-join stream overlap, launch index 3 = big GEMM for ncu.
// ---------------------------------------------------------------------------

#define BB 4
#define TT 2048
#define CC 2048
#define HH 32
#define NN 64
#define BT (BB*TT)                       // 8192
#define BTC ((size_t)BT*(size_t)CC)      // 16777216

__device__ float g_pool[23ull * 16777216ull];

#define SL_XR 0
#define SL_XW 1
#define SL_XK 2
#define SL_XV 3
#define SL_XA 4
#define SL_XG 5
#define SL_R  6
#define SL_K  7
#define SL_VL 8
#define SL_G  9
#define SL_WD 10
#define SL_A  11
#define SL_S  12
#define SL_Y  19
#define SL_ZS 20
#define SL_SMALL 21
#define SL_WB  22

// ===========================================================================
// helpers
// ===========================================================================
__device__ __forceinline__ uint32_t smem_u32(const void* p) {
    uint32_t a;
    asm("{ .reg .u64 t; cvta.to.shared.u64 t, %1; cvt.u32.u64 %0, t; }"
        : "=r"(a) : "l"(p));
    return a;
}
__device__ __forceinline__ void cpasync16(uint32_t dst, const void* src) {
    asm volatile("cp.async.cg.shared.global [%0], [%1], 16;" :: "r"(dst), "l"(src));
}
__device__ __forceinline__ void ldsm4(uint32_t* r, uint32_t addr) {
    asm volatile("ldmatrix.sync.aligned.m8n8.x4.shared.b16 {%0,%1,%2,%3}, [%4];"
        : "=r"(r[0]), "=r"(r[1]), "=r"(r[2]), "=r"(r[3]) : "r"(addr));
}
__device__ __forceinline__ void mma16816(float* d, const uint32_t* a, const uint32_t* b) {
    asm volatile(
        "mma.sync.aligned.m16n8k16.row.col.f32.bf16.bf16.f32 "
        "{%0,%1,%2,%3}, {%4,%5,%6,%7}, {%8,%9}, {%0,%1,%2,%3};"
        : "+f"(d[0]), "+f"(d[1]), "+f"(d[2]), "+f"(d[3])
        : "r"(a[0]), "r"(a[1]), "r"(a[2]), "r"(a[3]), "r"(b[0]), "r"(b[1]));
}
__device__ __forceinline__ uint32_t pack_bf2(float a, float b) {
    __nv_bfloat162 t = __floats2bfloat162_rn(a, b);
    return *reinterpret_cast<uint32_t*>(&t);
}

// EPI: 0=none, 3=sigmoid(v+bias[n]), 4=decay transform with bias[n]
__device__ __forceinline__ float epi_rt(int epi, float v, float b) {
    if (epi == 3) {
        return 1.f / (1.f + expf(-(v + b)));
    } else if (epi == 4) {
        float z  = v + b;
        float sp = (z < -20.f) ? (-z) : log1pf(expf(-z));
        float w  = -sp - 0.5f;
        return expf(-expf(w));
    }
    return v;
}

// ===========================================================================
// GEMM core config (R5/R7 proven): CTA 128x128x32, 4-stage, warp 64x32.
// ===========================================================================
#define PADK 40
#define TILE_B (128*PADK*2)              // 10240
#define STG_B  (4*TILE_B)                // 40960
#define HSTAGES 4
#define HSMEM  (HSTAGES*STG_B)           // 163840

// shared device body: computes one 128x128 tile given pointers
template<int EPI_T>
__device__ __forceinline__ void hgemm_body(
    const __nv_bfloat16* __restrict__ Ah, const __nv_bfloat16* __restrict__ Al,
    const __nv_bfloat16* __restrict__ Bh, const __nv_bfloat16* __restrict__ Bl,
    float* __restrict__ C, int K, int lda, int Ntot,
    const float* __restrict__ bias, int epi_rt_code, char* sm)
{
    const int tid  = threadIdx.x;
    const int lane = tid & 31;
    const int wid  = tid >> 5;
    const int m0 = blockIdx.y * 128;
    const int n0 = blockIdx.x * 128;
    const int mw = (wid >> 2) * 64;
    const int nw = (wid & 3) * 32;
    const uint32_t sbase = smem_u32(sm);
    const int KT = K >> 5;

    float acc[4][4][4];
#pragma unroll
    for (int mt = 0; mt < 4; mt++)
#pragma unroll
        for (int nt = 0; nt < 4; nt++)
#pragma unroll
            for (int q = 0; q < 4; q++) acc[mt][nt][q] = 0.f;

    auto issue = [&](int kt, int stage) {
        const int k0 = kt << 5;
        const uint32_t sdst = sbase + stage * STG_B;
#pragma unroll
        for (int u = 0; u < 8; u++) {
            int i  = tid + u * 256;
            int op = i >> 9;
            int r  = (i & 511) >> 2;
            int c  = i & 3;
            const __nv_bfloat16* src;
            if (op == 0)      src = Ah + (size_t)(m0 + r) * lda + k0 + c * 8;
            else if (op == 1) src = Al + (size_t)(m0 + r) * lda + k0 + c * 8;
            else if (op == 2) src = Bh + (size_t)(n0 + r) * K + k0 + c * 8;
            else              src = Bl + (size_t)(n0 + r) * K + k0 + c * 8;
            cpasync16(sdst + op * TILE_B + r * (PADK*2) + c * 16, src);
        }
    };

#pragma unroll
    for (int s = 0; s < HSTAGES - 1; s++) {
        if (s < KT) issue(s, s);
        asm volatile("cp.async.commit_group;" ::: "memory");
    }

    const int grp = lane >> 3;
    const int l7  = lane & 7;

    for (int kt = 0; kt < KT; kt++) {
        asm volatile("cp.async.wait_group 2;" ::: "memory");
        __syncthreads();

        const int st = kt % HSTAGES;
        const uint32_t sAh = sbase + st * STG_B;
        const uint32_t sAl = sAh + TILE_B;
        const uint32_t sBh = sAh + 2 * TILE_B;
        const uint32_t sBl = sAh + 3 * TILE_B;

#pragma unroll
        for (int kk = 0; kk < 2; kk++) {
            const int ko = kk * 16;
            uint32_t ahf[4][4], alf[4][4], bhf[4][2], blf[4][2];
#pragma unroll
            for (int mt = 0; mt < 4; mt++) {
                int row = mw + mt * 16 + ((grp & 1) << 3) + l7;
                int kof = ko + ((grp & 2) << 2);
                uint32_t a = row * (PADK*2) + kof * 2;
                ldsm4(ahf[mt], sAh + a);
                ldsm4(alf[mt], sAl + a);
            }
#pragma unroll
            for (int np = 0; np < 2; np++) {
                int row = nw + np * 16 + ((grp >> 1) << 3) + l7;
                int kof = ko + ((grp & 1) << 3);
                uint32_t a = row * (PADK*2) + kof * 2;
                uint32_t t[4];
                ldsm4(t, sBh + a);
                bhf[np*2][0]   = t[0]; bhf[np*2][1]   = t[1];
                bhf[np*2+1][0] = t[2]; bhf[np*2+1][1] = t[3];
                ldsm4(t, sBl + a);
                blf[np*2][0]   = t[0]; blf[np*2][1]   = t[1];
                blf[np*2+1][0] = t[2]; blf[np*2+1][1] = t[3];
            }
#pragma unroll
            for (int mt = 0; mt < 4; mt++)
#pragma unroll
                for (int nt = 0; nt < 4; nt++) {
                    mma16816(acc[mt][nt], ahf[mt], bhf[nt]);
                    mma16816(acc[mt][nt], ahf[mt], blf[nt]);
                    mma16816(acc[mt][nt], alf[mt], bhf[nt]);
                }
        }

        int nkt = kt + HSTAGES - 1;
        if (nkt < KT) issue(nkt, nkt % HSTAGES);
        asm volatile("cp.async.commit_group;" ::: "memory");
    }

    const int r0 = lane >> 2;
    const int c0 = (lane & 3) * 2;
    const int epi = (EPI_T >= 0) ? EPI_T : epi_rt_code;
#pragma unroll
    for (int mt = 0; mt < 4; mt++) {
#pragma unroll
        for (int nt = 0; nt < 4; nt++) {
            int row = m0 + mw + mt * 16 + r0;
            int col = n0 + nw + nt * 8 + c0;
            float b0 = 0.f, b1 = 0.f;
            if (epi != 0) { b0 = bias[col]; b1 = bias[col + 1]; }
            float v0 = epi_rt(epi, acc[mt][nt][0], b0);
            float v1 = epi_rt(epi, acc[mt][nt][1], b1);
            float v2 = epi_rt(epi, acc[mt][nt][2], b0);
            float v3 = epi_rt(epi, acc[mt][nt][3], b1);
            *(float2*)(C + (size_t)row * Ntot + col)       = make_float2(v0, v1);
            *(float2*)(C + (size_t)(row + 8) * Ntot + col) = make_float2(v2, v3);
        }
    }
}

// single GEMM (gate, Wo)
template<int EPI>
__global__ void __launch_bounds__(256, 1)
hgemm(const __nv_bfloat16* __restrict__ Ah, const __nv_bfloat16* __restrict__ Al,
      const __nv_bfloat16* __restrict__ Bh, const __nv_bfloat16* __restrict__ Bl,
      float* __restrict__ C, int K, int lda, int Ntot, const float* __restrict__ bias)
{
    extern __shared__ char sm[];
    hgemm_body<EPI>(Ah, Al, Bh, Bl, C, K, lda, Ntot, bias, EPI, sm);
}

// batched r/k/v projections: z selects operand set. All K=lda=Ntot=CC, EPI=0.
__global__ void __launch_bounds__(256, 1)
hgemm_batch3(const __nv_bfloat16* Ah0, const __nv_bfloat16* Al0, float* C0,
             const __nv_bfloat16* Ah1, const __nv_bfloat16* Al1, float* C1,
             const __nv_bfloat16* Ah2, const __nv_bfloat16* Al2, float* C2,
             const __nv_bfloat16* Bh0, const __nv_bfloat16* Bl0,
             const __nv_bfloat16* Bh1, const __nv_bfloat16* Bl1,
             const __nv_bfloat16* Bh2, const __nv_bfloat16* Bl2)
{
    extern __shared__ char sm[];
    const __nv_bfloat16 *Ah, *Al, *Bh, *Bl; float* C;
    if (blockIdx.z == 0)      { Ah=Ah0; Al=Al0; Bh=Bh0; Bl=Bl0; C=C0; }
    else if (blockIdx.z == 1) { Ah=Ah1; Al=Al1; Bh=Bh1; Bl=Bl1; C=C1; }
    else                      { Ah=Ah2; Al=Al2; Bh=Bh2; Bl=Bl2; C=C2; }
    hgemm_body<0>(Ah, Al, Bh, Bl, C, CC, CC, CC, nullptr, 0, sm);
}

// batched stage-2 (td/aaa/mv): z selects K, epi, A col-offset, B, C, bias.
#define HCATN 320
__global__ void __launch_bounds__(256, 1)
hgemm_s2(const __nv_bfloat16* hcat_h, const __nv_bfloat16* hcat_l,
         const __nv_bfloat16* B0h, const __nv_bfloat16* B0l,
         const __nv_bfloat16* B1h, const __nv_bfloat16* B1l,
         const __nv_bfloat16* B2h, const __nv_bfloat16* B2l,
         float* C0, float* C1, float* C2,
         const float* bias0, const float* bias1, const float* bias2)
{
    extern __shared__ char sm[];
    int K, epi, aoff;
    const __nv_bfloat16 *Bh, *Bl; float* C; const float* bias;
    if (blockIdx.z == 0)      { K=64; epi=4; aoff=0;   Bh=B0h; Bl=B0l; C=C0; bias=bias0; }
    else if (blockIdx.z == 1) { K=64; epi=3; aoff=64;  Bh=B1h; Bl=B1l; C=C1; bias=bias1; }
    else                      { K=32; epi=3; aoff=256; Bh=B2h; Bl=B2l; C=C2; bias=bias2; }
    hgemm_body<-1>(hcat_h + aoff, hcat_l + aoff, Bh, Bl, C, K, HCATN, CC, bias, epi, sm);
}

// ===========================================================================
// Stage-1 fused LoRA GEMM: 5 column segments of W1cat[320][2048].
// ===========================================================================
#define S1_ATILE (128*PADK*2)
#define S1_BTILE (64*PADK*2)
#define S1_STG   (2*S1_ATILE + 2*S1_BTILE)
#define S1_SMEM  (3*S1_STG)

__global__ void __launch_bounds__(256, 1)
hgemm_s1(const __nv_bfloat16* __restrict__ xw_h, const __nv_bfloat16* __restrict__ xw_l,
         const __nv_bfloat16* __restrict__ xa_h, const __nv_bfloat16* __restrict__ xa_l,
         const __nv_bfloat16* __restrict__ xg_h, const __nv_bfloat16* __restrict__ xg_l,
         const __nv_bfloat16* __restrict__ xv_h, const __nv_bfloat16* __restrict__ xv_l,
         const __nv_bfloat16* __restrict__ W1h, const __nv_bfloat16* __restrict__ W1l,
         __nv_bfloat16* __restrict__ Hh, __nv_bfloat16* __restrict__ Hl)
{
    extern __shared__ char sm[];
    const int tid  = threadIdx.x;
    const int lane = tid & 31;
    const int wid  = tid >> 5;
    const int seg  = blockIdx.x;
    const int m0   = blockIdx.y * 128;
    const int n0w  = seg * 64;
    const uint32_t sbase = smem_u32(sm);

    const __nv_bfloat16* Ah;
    const __nv_bfloat16* Al;
    if (seg == 0)      { Ah = xw_h; Al = xw_l; }
    else if (seg == 1) { Ah = xa_h; Al = xa_l; }
    else if (seg <= 3) { Ah = xg_h; Al = xg_l; }
    else               { Ah = xv_h; Al = xv_l; }

    const int mw = (wid >> 1) * 32;
    const int nw = (wid & 1) * 32;

    float acc[2][4][4];
#pragma unroll
    for (int mt = 0; mt < 2; mt++)
#pragma unroll
        for (int nt = 0; nt < 4; nt++)
#pragma unroll
            for (int q = 0; q < 4; q++) acc[mt][nt][q] = 0.f;

    auto issue = [&](int kt, int stage) {
        const int k0 = kt << 5;
        const uint32_t sdst = sbase + stage * S1_STG;
#pragma unroll
        for (int u = 0; u < 6; u++) {
            int i = tid + u * 256;
            if (i < 1024) {
                int sp = i >> 9, r = (i >> 2) & 127, c = i & 3;
                const __nv_bfloat16* src = (sp ? Al : Ah) + (size_t)(m0 + r) * CC + k0 + c * 8;
                cpasync16(sdst + sp * S1_ATILE + r * (PADK*2) + c * 16, src);
            } else {
                int j = i - 1024;
                int sp = j >> 8, r = (j >> 2) & 63, c = j & 3;
                const __nv_bfloat16* src = (sp ? W1l : W1h) + (size_t)(n0w + r) * CC + k0 + c * 8;
                cpasync16(sdst + 2*S1_ATILE + sp * S1_BTILE + r * (PADK*2) + c * 16, src);
            }
        }
    };

#pragma unroll
    for (int s = 0; s < 2; s++) {
        issue(s, s);
        asm volatile("cp.async.commit_group;" ::: "memory");
    }

    const int grp = lane >> 3;
    const int l7  = lane & 7;
    const int KT = CC >> 5;

    for (int kt = 0; kt < KT; kt++) {
        asm volatile("cp.async.wait_group 1;" ::: "memory");
        __syncthreads();

        const int st = kt % 3;
        const uint32_t sAh = sbase + st * S1_STG;
        const uint32_t sAl = sAh + S1_ATILE;
        const uint32_t sBh = sAh + 2 * S1_ATILE;
        const uint32_t sBl = sBh + S1_BTILE;

#pragma unroll
        for (int kk = 0; kk < 2; kk++) {
            const int ko = kk * 16;
            uint32_t ahf[2][4], alf[2][4], bhf[4][2], blf[4][2];
#pragma unroll
            for (int mt = 0; mt < 2; mt++) {
                int row = mw + mt * 16 + ((grp & 1) << 3) + l7;
                int kof = ko + ((grp & 2) << 2);
                uint32_t a = row * (PADK*2) + kof * 2;
                ldsm4(ahf[mt], sAh + a);
                ldsm4(alf[mt], sAl + a);
            }
#pragma unroll
            for (int np = 0; np < 2; np++) {
                int row = nw + np * 16 + ((grp >> 1) << 3) + l7;
                int kof = ko + ((grp & 1) << 3);
                uint32_t a = row * (PADK*2) + kof * 2;
                uint32_t t[4];
                ldsm4(t, sBh + a);
                bhf[np*2][0]   = t[0]; bhf[np*2][1]   = t[1];
                bhf[np*2+1][0] = t[2]; bhf[np*2+1][1] = t[3];
                ldsm4(t, sBl + a);
                blf[np*2][0]   = t[0]; blf[np*2][1]   = t[1];
                blf[np*2+1][0] = t[2]; blf[np*2+1][1] = t[3];
            }
#pragma unroll
            for (int mt = 0; mt < 2; mt++)
#pragma unroll
                for (int nt = 0; nt < 4; nt++) {
                    mma16816(acc[mt][nt], ahf[mt], bhf[nt]);
                    mma16816(acc[mt][nt], ahf[mt], blf[nt]);
                    mma16816(acc[mt][nt], alf[mt], bhf[nt]);
                }
        }

        int nkt = kt + 2;
        if (nkt < KT) issue(nkt, nkt % 3);
        asm volatile("cp.async.commit_group;" ::: "memory");
    }

    const int r0 = lane >> 2;
    const int c0 = (lane & 3) * 2;
#pragma unroll
    for (int mt = 0; mt < 2; mt++) {
#pragma unroll
        for (int nt = 0; nt < 4; nt++) {
            float v[4];
#pragma unroll
            for (int q = 0; q < 4; q++) {
                float t = acc[mt][nt][q];
                if (seg == 0)              t = tanhf(t);
                else if (seg == 2 || seg == 3) t = 1.f / (1.f + expf(-t));
                v[q] = t;
            }
            int row = m0 + mw + mt * 16 + r0;
            int col = seg * 64 + nw + nt * 8 + c0;
            float h0 = __bfloat162float(__float2bfloat16(v[0]));
            float h1 = __bfloat162float(__float2bfloat16(v[1]));
            float h2 = __bfloat162float(__float2bfloat16(v[2]));
            float h3 = __bfloat162float(__float2bfloat16(v[3]));
            *(uint32_t*)&Hh[(size_t)row * HCATN + col]       = pack_bf2(v[0], v[1]);
            *(uint32_t*)&Hl[(size_t)row * HCATN + col]       = pack_bf2(v[0]-h0, v[1]-h1);
            *(uint32_t*)&Hh[(size_t)(row+8) * HCATN + col]   = pack_bf2(v[2], v[3]);
            *(uint32_t*)&Hl[(size_t)(row+8) * HCATN + col]   = pack_bf2(v[2]-h2, v[3]-h3);
        }
    }
}

// ===========================================================================
// Weight transpose + split: W[K][N] fp32 -> Th/Tl[N][K] bf16
// ===========================================================================
__device__ __forceinline__ void transpose_body(const float* __restrict__ W,
                                               __nv_bfloat16* __restrict__ Th,
                                               __nv_bfloat16* __restrict__ Tl,
                                               int K, int N)
{
    __shared__ float tile[32][33];
    int bx = blockIdx.x * 32;
    int by = blockIdx.y * 32;
#pragma unroll
    for (int j = 0; j < 32; j += 8)
        tile[threadIdx.y + j][threadIdx.x] =
            W[(size_t)(by + threadIdx.y + j) * N + bx + threadIdx.x];
    __syncthreads();
#pragma unroll
    for (int j = 0; j < 32; j += 8) {
        float v = tile[threadIdx.x][threadIdx.y + j];
        int n = bx + threadIdx.y + j;
        int k = by + threadIdx.x;
        __nv_bfloat16 h = __float2bfloat16(v);
        Th[(size_t)n * K + k] = h;
        Tl[(size_t)n * K + k] = __float2bfloat16(v - __bfloat162float(h));
    }
}

__global__ void transpose_split(const float* __restrict__ W,
                                __nv_bfloat16* __restrict__ Th,
                                __nv_bfloat16* __restrict__ Tl, int K, int N)
{
    transpose_body(W, Th, Tl, K, N);
}

// merged 4 big 2048x2048 weight transposes, z-select
__global__ void transpose_big4(const float* W0, const float* W1_, const float* W2_, const float* W3_,
                               __nv_bfloat16* h0, __nv_bfloat16* l0,
                               __nv_bfloat16* h1, __nv_bfloat16* l1,
                               __nv_bfloat16* h2, __nv_bfloat16* l2,
                               __nv_bfloat16* h3, __nv_bfloat16* l3)
{
    const float* W; __nv_bfloat16 *Th, *Tl;
    if (blockIdx.z == 0)      { W = W0;  Th = h0; Tl = l0; }
    else if (blockIdx.z == 1) { W = W1_; Th = h1; Tl = l1; }
    else if (blockIdx.z == 2) { W = W2_; Th = h2; Tl = l2; }
    else                      { W = W3_; Th = h3; Tl = l3; }
    transpose_body(W, Th, Tl, CC, CC);
}

// ---------------------------------------------------------------------------
// Token-shift mixing, fused bf16 hi/lo split output for all 6 streams.
// ---------------------------------------------------------------------------
__global__ void mix_split_kernel(const float* __restrict__ x,
    const float* __restrict__ mr, const float* __restrict__ mw,
    const float* __restrict__ mk, const float* __restrict__ mv,
    const float* __restrict__ ma, const float* __restrict__ mg,
    __nv_bfloat16* __restrict__ rh, __nv_bfloat16* __restrict__ rl,
    __nv_bfloat16* __restrict__ wh, __nv_bfloat16* __restrict__ wl,
    __nv_bfloat16* __restrict__ kh, __nv_bfloat16* __restrict__ kl,
    __nv_bfloat16* __restrict__ vh, __nv_bfloat16* __restrict__ vl,
    __nv_bfloat16* __restrict__ ah, __nv_bfloat16* __restrict__ al,
    __nv_bfloat16* __restrict__ gh, __nv_bfloat16* __restrict__ gl)
{
    size_t i = (size_t)blockIdx.x * blockDim.x + threadIdx.x;
    size_t n4 = BTC / 4;
    if (i >= n4) return;
    size_t e = i * 4;
    int c  = (int)(e % CC);
    int bt = (int)(e / CC);
    int t  = bt % TT;

    float4 xc = ((const float4*)x)[i];
    float4 xp = make_float4(0.f, 0.f, 0.f, 0.f);
    if (t > 0) xp = ((const float4*)x)[i - CC/4];
    float4 xx = make_float4(xp.x-xc.x, xp.y-xc.y, xp.z-xc.z, xp.w-xc.w);

    int c4 = c / 4;
#define DOMIX(MV, OH, OL) { \
        float4 m = ((const float4*)MV)[c4]; \
        float4 o = make_float4(xc.x + xx.x*m.x, xc.y + xx.y*m.y, \
                               xc.z + xx.z*m.z, xc.w + xx.w*m.w); \
        float h0 = __bfloat162float(__float2bfloat16(o.x)); \
        float h1 = __bfloat162float(__float2bfloat16(o.y)); \
        float h2 = __bfloat162float(__float2bfloat16(o.z)); \
        float h3 = __bfloat162float(__float2bfloat16(o.w)); \
        ((uint2*)OH)[i] = make_uint2(pack_bf2(o.x, o.y), pack_bf2(o.z, o.w)); \
        ((uint2*)OL)[i] = make_uint2(pack_bf2(o.x-h0, o.y-h1), pack_bf2(o.z-h2, o.w-h3)); }
    DOMIX(mr, rh, rl); DOMIX(mw, wh, wl); DOMIX(mk, kh, kl);
    DOMIX(mv, vh, vl); DOMIX(ma, ah, al); DOMIX(mg, gh, gl);
#undef DOMIX
}

// ---------------------------------------------------------------------------
__device__ __forceinline__ float warp_sum(float v) {
#pragma unroll
    for (int o = 16; o > 0; o >>= 1) v += __shfl_xor_sync(0xffffffffu, v, o);
    return v;
}

// ---------------------------------------------------------------------------
// WKV7 recurrence with fused prep. 256 threads/block, one block per (b,h).
// ---------------------------------------------------------------------------
__global__ void __launch_bounds__(256)
wkv7_kernel(const float* __restrict__ r_,  const float* __restrict__ wd_,
            const float* __restrict__ k_,  const float* __restrict__ a_,
            const float* __restrict__ vl_, const float* __restrict__ s_,
            const float* __restrict__ v0_,
            const float* __restrict__ misc_kkk, const float* __restrict__ misc_a,
            float* __restrict__ yT)
{
    __shared__ __align__(16) float sb[2*392];
    const int bh  = blockIdx.x;
    const int b   = bh >> 5, h = bh & 31;
    const int tid = threadIdx.x;
    const int tg  = tid >> 6;
    const int n   = tid & 63;
    const int row = tid >> 2;
    const int cg  = tid & 3;
    const int cb  = cg * 16;
    const size_t src0  = ((size_t)b * TT) * CC + (size_t)h * NN + n;
    const size_t ybase = (size_t)bh * TT * NN;

    const float* pA;
    const float* pB = nullptr;
    const float* pC = nullptr;
    float ma = 0.f, mkk = 0.f;
    if (tg == 0)      pA = r_  + src0;
    else if (tg == 1) pA = wd_ + src0;
    else if (tg == 2) { pA = k_ + src0; pB = a_ + src0;
                        mkk = misc_kkk[h*NN+n]; ma = misc_a[h*NN+n]; }
    else              { pA = vl_ + src0; pB = s_ + src0; pC = v0_ + src0; }

    float st[16];
#pragma unroll
    for (int j = 0; j < 16; j++) st[j] = 0.f;

    {
        float va = pA[0];
        if (tg == 0)      sb[0*64+n] = va;
        else if (tg == 1) sb[1*64+n] = va;
        else if (tg == 2) {
            float vb = pB[0];
            float kk = va * mkk;
            sb[2*64+n] = va * fmaf(vb - 1.f, ma, 1.f);
            sb[4*64+n] = -kk;
            sb[5*64+n] = kk * vb;
            float wsum = warp_sum(kk*kk);
            if ((tid & 31) == 0) sb[384 + ((tid >> 5) & 1)] = wsum;
        } else {
            float vb = pB[0], vc = pC[0];
            sb[3*64+n] = va + (vc - va) * vb;
        }
    }
    __syncthreads();

    int cur = 0;
    for (int t = 0; t < TT; t++) {
        float fa = 0.f, fb = 0.f, fc = 0.f;
        if (t + 1 < TT) {
            size_t o = (size_t)(t + 1) * CC;
            fa = pA[o];
            if (tg >= 2) fb = pB[o];
            if (tg == 3) fc = pC[o];
        }

        const float* base = &sb[cur * 392];
        float ssq  = base[384] + base[385];
        float invn = 1.f / fmaxf(sqrtf(ssq), 1e-12f);
        float f2   = invn * invn;

        const float4* r4p = (const float4*)(base + 0*64 + cb);
        const float4* w4p = (const float4*)(base + 1*64 + cb);
        const float4* k4p = (const float4*)(base + 2*64 + cb);
        const float4* a4p = (const float4*)(base + 4*64 + cb);
        const float4* b4p = (const float4*)(base + 5*64 + cb);
        const float vi = base[3*64 + row];

        float c0=0.f, c1=0.f, c2=0.f, c3=0.f;
#pragma unroll
        for (int q = 0; q < 4; q++) {
            float4 a4 = a4p[q];
            c0 = fmaf(st[q*4+0], a4.x, c0);
            c1 = fmaf(st[q*4+1], a4.y, c1);
            c2 = fmaf(st[q*4+2], a4.z, c2);
            c3 = fmaf(st[q*4+3], a4.w, c3);
        }
        float sai = (c0 + c1) + (c2 + c3);
        sai += __shfl_xor_sync(0xffffffffu, sai, 1);
        sai += __shfl_xor_sync(0xffffffffu, sai, 2);
        sai *= f2;

        float y0=0.f, y1=0.f, y2=0.f, y3=0.f;
#pragma unroll
        for (int q = 0; q < 4; q++) {
            float4 w4 = w4p[q], b4 = b4p[q], k4 = k4p[q], r4 = r4p[q];
            float t0 = fmaf(sai, b4.x, fmaf(vi, k4.x, st[q*4+0]*w4.x));
            float t1 = fmaf(sai, b4.y, fmaf(vi, k4.y, st[q*4+1]*w4.y));
            float t2 = fmaf(sai, b4.z, fmaf(vi, k4.z, st[q*4+2]*w4.z));
            float t3 = fmaf(sai, b4.w, fmaf(vi, k4.w, st[q*4+3]*w4.w));
            st[q*4+0] = t0; st[q*4+1] = t1; st[q*4+2] = t2; st[q*4+3] = t3;
            y0 = fmaf(t0, r4.x, y0);
            y1 = fmaf(t1, r4.y, y1);
            y2 = fmaf(t2, r4.z, y2);
            y3 = fmaf(t3, r4.w, y3);
        }
        float yp = (y0 + y1) + (y2 + y3);
        yp += __shfl_xor_sync(0xffffffffu, yp, 1);
        yp += __shfl_xor_sync(0xffffffffu, yp, 2);
        if (cg == 0) yT[ybase + (size_t)t * NN + row] = yp;

        int nxt = cur ^ 1;
        if (t + 1 < TT) {
            float* d = &sb[nxt * 392];
            if (tg == 0)      d[0*64+n] = fa;
            else if (tg == 1) d[1*64+n] = fa;
            else if (tg == 2) {
                float kk = fa * mkk;
                d[2*64+n] = fa * fmaf(fb - 1.f, ma, 1.f);
                d[4*64+n] = -kk;
                d[5*64+n] = kk * fb;
                float wsum = warp_sum(kk*kk);
                if ((tid & 31) == 0) d[384 + ((tid >> 5) & 1)] = wsum;
            } else {
                d[3*64+n] = fa + (fc - fa) * fb;
            }
        }
        __syncthreads();
        cur = nxt;
    }
}

// ---------------------------------------------------------------------------
// GroupNorm + bonus + gate (prep transforms recomputed inline).
// ---------------------------------------------------------------------------
__global__ void post_kernel(const float* __restrict__ yT,
                            const float* __restrict__ r_, const float* __restrict__ k_,
                            const float* __restrict__ a_, const float* __restrict__ vl_,
                            const float* __restrict__ s_, const float* __restrict__ v0_,
                            const float* __restrict__ g,  const float* __restrict__ faaaa,
                            const float* __restrict__ misc_a,
                            const float* __restrict__ lnw, const float* __restrict__ lnb,
                            __nv_bfloat16* __restrict__ zh, __nv_bfloat16* __restrict__ zl)
{
    int gw   = (blockIdx.x * blockDim.x + threadIdx.x) >> 5;
    int lane = threadIdx.x & 31;
    if (gw >= BT * HH) return;
    int h  = gw % HH;
    int bt = gw / HH;
    int b  = bt / TT, t = bt % TT;

    size_t src = (size_t)bt * CC + (size_t)h * NN;
    size_t dst = (((size_t)(b*HH + h)) * TT + t) * NN;
    int n0 = lane, n1 = lane + 32;
    int c0 = h*NN + n0, c1 = h*NN + n1;

    float y0 = yT[dst+n0], y1 = yT[dst+n1];
    float sum = warp_sum(y0 + y1);
    float sq  = warp_sum(y0*y0 + y1*y1);
    float mu  = sum * (1.f/64.f);
    float var = sq * (1.f/64.f) - mu*mu;
    float rs  = rsqrtf(var + 6.4e-4f);

    float k0 = k_[src+n0], k1 = k_[src+n1];
    float a0 = a_[src+n0], a1 = a_[src+n1];
    float fk0 = k0 * fmaf(a0 - 1.f, misc_a[c0], 1.f);
    float fk1 = k1 * fmaf(a1 - 1.f, misc_a[c1], 1.f);
    float rk = r_[src+n0]*fk0*faaaa[c0] + r_[src+n1]*fk1*faaaa[c1];
    float srk = warp_sum(rk);

    float vv0 = vl_[src+n0], vv1 = vl_[src+n1];
    float fv0 = vv0 + (v0_[src+n0] - vv0) * s_[src+n0];
    float fv1 = vv1 + (v0_[src+n1] - vv1) * s_[src+n1];

    float z0 = ((y0 - mu)*rs*lnw[c0] + lnb[c0] + srk*fv0) * g[src+n0];
    float z1 = ((y1 - mu)*rs*lnw[c1] + lnb[c1] + srk*fv1) * g[src+n1];
    __nv_bfloat16 h0 = __float2bfloat16(z0);
    __nv_bfloat16 h1 = __float2bfloat16(z1);
    zh[src+n0] = h0; zh[src+n1] = h1;
    zl[src+n0] = __float2bfloat16(z0 - __bfloat162float(h0));
    zl[src+n1] = __float2bfloat16(z1 - __bfloat162float(h1));
}

__global__ void copy4_kernel(const float* __restrict__ src, float* __restrict__ dst,
                             size_t n4)
{
    size_t i = (size_t)blockIdx.x * blockDim.x + threadIdx.x;
    if (i < n4) ((float4*)dst)[i] = ((const float4*)src)[i];
}

// ---------------------------------------------------------------------------
// launch
// ---------------------------------------------------------------------------
extern "C" void kernel_launch(void* const* d_in, const int* in_sizes, int n_in,
                              void* d_out, int out_size)
{
    const float* x         = (const float*)d_in[0];
    const float* v0        = (const float*)d_in[1];
    const float* maa_r     = (const float*)d_in[2];
    const float* maa_w     = (const float*)d_in[3];
    const float* maa_k     = (const float*)d_in[4];
    const float* maa_v     = (const float*)d_in[5];
    const float* maa_a     = (const float*)d_in[6];
    const float* maa_g     = (const float*)d_in[7];
    const float* time_decay= (const float*)d_in[8];
    const float* faaaa     = (const float*)d_in[9];
    const float* time_aaaaa= (const float*)d_in[10];
    const float* td_w1     = (const float*)d_in[11];
    const float* td_w2     = (const float*)d_in[12];
    const float* aaa_w1    = (const float*)d_in[13];
    const float* aaa_w2    = (const float*)d_in[14];
    const float* gate_w1   = (const float*)d_in[15];
    const float* gate_w2   = (const float*)d_in[16];
    const float* mv_w1     = (const float*)d_in[17];
    const float* mv_w2     = (const float*)d_in[18];
    const float* misc_v    = (const float*)d_in[19];
    const float* misc_kkk  = (const float*)d_in[20];
    const float* misc_a    = (const float*)d_in[21];
    const float* Wr        = (const float*)d_in[22];
    const float* Wk        = (const float*)d_in[23];
    const float* Wv        = (const float*)d_in[24];
    const float* Wo        = (const float*)d_in[25];
    const float* ln_w      = (const float*)d_in[26];
    const float* ln_b      = (const float*)d_in[27];

    float* pool = nullptr;
    cudaGetSymbolAddress((void**)&pool, g_pool);

    __nv_bfloat16* xr_h = (__nv_bfloat16*)(pool + (size_t)SL_XR * BTC);
    __nv_bfloat16* xr_l = xr_h + BTC;
    __nv_bfloat16* xw_h = (__nv_bfloat16*)(pool + (size_t)SL_XW * BTC);
    __nv_bfloat16* xw_l = xw_h + BTC;
    __nv_bfloat16* xk_h = (__nv_bfloat16*)(pool + (size_t)SL_XK * BTC);
    __nv_bfloat16* xk_l = xk_h + BTC;
    __nv_bfloat16* xv_h = (__nv_bfloat16*)(pool + (size_t)SL_XV * BTC);
    __nv_bfloat16* xv_l = xv_h + BTC;
    __nv_bfloat16* xa_h = (__nv_bfloat16*)(pool + (size_t)SL_XA * BTC);
    __nv_bfloat16* xa_l = xa_h + BTC;
    __nv_bfloat16* xg_h = (__nv_bfloat16*)(pool + (size_t)SL_XG * BTC);
    __nv_bfloat16* xg_l = xg_h + BTC;

    float* r_ = pool + (size_t)SL_R  * BTC;
    float* k_ = pool + (size_t)SL_K  * BTC;
    float* vl = pool + (size_t)SL_VL * BTC;
    float* g_ = pool + (size_t)SL_G  * BTC;
    float* wd = pool + (size_t)SL_WD * BTC;
    float* a_ = pool + (size_t)SL_A  * BTC;
    float* s_ = pool + (size_t)SL_S  * BTC;
    float* yT = pool + (size_t)SL_Y  * BTC;
    __nv_bfloat16* z_h = (__nv_bfloat16*)(pool + (size_t)SL_ZS * BTC);
    __nv_bfloat16* z_l = z_h + BTC;

    __nv_bfloat16* sb16 = (__nv_bfloat16*)(pool + (size_t)SL_SMALL * BTC);
    __nv_bfloat16* hcat_h = sb16;
    __nv_bfloat16* hcat_l = hcat_h + (size_t)BT * HCATN;
    __nv_bfloat16* W1h    = hcat_l + (size_t)BT * HCATN;
    __nv_bfloat16* W1l    = W1h + (size_t)HCATN * CC;
    __nv_bfloat16* tdw_h  = W1l + (size_t)HCATN * CC;
    __nv_bfloat16* tdw_l  = tdw_h  + (size_t)CC * 64;
    __nv_bfloat16* aaaw_h = tdw_l  + (size_t)CC * 64;
    __nv_bfloat16* aaaw_l = aaaw_h + (size_t)CC * 64;
    __nv_bfloat16* gatew_h= aaaw_l + (size_t)CC * 64;
    __nv_bfloat16* gatew_l= gatew_h+ (size_t)CC * 128;
    __nv_bfloat16* mvw_h  = gatew_l+ (size_t)CC * 128;
    __nv_bfloat16* mvw_l  = mvw_h  + (size_t)CC * 32;

    __nv_bfloat16* wb = (__nv_bfloat16*)(pool + (size_t)SL_WB * BTC);
    const size_t WSZ = (size_t)CC * CC;
    __nv_bfloat16* Wr_h = wb;            __nv_bfloat16* Wr_l = wb + WSZ;
    __nv_bfloat16* Wk_h = wb + 2*WSZ;    __nv_bfloat16* Wk_l = wb + 3*WSZ;
    __nv_bfloat16* Wv_h = wb + 4*WSZ;    __nv_bfloat16* Wv_l = wb + 5*WSZ;
    __nv_bfloat16* Wo_h = wb + 6*WSZ;    __nv_bfloat16* Wo_l = wb + 7*WSZ;

    cudaFuncSetAttribute(hgemm<0>, cudaFuncAttributeMaxDynamicSharedMemorySize, HSMEM);
    cudaFuncSetAttribute(hgemm_batch3, cudaFuncAttributeMaxDynamicSharedMemorySize, HSMEM);
    cudaFuncSetAttribute(hgemm_s2, cudaFuncAttributeMaxDynamicSharedMemorySize, HSMEM);
    cudaFuncSetAttribute(hgemm_s1, cudaFuncAttributeMaxDynamicSharedMemorySize, S1_SMEM);

    // streams/events (created once, outside graph capture on the first call)
    static cudaStream_t s2 = nullptr;
    static cudaEvent_t evA = nullptr, evB = nullptr, evC = nullptr, evD = nullptr;
    if (!s2) {
        cudaStreamCreateWithFlags(&s2, cudaStreamNonBlocking);
        cudaEventCreateWithFlags(&evA, cudaEventDisableTiming);
        cudaEventCreateWithFlags(&evB, cudaEventDisableTiming);
        cudaEventCreateWithFlags(&evC, cudaEventDisableTiming);
        cudaEventCreateWithFlags(&evD, cudaEventDisableTiming);
    }

    dim3 tb(32, 8);
    size_t n4 = BTC / 4;

    // k0: merged big weight transposes (Wr, Wk, Wv, Wo)
    transpose_big4<<<dim3(CC/32, CC/32, 4), tb>>>(
        Wr, Wk, Wv, Wo,
        Wr_h, Wr_l, Wk_h, Wk_l, Wv_h, Wv_l, Wo_h, Wo_l);

    // k1: token-shift mixing + split
    mix_split_kernel<<<(unsigned)((n4 + 255) / 256), 256>>>(
        x, maa_r, maa_w, maa_k, maa_v, maa_a, maa_g,
        xr_h, xr_l, xw_h, xw_l, xk_h, xk_l, xv_h, xv_l, xa_h, xa_l, xg_h, xg_l);

    // k2: v0 passthrough into second output half (independent)
    if ((size_t)out_size >= 2 * BTC) {
        copy4_kernel<<<(unsigned)((n4 + 255) / 256), 256>>>(
            v0, (float*)d_out + BTC, n4);
    } else {
        copy4_kernel<<<1, 256>>>(v0, pool + (size_t)SL_R * BTC, 0);  // keep index stable
    }

    // fork: side stream does the 8 small transposes under the big GEMM batch
    cudaEventRecord(evA, 0);

    // k3: merged big projections r/k/v  (ncu -s 5 lands here)
    hgemm_batch3<<<dim3(CC/128, BT/128, 3), 256, HSMEM>>>(
        xr_h, xr_l, r_,  xk_h, xk_l, k_,  xv_h, xv_l, vl,
        Wr_h, Wr_l, Wk_h, Wk_l, Wv_h, Wv_l);

    // k4..k11 (stream s2): small weight transposes
    cudaStreamWaitEvent(s2, evA, 0);
    transpose_split<<<dim3(64/32,  CC/32), tb, 0, s2>>>(td_w1,   W1h,                 W1l,                 CC, 64);
    transpose_split<<<dim3(64/32,  CC/32), tb, 0, s2>>>(aaa_w1,  W1h + (size_t)64*CC, W1l + (size_t)64*CC, CC, 64);
    transpose_split<<<dim3(128/32, CC/32), tb, 0, s2>>>(gate_w1, W1h + (size_t)128*CC,W1l + (size_t)128*CC,CC, 128);
    transpose_split<<<dim3(32/32,  CC/32), tb, 0, s2>>>(mv_w1,   W1h + (size_t)256*CC,W1l + (size_t)256*CC,CC, 32);
    transpose_split<<<dim3(CC/32, 64/32),  tb, 0, s2>>>(td_w2,  tdw_h,  tdw_l,  64,  CC);
    transpose_split<<<dim3(CC/32, 64/32),  tb, 0, s2>>>(aaa_w2, aaaw_h, aaaw_l, 64,  CC);
    transpose_split<<<dim3(CC/32, 128/32), tb, 0, s2>>>(gate_w2,gatew_h,gatew_l,128, CC);
    transpose_split<<<dim3(CC/32, 32/32),  tb, 0, s2>>>(mv_w2,  mvw_h,  mvw_l,  32,  CC);
    cudaEventRecord(evB, s2);
    cudaStreamWaitEvent(0, evB, 0);

    // k12: stage-1 fused LoRA GEMM (needs mix + W1 transposes)
    hgemm_s1<<<dim3(5, BT/128), 256, S1_SMEM>>>(
        xw_h, xw_l, xa_h, xa_l, xg_h, xg_l, xv_h, xv_l, W1h, W1l, hcat_h, hcat_l);
    cudaEventRecord(evC, 0);

    // k13: merged stage-2 (td, aaa, mv) -> wd, a_, s_
    hgemm_s2<<<dim3(CC/128, BT/128, 3), 256, HSMEM>>>(
        hcat_h, hcat_l,
        tdw_h, tdw_l, aaaw_h, aaaw_l, mvw_h, mvw_l,
        wd, a_, s_, time_decay, time_aaaaa, misc_v);

    // k14: WKV7 recurrence (prep fused into staging)
    wkv7_kernel<<<BB*HH, 256>>>(r_, wd, k_, a_, vl, s_, v0, misc_kkk, misc_a, yT);

    // k15 (stream s2): gate stage-2 GEMM, overlaps stage-2/wkv7
    cudaStreamWaitEvent(s2, evC, 0);
    hgemm<0><<<dim3(CC/128, BT/128), 256, HSMEM, s2>>>(
        hcat_h+128, hcat_l+128, gatew_h, gatew_l, g_, 128, HCATN, CC, nullptr);
    cudaEventRecord(evD, s2);
    cudaStreamWaitEvent(0, evD, 0);

    // k16: groupnorm + bonus + gate -> z split
    post_kernel<<<(BT*HH)/8, 256>>>(yT, r_, k_, a_, vl, s_, v0, g_, faaaa,
                                    misc_a, ln_w, ln_b, z_h, z_l);

    // k17: output projection directly into d_out
    hgemm<0><<<dim3(CC/128, BT/128), 256, HSMEM>>>(
        z_h, z_l, Wo_h, Wo_l, (float*)d_out, CC, CC, CC, nullptr);
}

// round 9
// speedup vs baseline: 3.0657x; 3.0657x over previous
#include <cuda_runtime.h>
#include <cuda_bf16.h>
#include <math.h>
#include <stdint.h>

// ---------------------------------------------------------------------------
// RWKV-7 Tmix forward. B=4, T=2048, C=2048, H=32, N=64.
// R9: single stream (revert R8 streams). hgemm: 2-stage double buffer,
// 80KB smem, 2 CTAs/SM via __launch_bounds__(256,2), B-frags consumed inline.
// ---------------------------------------------------------------------------

#define BB 4
#define TT 2048
#define CC 2048
#define HH 32
#define NN 64
#define BT (BB*TT)                       // 8192
#define BTC ((size_t)BT*(size_t)CC)      // 16777216

__device__ float g_pool[23ull * 16777216ull];

#define SL_XR 0
#define SL_XW 1
#define SL_XK 2
#define SL_XV 3
#define SL_XA 4
#define SL_XG 5
#define SL_R  6
#define SL_K  7
#define SL_VL 8
#define SL_G  9
#define SL_WD 10
#define SL_A  11
#define SL_S  12
#define SL_Y  19
#define SL_ZS 20
#define SL_SMALL 21
#define SL_WB  22

// ===========================================================================
// helpers
// ===========================================================================
__device__ __forceinline__ uint32_t smem_u32(const void* p) {
    uint32_t a;
    asm("{ .reg .u64 t; cvta.to.shared.u64 t, %1; cvt.u32.u64 %0, t; }"
        : "=r"(a) : "l"(p));
    return a;
}
__device__ __forceinline__ void cpasync16(uint32_t dst, const void* src) {
    asm volatile("cp.async.cg.shared.global [%0], [%1], 16;" :: "r"(dst), "l"(src));
}
__device__ __forceinline__ void ldsm4(uint32_t* r, uint32_t addr) {
    asm volatile("ldmatrix.sync.aligned.m8n8.x4.shared.b16 {%0,%1,%2,%3}, [%4];"
        : "=r"(r[0]), "=r"(r[1]), "=r"(r[2]), "=r"(r[3]) : "r"(addr));
}
__device__ __forceinline__ void mma16816(float* d, const uint32_t* a, const uint32_t* b) {
    asm volatile(
        "mma.sync.aligned.m16n8k16.row.col.f32.bf16.bf16.f32 "
        "{%0,%1,%2,%3}, {%4,%5,%6,%7}, {%8,%9}, {%0,%1,%2,%3};"
        : "+f"(d[0]), "+f"(d[1]), "+f"(d[2]), "+f"(d[3])
        : "r"(a[0]), "r"(a[1]), "r"(a[2]), "r"(a[3]), "r"(b[0]), "r"(b[1]));
}
__device__ __forceinline__ uint32_t pack_bf2(float a, float b) {
    __nv_bfloat162 t = __floats2bfloat162_rn(a, b);
    return *reinterpret_cast<uint32_t*>(&t);
}

// EPI: 0=none, 3=sigmoid(v+bias[n]), 4=decay transform with bias[n]
__device__ __forceinline__ float epi_rt(int epi, float v, float b) {
    if (epi == 3) {
        return 1.f / (1.f + expf(-(v + b)));
    } else if (epi == 4) {
        float z  = v + b;
        float sp = (z < -20.f) ? (-z) : log1pf(expf(-z));
        float w  = -sp - 0.5f;
        return expf(-expf(w));
    }
    return v;
}

// ===========================================================================
// GEMM core: CTA 128x128x32, 2-stage double buffer, warp 64x32 (2x4 warps),
// 2 CTAs/SM. D = Ah*Bh + Ah*Bl + Al*Bh, fp32 accum.
// ===========================================================================
#define PADK 40
#define TILE_B (128*PADK*2)              // 10240
#define STG_B  (4*TILE_B)                // 40960
#define HSTAGES 2
#define HSMEM  (HSTAGES*STG_B)           // 81920

template<int EPI_T>
__device__ __forceinline__ void hgemm_body(
    const __nv_bfloat16* __restrict__ Ah, const __nv_bfloat16* __restrict__ Al,
    const __nv_bfloat16* __restrict__ Bh, const __nv_bfloat16* __restrict__ Bl,
    float* __restrict__ C, int K, int lda, int Ntot,
    const float* __restrict__ bias, int epi_rt_code, char* sm)
{
    const int tid  = threadIdx.x;
    const int lane = tid & 31;
    const int wid  = tid >> 5;
    const int m0 = blockIdx.y * 128;
    const int n0 = blockIdx.x * 128;
    const int mw = (wid >> 2) * 64;
    const int nw = (wid & 3) * 32;
    const uint32_t sbase = smem_u32(sm);
    const int KT = K >> 5;

    float acc[4][4][4];
#pragma unroll
    for (int mt = 0; mt < 4; mt++)
#pragma unroll
        for (int nt = 0; nt < 4; nt++)
#pragma unroll
            for (int q = 0; q < 4; q++) acc[mt][nt][q] = 0.f;

    auto issue = [&](int kt, int stage) {
        const int k0 = kt << 5;
        const uint32_t sdst = sbase + stage * STG_B;
#pragma unroll
        for (int u = 0; u < 8; u++) {
            int i  = tid + u * 256;
            int op = i >> 9;
            int r  = (i & 511) >> 2;
            int c  = i & 3;
            const __nv_bfloat16* src;
            if (op == 0)      src = Ah + (size_t)(m0 + r) * lda + k0 + c * 8;
            else if (op == 1) src = Al + (size_t)(m0 + r) * lda + k0 + c * 8;
            else if (op == 2) src = Bh + (size_t)(n0 + r) * K + k0 + c * 8;
            else              src = Bl + (size_t)(n0 + r) * K + k0 + c * 8;
            cpasync16(sdst + op * TILE_B + r * (PADK*2) + c * 16, src);
        }
    };

    // prologue: stage 0
    issue(0, 0);
    asm volatile("cp.async.commit_group;" ::: "memory");

    const int grp = lane >> 3;
    const int l7  = lane & 7;

    for (int kt = 0; kt < KT; kt++) {
        asm volatile("cp.async.wait_group 0;" ::: "memory");
        __syncthreads();

        // prefetch next stage (overlaps with compute below)
        if (kt + 1 < KT) issue(kt + 1, (kt + 1) & 1);
        asm volatile("cp.async.commit_group;" ::: "memory");

        const int st = kt & 1;
        const uint32_t sAh = sbase + st * STG_B;
        const uint32_t sAl = sAh + TILE_B;
        const uint32_t sBh = sAh + 2 * TILE_B;
        const uint32_t sBl = sAh + 3 * TILE_B;

#pragma unroll
        for (int kk = 0; kk < 2; kk++) {
            const int ko = kk * 16;
            uint32_t ahf[4][4], alf[4][4];
#pragma unroll
            for (int mt = 0; mt < 4; mt++) {
                int row = mw + mt * 16 + ((grp & 1) << 3) + l7;
                int kof = ko + ((grp & 2) << 2);
                uint32_t a = row * (PADK*2) + kof * 2;
                ldsm4(ahf[mt], sAh + a);
                ldsm4(alf[mt], sAl + a);
            }
            // B fragments loaded per np-pair and consumed immediately (regs)
#pragma unroll
            for (int np = 0; np < 2; np++) {
                int row = nw + np * 16 + ((grp >> 1) << 3) + l7;
                int kof = ko + ((grp & 1) << 3);
                uint32_t a = row * (PADK*2) + kof * 2;
                uint32_t th[4], tl[4];
                ldsm4(th, sBh + a);
                ldsm4(tl, sBl + a);
#pragma unroll
                for (int mt = 0; mt < 4; mt++) {
                    mma16816(acc[mt][np*2],   ahf[mt], th);
                    mma16816(acc[mt][np*2],   ahf[mt], tl);
                    mma16816(acc[mt][np*2],   alf[mt], th);
                    mma16816(acc[mt][np*2+1], ahf[mt], th + 2);
                    mma16816(acc[mt][np*2+1], ahf[mt], tl + 2);
                    mma16816(acc[mt][np*2+1], alf[mt], th + 2);
                }
            }
        }
        __syncthreads();
    }

    const int r0 = lane >> 2;
    const int c0 = (lane & 3) * 2;
    const int epi = (EPI_T >= 0) ? EPI_T : epi_rt_code;
#pragma unroll
    for (int mt = 0; mt < 4; mt++) {
#pragma unroll
        for (int nt = 0; nt < 4; nt++) {
            int row = m0 + mw + mt * 16 + r0;
            int col = n0 + nw + nt * 8 + c0;
            float b0 = 0.f, b1 = 0.f;
            if (epi != 0) { b0 = bias[col]; b1 = bias[col + 1]; }
            float v0 = epi_rt(epi, acc[mt][nt][0], b0);
            float v1 = epi_rt(epi, acc[mt][nt][1], b1);
            float v2 = epi_rt(epi, acc[mt][nt][2], b0);
            float v3 = epi_rt(epi, acc[mt][nt][3], b1);
            *(float2*)(C + (size_t)row * Ntot + col)       = make_float2(v0, v1);
            *(float2*)(C + (size_t)(row + 8) * Ntot + col) = make_float2(v2, v3);
        }
    }
}

// single GEMM (gate, Wo)
template<int EPI>
__global__ void __launch_bounds__(256, 2)
hgemm(const __nv_bfloat16* __restrict__ Ah, const __nv_bfloat16* __restrict__ Al,
      const __nv_bfloat16* __restrict__ Bh, const __nv_bfloat16* __restrict__ Bl,
      float* __restrict__ C, int K, int lda, int Ntot, const float* __restrict__ bias)
{
    extern __shared__ char sm[];
    hgemm_body<EPI>(Ah, Al, Bh, Bl, C, K, lda, Ntot, bias, EPI, sm);
}

// batched r/k/v projections: z selects operand set. All K=lda=Ntot=CC, EPI=0.
__global__ void __launch_bounds__(256, 2)
hgemm_batch3(const __nv_bfloat16* Ah0, const __nv_bfloat16* Al0, float* C0,
             const __nv_bfloat16* Ah1, const __nv_bfloat16* Al1, float* C1,
             const __nv_bfloat16* Ah2, const __nv_bfloat16* Al2, float* C2,
             const __nv_bfloat16* Bh0, const __nv_bfloat16* Bl0,
             const __nv_bfloat16* Bh1, const __nv_bfloat16* Bl1,
             const __nv_bfloat16* Bh2, const __nv_bfloat16* Bl2)
{
    extern __shared__ char sm[];
    const __nv_bfloat16 *Ah, *Al, *Bh, *Bl; float* C;
    if (blockIdx.z == 0)      { Ah=Ah0; Al=Al0; Bh=Bh0; Bl=Bl0; C=C0; }
    else if (blockIdx.z == 1) { Ah=Ah1; Al=Al1; Bh=Bh1; Bl=Bl1; C=C1; }
    else                      { Ah=Ah2; Al=Al2; Bh=Bh2; Bl=Bl2; C=C2; }
    hgemm_body<0>(Ah, Al, Bh, Bl, C, CC, CC, CC, nullptr, 0, sm);
}

// batched stage-2 (td/aaa/mv): z selects K, epi, A col-offset, B, C, bias.
#define HCATN 320
__global__ void __launch_bounds__(256, 2)
hgemm_s2(const __nv_bfloat16* hcat_h, const __nv_bfloat16* hcat_l,
         const __nv_bfloat16* B0h, const __nv_bfloat16* B0l,
         const __nv_bfloat16* B1h, const __nv_bfloat16* B1l,
         const __nv_bfloat16* B2h, const __nv_bfloat16* B2l,
         float* C0, float* C1, float* C2,
         const float* bias0, const float* bias1, const float* bias2)
{
    extern __shared__ char sm[];
    int K, epi, aoff;
    const __nv_bfloat16 *Bh, *Bl; float* C; const float* bias;
    if (blockIdx.z == 0)      { K=64; epi=4; aoff=0;   Bh=B0h; Bl=B0l; C=C0; bias=bias0; }
    else if (blockIdx.z == 1) { K=64; epi=3; aoff=64;  Bh=B1h; Bl=B1l; C=C1; bias=bias1; }
    else                      { K=32; epi=3; aoff=256; Bh=B2h; Bl=B2l; C=C2; bias=bias2; }
    hgemm_body<-1>(hcat_h + aoff, hcat_l + aoff, Bh, Bl, C, K, HCATN, CC, bias, epi, sm);
}

// ===========================================================================
// Stage-1 fused LoRA GEMM: 5 column segments of W1cat[320][2048].
// 3-stage pipeline, 2 CTAs/SM.
// ===========================================================================
#define S1_ATILE (128*PADK*2)
#define S1_BTILE (64*PADK*2)
#define S1_STG   (2*S1_ATILE + 2*S1_BTILE)
#define S1_SMEM  (3*S1_STG)   // 92160

__global__ void __launch_bounds__(256, 2)
hgemm_s1(const __nv_bfloat16* __restrict__ xw_h, const __nv_bfloat16* __restrict__ xw_l,
         const __nv_bfloat16* __restrict__ xa_h, const __nv_bfloat16* __restrict__ xa_l,
         const __nv_bfloat16* __restrict__ xg_h, const __nv_bfloat16* __restrict__ xg_l,
         const __nv_bfloat16* __restrict__ xv_h, const __nv_bfloat16* __restrict__ xv_l,
         const __nv_bfloat16* __restrict__ W1h, const __nv_bfloat16* __restrict__ W1l,
         __nv_bfloat16* __restrict__ Hh, __nv_bfloat16* __restrict__ Hl)
{
    extern __shared__ char sm[];
    const int tid  = threadIdx.x;
    const int lane = tid & 31;
    const int wid  = tid >> 5;
    const int seg  = blockIdx.x;
    const int m0   = blockIdx.y * 128;
    const int n0w  = seg * 64;
    const uint32_t sbase = smem_u32(sm);

    const __nv_bfloat16* Ah;
    const __nv_bfloat16* Al;
    if (seg == 0)      { Ah = xw_h; Al = xw_l; }
    else if (seg == 1) { Ah = xa_h; Al = xa_l; }
    else if (seg <= 3) { Ah = xg_h; Al = xg_l; }
    else               { Ah = xv_h; Al = xv_l; }

    const int mw = (wid >> 1) * 32;
    const int nw = (wid & 1) * 32;

    float acc[2][4][4];
#pragma unroll
    for (int mt = 0; mt < 2; mt++)
#pragma unroll
        for (int nt = 0; nt < 4; nt++)
#pragma unroll
            for (int q = 0; q < 4; q++) acc[mt][nt][q] = 0.f;

    auto issue = [&](int kt, int stage) {
        const int k0 = kt << 5;
        const uint32_t sdst = sbase + stage * S1_STG;
#pragma unroll
        for (int u = 0; u < 6; u++) {
            int i = tid + u * 256;
            if (i < 1024) {
                int sp = i >> 9, r = (i >> 2) & 127, c = i & 3;
                const __nv_bfloat16* src = (sp ? Al : Ah) + (size_t)(m0 + r) * CC + k0 + c * 8;
                cpasync16(sdst + sp * S1_ATILE + r * (PADK*2) + c * 16, src);
            } else {
                int j = i - 1024;
                int sp = j >> 8, r = (j >> 2) & 63, c = j & 3;
                const __nv_bfloat16* src = (sp ? W1l : W1h) + (size_t)(n0w + r) * CC + k0 + c * 8;
                cpasync16(sdst + 2*S1_ATILE + sp * S1_BTILE + r * (PADK*2) + c * 16, src);
            }
        }
    };

#pragma unroll
    for (int s = 0; s < 2; s++) {
        issue(s, s);
        asm volatile("cp.async.commit_group;" ::: "memory");
    }

    const int grp = lane >> 3;
    const int l7  = lane & 7;
    const int KT = CC >> 5;

    for (int kt = 0; kt < KT; kt++) {
        asm volatile("cp.async.wait_group 1;" ::: "memory");
        __syncthreads();

        const int st = kt % 3;
        const uint32_t sAh = sbase + st * S1_STG;
        const uint32_t sAl = sAh + S1_ATILE;
        const uint32_t sBh = sAh + 2 * S1_ATILE;
        const uint32_t sBl = sBh + S1_BTILE;

#pragma unroll
        for (int kk = 0; kk < 2; kk++) {
            const int ko = kk * 16;
            uint32_t ahf[2][4], alf[2][4];
#pragma unroll
            for (int mt = 0; mt < 2; mt++) {
                int row = mw + mt * 16 + ((grp & 1) << 3) + l7;
                int kof = ko + ((grp & 2) << 2);
                uint32_t a = row * (PADK*2) + kof * 2;
                ldsm4(ahf[mt], sAh + a);
                ldsm4(alf[mt], sAl + a);
            }
#pragma unroll
            for (int np = 0; np < 2; np++) {
                int row = nw + np * 16 + ((grp >> 1) << 3) + l7;
                int kof = ko + ((grp & 1) << 3);
                uint32_t a = row * (PADK*2) + kof * 2;
                uint32_t th[4], tl[4];
                ldsm4(th, sBh + a);
                ldsm4(tl, sBl + a);
#pragma unroll
                for (int mt = 0; mt < 2; mt++) {
                    mma16816(acc[mt][np*2],   ahf[mt], th);
                    mma16816(acc[mt][np*2],   ahf[mt], tl);
                    mma16816(acc[mt][np*2],   alf[mt], th);
                    mma16816(acc[mt][np*2+1], ahf[mt], th + 2);
                    mma16816(acc[mt][np*2+1], ahf[mt], tl + 2);
                    mma16816(acc[mt][np*2+1], alf[mt], th + 2);
                }
            }
        }

        int nkt = kt + 2;
        if (nkt < KT) issue(nkt, nkt % 3);
        asm volatile("cp.async.commit_group;" ::: "memory");
    }

    const int r0 = lane >> 2;
    const int c0 = (lane & 3) * 2;
#pragma unroll
    for (int mt = 0; mt < 2; mt++) {
#pragma unroll
        for (int nt = 0; nt < 4; nt++) {
            float v[4];
#pragma unroll
            for (int q = 0; q < 4; q++) {
                float t = acc[mt][nt][q];
                if (seg == 0)              t = tanhf(t);
                else if (seg == 2 || seg == 3) t = 1.f / (1.f + expf(-t));
                v[q] = t;
            }
            int row = m0 + mw + mt * 16 + r0;
            int col = seg * 64 + nw + nt * 8 + c0;
            float h0 = __bfloat162float(__float2bfloat16(v[0]));
            float h1 = __bfloat162float(__float2bfloat16(v[1]));
            float h2 = __bfloat162float(__float2bfloat16(v[2]));
            float h3 = __bfloat162float(__float2bfloat16(v[3]));
            *(uint32_t*)&Hh[(size_t)row * HCATN + col]       = pack_bf2(v[0], v[1]);
            *(uint32_t*)&Hl[(size_t)row * HCATN + col]       = pack_bf2(v[0]-h0, v[1]-h1);
            *(uint32_t*)&Hh[(size_t)(row+8) * HCATN + col]   = pack_bf2(v[2], v[3]);
            *(uint32_t*)&Hl[(size_t)(row+8) * HCATN + col]   = pack_bf2(v[2]-h2, v[3]-h3);
        }
    }
}

// ===========================================================================
// Weight transpose + split: W[K][N] fp32 -> Th/Tl[N][K] bf16
// ===========================================================================
__device__ __forceinline__ void transpose_body(const float* __restrict__ W,
                                               __nv_bfloat16* __restrict__ Th,
                                               __nv_bfloat16* __restrict__ Tl,
                                               int K, int N)
{
    __shared__ float tile[32][33];
    int bx = blockIdx.x * 32;
    int by = blockIdx.y * 32;
#pragma unroll
    for (int j = 0; j < 32; j += 8)
        tile[threadIdx.y + j][threadIdx.x] =
            W[(size_t)(by + threadIdx.y + j) * N + bx + threadIdx.x];
    __syncthreads();
#pragma unroll
    for (int j = 0; j < 32; j += 8) {
        float v = tile[threadIdx.x][threadIdx.y + j];
        int n = bx + threadIdx.y + j;
        int k = by + threadIdx.x;
        __nv_bfloat16 h = __float2bfloat16(v);
        Th[(size_t)n * K + k] = h;
        Tl[(size_t)n * K + k] = __float2bfloat16(v - __bfloat162float(h));
    }
}

__global__ void transpose_split(const float* __restrict__ W,
                                __nv_bfloat16* __restrict__ Th,
                                __nv_bfloat16* __restrict__ Tl, int K, int N)
{
    transpose_body(W, Th, Tl, K, N);
}

// merged 4 big 2048x2048 weight transposes, z-select
__global__ void transpose_big4(const float* W0, const float* W1_, const float* W2_, const float* W3_,
                               __nv_bfloat16* h0, __nv_bfloat16* l0,
                               __nv_bfloat16* h1, __nv_bfloat16* l1,
                               __nv_bfloat16* h2, __nv_bfloat16* l2,
                               __nv_bfloat16* h3, __nv_bfloat16* l3)
{
    const float* W; __nv_bfloat16 *Th, *Tl;
    if (blockIdx.z == 0)      { W = W0;  Th = h0; Tl = l0; }
    else if (blockIdx.z == 1) { W = W1_; Th = h1; Tl = l1; }
    else if (blockIdx.z == 2) { W = W2_; Th = h2; Tl = l2; }
    else                      { W = W3_; Th = h3; Tl = l3; }
    transpose_body(W, Th, Tl, CC, CC);
}

// ---------------------------------------------------------------------------
// Token-shift mixing, fused bf16 hi/lo split output for all 6 streams.
// ---------------------------------------------------------------------------
__global__ void mix_split_kernel(const float* __restrict__ x,
    const float* __restrict__ mr, const float* __restrict__ mw,
    const float* __restrict__ mk, const float* __restrict__ mv,
    const float* __restrict__ ma, const float* __restrict__ mg,
    __nv_bfloat16* __restrict__ rh, __nv_bfloat16* __restrict__ rl,
    __nv_bfloat16* __restrict__ wh, __nv_bfloat16* __restrict__ wl,
    __nv_bfloat16* __restrict__ kh, __nv_bfloat16* __restrict__ kl,
    __nv_bfloat16* __restrict__ vh, __nv_bfloat16* __restrict__ vl,
    __nv_bfloat16* __restrict__ ah, __nv_bfloat16* __restrict__ al,
    __nv_bfloat16* __restrict__ gh, __nv_bfloat16* __restrict__ gl)
{
    size_t i = (size_t)blockIdx.x * blockDim.x + threadIdx.x;
    size_t n4 = BTC / 4;
    if (i >= n4) return;
    size_t e = i * 4;
    int c  = (int)(e % CC);
    int bt = (int)(e / CC);
    int t  = bt % TT;

    float4 xc = ((const float4*)x)[i];
    float4 xp = make_float4(0.f, 0.f, 0.f, 0.f);
    if (t > 0) xp = ((const float4*)x)[i - CC/4];
    float4 xx = make_float4(xp.x-xc.x, xp.y-xc.y, xp.z-xc.z, xp.w-xc.w);

    int c4 = c / 4;
#define DOMIX(MV, OH, OL) { \
        float4 m = ((const float4*)MV)[c4]; \
        float4 o = make_float4(xc.x + xx.x*m.x, xc.y + xx.y*m.y, \
                               xc.z + xx.z*m.z, xc.w + xx.w*m.w); \
        float h0 = __bfloat162float(__float2bfloat16(o.x)); \
        float h1 = __bfloat162float(__float2bfloat16(o.y)); \
        float h2 = __bfloat162float(__float2bfloat16(o.z)); \
        float h3 = __bfloat162float(__float2bfloat16(o.w)); \
        ((uint2*)OH)[i] = make_uint2(pack_bf2(o.x, o.y), pack_bf2(o.z, o.w)); \
        ((uint2*)OL)[i] = make_uint2(pack_bf2(o.x-h0, o.y-h1), pack_bf2(o.z-h2, o.w-h3)); }
    DOMIX(mr, rh, rl); DOMIX(mw, wh, wl); DOMIX(mk, kh, kl);
    DOMIX(mv, vh, vl); DOMIX(ma, ah, al); DOMIX(mg, gh, gl);
#undef DOMIX
}

// ---------------------------------------------------------------------------
__device__ __forceinline__ float warp_sum(float v) {
#pragma unroll
    for (int o = 16; o > 0; o >>= 1) v += __shfl_xor_sync(0xffffffffu, v, o);
    return v;
}

// ---------------------------------------------------------------------------
// WKV7 recurrence with fused prep. 256 threads/block, one block per (b,h).
// ---------------------------------------------------------------------------
__global__ void __launch_bounds__(256)
wkv7_kernel(const float* __restrict__ r_,  const float* __restrict__ wd_,
            const float* __restrict__ k_,  const float* __restrict__ a_,
            const float* __restrict__ vl_, const float* __restrict__ s_,
            const float* __restrict__ v0_,
            const float* __restrict__ misc_kkk, const float* __restrict__ misc_a,
            float* __restrict__ yT)
{
    __shared__ __align__(16) float sb[2*392];
    const int bh  = blockIdx.x;
    const int b   = bh >> 5, h = bh & 31;
    const int tid = threadIdx.x;
    const int tg  = tid >> 6;
    const int n   = tid & 63;
    const int row = tid >> 2;
    const int cg  = tid & 3;
    const int cb  = cg * 16;
    const size_t src0  = ((size_t)b * TT) * CC + (size_t)h * NN + n;
    const size_t ybase = (size_t)bh * TT * NN;

    const float* pA;
    const float* pB = nullptr;
    const float* pC = nullptr;
    float ma = 0.f, mkk = 0.f;
    if (tg == 0)      pA = r_  + src0;
    else if (tg == 1) pA = wd_ + src0;
    else if (tg == 2) { pA = k_ + src0; pB = a_ + src0;
                        mkk = misc_kkk[h*NN+n]; ma = misc_a[h*NN+n]; }
    else              { pA = vl_ + src0; pB = s_ + src0; pC = v0_ + src0; }

    float st[16];
#pragma unroll
    for (int j = 0; j < 16; j++) st[j] = 0.f;

    {
        float va = pA[0];
        if (tg == 0)      sb[0*64+n] = va;
        else if (tg == 1) sb[1*64+n] = va;
        else if (tg == 2) {
            float vb = pB[0];
            float kk = va * mkk;
            sb[2*64+n] = va * fmaf(vb - 1.f, ma, 1.f);
            sb[4*64+n] = -kk;
            sb[5*64+n] = kk * vb;
            float wsum = warp_sum(kk*kk);
            if ((tid & 31) == 0) sb[384 + ((tid >> 5) & 1)] = wsum;
        } else {
            float vb = pB[0], vc = pC[0];
            sb[3*64+n] = va + (vc - va) * vb;
        }
    }
    __syncthreads();

    int cur = 0;
    for (int t = 0; t < TT; t++) {
        float fa = 0.f, fb = 0.f, fc = 0.f;
        if (t + 1 < TT) {
            size_t o = (size_t)(t + 1) * CC;
            fa = pA[o];
            if (tg >= 2) fb = pB[o];
            if (tg == 3) fc = pC[o];
        }

        const float* base = &sb[cur * 392];
        float ssq  = base[384] + base[385];
        float invn = 1.f / fmaxf(sqrtf(ssq), 1e-12f);
        float f2   = invn * invn;

        const float4* r4p = (const float4*)(base + 0*64 + cb);
        const float4* w4p = (const float4*)(base + 1*64 + cb);
        const float4* k4p = (const float4*)(base + 2*64 + cb);
        const float4* a4p = (const float4*)(base + 4*64 + cb);
        const float4* b4p = (const float4*)(base + 5*64 + cb);
        const float vi = base[3*64 + row];

        float c0=0.f, c1=0.f, c2=0.f, c3=0.f;
#pragma unroll
        for (int q = 0; q < 4; q++) {
            float4 a4 = a4p[q];
            c0 = fmaf(st[q*4+0], a4.x, c0);
            c1 = fmaf(st[q*4+1], a4.y, c1);
            c2 = fmaf(st[q*4+2], a4.z, c2);
            c3 = fmaf(st[q*4+3], a4.w, c3);
        }
        float sai = (c0 + c1) + (c2 + c3);
        sai += __shfl_xor_sync(0xffffffffu, sai, 1);
        sai += __shfl_xor_sync(0xffffffffu, sai, 2);
        sai *= f2;

        float y0=0.f, y1=0.f, y2=0.f, y3=0.f;
#pragma unroll
        for (int q = 0; q < 4; q++) {
            float4 w4 = w4p[q], b4 = b4p[q], k4 = k4p[q], r4 = r4p[q];
            float t0 = fmaf(sai, b4.x, fmaf(vi, k4.x, st[q*4+0]*w4.x));
            float t1 = fmaf(sai, b4.y, fmaf(vi, k4.y, st[q*4+1]*w4.y));
            float t2 = fmaf(sai, b4.z, fmaf(vi, k4.z, st[q*4+2]*w4.z));
            float t3 = fmaf(sai, b4.w, fmaf(vi, k4.w, st[q*4+3]*w4.w));
            st[q*4+0] = t0; st[q*4+1] = t1; st[q*4+2] = t2; st[q*4+3] = t3;
            y0 = fmaf(t0, r4.x, y0);
            y1 = fmaf(t1, r4.y, y1);
            y2 = fmaf(t2, r4.z, y2);
            y3 = fmaf(t3, r4.w, y3);
        }
        float yp = (y0 + y1) + (y2 + y3);
        yp += __shfl_xor_sync(0xffffffffu, yp, 1);
        yp += __shfl_xor_sync(0xffffffffu, yp, 2);
        if (cg == 0) yT[ybase + (size_t)t * NN + row] = yp;

        int nxt = cur ^ 1;
        if (t + 1 < TT) {
            float* d = &sb[nxt * 392];
            if (tg == 0)      d[0*64+n] = fa;
            else if (tg == 1) d[1*64+n] = fa;
            else if (tg == 2) {
                float kk = fa * mkk;
                d[2*64+n] = fa * fmaf(fb - 1.f, ma, 1.f);
                d[4*64+n] = -kk;
                d[5*64+n] = kk * fb;
                float wsum = warp_sum(kk*kk);
                if ((tid & 31) == 0) d[384 + ((tid >> 5) & 1)] = wsum;
            } else {
                d[3*64+n] = fa + (fc - fa) * fb;
            }
        }
        __syncthreads();
        cur = nxt;
    }
}

// ---------------------------------------------------------------------------
// GroupNorm + bonus + gate (prep transforms recomputed inline).
// ---------------------------------------------------------------------------
__global__ void post_kernel(const float* __restrict__ yT,
                            const float* __restrict__ r_, const float* __restrict__ k_,
                            const float* __restrict__ a_, const float* __restrict__ vl_,
                            const float* __restrict__ s_, const float* __restrict__ v0_,
                            const float* __restrict__ g,  const float* __restrict__ faaaa,
                            const float* __restrict__ misc_a,
                            const float* __restrict__ lnw, const float* __restrict__ lnb,
                            __nv_bfloat16* __restrict__ zh, __nv_bfloat16* __restrict__ zl)
{
    int gw   = (blockIdx.x * blockDim.x + threadIdx.x) >> 5;
    int lane = threadIdx.x & 31;
    if (gw >= BT * HH) return;
    int h  = gw % HH;
    int bt = gw / HH;
    int b  = bt / TT, t = bt % TT;

    size_t src = (size_t)bt * CC + (size_t)h * NN;
    size_t dst = (((size_t)(b*HH + h)) * TT + t) * NN;
    int n0 = lane, n1 = lane + 32;
    int c0 = h*NN + n0, c1 = h*NN + n1;

    float y0 = yT[dst+n0], y1 = yT[dst+n1];
    float sum = warp_sum(y0 + y1);
    float sq  = warp_sum(y0*y0 + y1*y1);
    float mu  = sum * (1.f/64.f);
    float var = sq * (1.f/64.f) - mu*mu;
    float rs  = rsqrtf(var + 6.4e-4f);

    float k0 = k_[src+n0], k1 = k_[src+n1];
    float a0 = a_[src+n0], a1 = a_[src+n1];
    float fk0 = k0 * fmaf(a0 - 1.f, misc_a[c0], 1.f);
    float fk1 = k1 * fmaf(a1 - 1.f, misc_a[c1], 1.f);
    float rk = r_[src+n0]*fk0*faaaa[c0] + r_[src+n1]*fk1*faaaa[c1];
    float srk = warp_sum(rk);

    float vv0 = vl_[src+n0], vv1 = vl_[src+n1];
    float fv0 = vv0 + (v0_[src+n0] - vv0) * s_[src+n0];
    float fv1 = vv1 + (v0_[src+n1] - vv1) * s_[src+n1];

    float z0 = ((y0 - mu)*rs*lnw[c0] + lnb[c0] + srk*fv0) * g[src+n0];
    float z1 = ((y1 - mu)*rs*lnw[c1] + lnb[c1] + srk*fv1) * g[src+n1];
    __nv_bfloat16 h0 = __float2bfloat16(z0);
    __nv_bfloat16 h1 = __float2bfloat16(z1);
    zh[src+n0] = h0; zh[src+n1] = h1;
    zl[src+n0] = __float2bfloat16(z0 - __bfloat162float(h0));
    zl[src+n1] = __float2bfloat16(z1 - __bfloat162float(h1));
}

__global__ void copy4_kernel(const float* __restrict__ src, float* __restrict__ dst,
                             size_t n4)
{
    size_t i = (size_t)blockIdx.x * blockDim.x + threadIdx.x;
    if (i < n4) ((float4*)dst)[i] = ((const float4*)src)[i];
}

// ---------------------------------------------------------------------------
// launch (single stream — no events, no side streams)
// ---------------------------------------------------------------------------
extern "C" void kernel_launch(void* const* d_in, const int* in_sizes, int n_in,
                              void* d_out, int out_size)
{
    const float* x         = (const float*)d_in[0];
    const float* v0        = (const float*)d_in[1];
    const float* maa_r     = (const float*)d_in[2];
    const float* maa_w     = (const float*)d_in[3];
    const float* maa_k     = (const float*)d_in[4];
    const float* maa_v     = (const float*)d_in[5];
    const float* maa_a     = (const float*)d_in[6];
    const float* maa_g     = (const float*)d_in[7];
    const float* time_decay= (const float*)d_in[8];
    const float* faaaa     = (const float*)d_in[9];
    const float* time_aaaaa= (const float*)d_in[10];
    const float* td_w1     = (const float*)d_in[11];
    const float* td_w2     = (const float*)d_in[12];
    const float* aaa_w1    = (const float*)d_in[13];
    const float* aaa_w2    = (const float*)d_in[14];
    const float* gate_w1   = (const float*)d_in[15];
    const float* gate_w2   = (const float*)d_in[16];
    const float* mv_w1     = (const float*)d_in[17];
    const float* mv_w2     = (const float*)d_in[18];
    const float* misc_v    = (const float*)d_in[19];
    const float* misc_kkk  = (const float*)d_in[20];
    const float* misc_a    = (const float*)d_in[21];
    const float* Wr        = (const float*)d_in[22];
    const float* Wk        = (const float*)d_in[23];
    const float* Wv        = (const float*)d_in[24];
    const float* Wo        = (const float*)d_in[25];
    const float* ln_w      = (const float*)d_in[26];
    const float* ln_b      = (const float*)d_in[27];

    float* pool = nullptr;
    cudaGetSymbolAddress((void**)&pool, g_pool);

    __nv_bfloat16* xr_h = (__nv_bfloat16*)(pool + (size_t)SL_XR * BTC);
    __nv_bfloat16* xr_l = xr_h + BTC;
    __nv_bfloat16* xw_h = (__nv_bfloat16*)(pool + (size_t)SL_XW * BTC);
    __nv_bfloat16* xw_l = xw_h + BTC;
    __nv_bfloat16* xk_h = (__nv_bfloat16*)(pool + (size_t)SL_XK * BTC);
    __nv_bfloat16* xk_l = xk_h + BTC;
    __nv_bfloat16* xv_h = (__nv_bfloat16*)(pool + (size_t)SL_XV * BTC);
    __nv_bfloat16* xv_l = xv_h + BTC;
    __nv_bfloat16* xa_h = (__nv_bfloat16*)(pool + (size_t)SL_XA * BTC);
    __nv_bfloat16* xa_l = xa_h + BTC;
    __nv_bfloat16* xg_h = (__nv_bfloat16*)(pool + (size_t)SL_XG * BTC);
    __nv_bfloat16* xg_l = xg_h + BTC;

    float* r_ = pool + (size_t)SL_R  * BTC;
    float* k_ = pool + (size_t)SL_K  * BTC;
    float* vl = pool + (size_t)SL_VL * BTC;
    float* g_ = pool + (size_t)SL_G  * BTC;
    float* wd = pool + (size_t)SL_WD * BTC;
    float* a_ = pool + (size_t)SL_A  * BTC;
    float* s_ = pool + (size_t)SL_S  * BTC;
    float* yT = pool + (size_t)SL_Y  * BTC;
    __nv_bfloat16* z_h = (__nv_bfloat16*)(pool + (size_t)SL_ZS * BTC);
    __nv_bfloat16* z_l = z_h + BTC;

    __nv_bfloat16* sb16 = (__nv_bfloat16*)(pool + (size_t)SL_SMALL * BTC);
    __nv_bfloat16* hcat_h = sb16;
    __nv_bfloat16* hcat_l = hcat_h + (size_t)BT * HCATN;
    __nv_bfloat16* W1h    = hcat_l + (size_t)BT * HCATN;
    __nv_bfloat16* W1l    = W1h + (size_t)HCATN * CC;
    __nv_bfloat16* tdw_h  = W1l + (size_t)HCATN * CC;
    __nv_bfloat16* tdw_l  = tdw_h  + (size_t)CC * 64;
    __nv_bfloat16* aaaw_h = tdw_l  + (size_t)CC * 64;
    __nv_bfloat16* aaaw_l = aaaw_h + (size_t)CC * 64;
    __nv_bfloat16* gatew_h= aaaw_l + (size_t)CC * 64;
    __nv_bfloat16* gatew_l= gatew_h+ (size_t)CC * 128;
    __nv_bfloat16* mvw_h  = gatew_l+ (size_t)CC * 128;
    __nv_bfloat16* mvw_l  = mvw_h  + (size_t)CC * 32;

    __nv_bfloat16* wb = (__nv_bfloat16*)(pool + (size_t)SL_WB * BTC);
    const size_t WSZ = (size_t)CC * CC;
    __nv_bfloat16* Wr_h = wb;            __nv_bfloat16* Wr_l = wb + WSZ;
    __nv_bfloat16* Wk_h = wb + 2*WSZ;    __nv_bfloat16* Wk_l = wb + 3*WSZ;
    __nv_bfloat16* Wv_h = wb + 4*WSZ;    __nv_bfloat16* Wv_l = wb + 5*WSZ;
    __nv_bfloat16* Wo_h = wb + 6*WSZ;    __nv_bfloat16* Wo_l = wb + 7*WSZ;

    cudaFuncSetAttribute(hgemm<0>, cudaFuncAttributeMaxDynamicSharedMemorySize, HSMEM);
    cudaFuncSetAttribute(hgemm_batch3, cudaFuncAttributeMaxDynamicSharedMemorySize, HSMEM);
    cudaFuncSetAttribute(hgemm_s2, cudaFuncAttributeMaxDynamicSharedMemorySize, HSMEM);
    cudaFuncSetAttribute(hgemm_s1, cudaFuncAttributeMaxDynamicSharedMemorySize, S1_SMEM);

    dim3 tb(32, 8);
    size_t n4 = BTC / 4;

    // k0: merged big weight transposes (Wr, Wk, Wv, Wo)
    transpose_big4<<<dim3(CC/32, CC/32, 4), tb>>>(
        Wr, Wk, Wv, Wo,
        Wr_h, Wr_l, Wk_h, Wk_l, Wv_h, Wv_l, Wo_h, Wo_l);

    // k1: token-shift mixing + split
    mix_split_kernel<<<(unsigned)((n4 + 255) / 256), 256>>>(
        x, maa_r, maa_w, maa_k, maa_v, maa_a, maa_g,
        xr_h, xr_l, xw_h, xw_l, xk_h, xk_l, xv_h, xv_l, xa_h, xa_l, xg_h, xg_l);

    // k2: v0 passthrough into second output half
    if ((size_t)out_size >= 2 * BTC) {
        copy4_kernel<<<(unsigned)((n4 + 255) / 256), 256>>>(
            v0, (float*)d_out + BTC, n4);
    } else {
        copy4_kernel<<<1, 256>>>(v0, pool + (size_t)SL_R * BTC, 0);
    }

    // k3: merged big projections r/k/v  (ncu -s 5 lands here)
    hgemm_batch3<<<dim3(CC/128, BT/128, 3), 256, HSMEM>>>(
        xr_h, xr_l, r_,  xk_h, xk_l, k_,  xv_h, xv_l, vl,
        Wr_h, Wr_l, Wk_h, Wk_l, Wv_h, Wv_l);

    // small weight transposes
    transpose_split<<<dim3(64/32,  CC/32), tb>>>(td_w1,   W1h,                 W1l,                 CC, 64);
    transpose_split<<<dim3(64/32,  CC/32), tb>>>(aaa_w1,  W1h + (size_t)64*CC, W1l + (size_t)64*CC, CC, 64);
    transpose_split<<<dim3(128/32, CC/32), tb>>>(gate_w1, W1h + (size_t)128*CC,W1l + (size_t)128*CC,CC, 128);
    transpose_split<<<dim3(32/32,  CC/32), tb>>>(mv_w1,   W1h + (size_t)256*CC,W1l + (size_t)256*CC,CC, 32);
    transpose_split<<<dim3(CC/32, 64/32),  tb>>>(td_w2,  tdw_h,  tdw_l,  64,  CC);
    transpose_split<<<dim3(CC/32, 64/32),  tb>>>(aaa_w2, aaaw_h, aaaw_l, 64,  CC);
    transpose_split<<<dim3(CC/32, 128/32), tb>>>(gate_w2,gatew_h,gatew_l,128, CC);
    transpose_split<<<dim3(CC/32, 32/32),  tb>>>(mv_w2,  mvw_h,  mvw_l,  32,  CC);

    // stage-1 fused LoRA GEMM
    hgemm_s1<<<dim3(5, BT/128), 256, S1_SMEM>>>(
        xw_h, xw_l, xa_h, xa_l, xg_h, xg_l, xv_h, xv_l, W1h, W1l, hcat_h, hcat_l);

    // merged stage-2 (td, aaa, mv) -> wd, a_, s_
    hgemm_s2<<<dim3(CC/128, BT/128, 3), 256, HSMEM>>>(
        hcat_h, hcat_l,
        tdw_h, tdw_l, aaaw_h, aaaw_l, mvw_h, mvw_l,
        wd, a_, s_, time_decay, time_aaaaa, misc_v);

    // gate stage-2 GEMM
    hgemm<0><<<dim3(CC/128, BT/128), 256, HSMEM>>>(
        hcat_h+128, hcat_l+128, gatew_h, gatew_l, g_, 128, HCATN, CC, nullptr);

    // WKV7 recurrence (prep fused into staging)
    wkv7_kernel<<<BB*HH, 256>>>(r_, wd, k_, a_, vl, s_, v0, misc_kkk, misc_a, yT);

    // groupnorm + bonus + gate -> z split
    post_kernel<<<(BT*HH)/8, 256>>>(yT, r_, k_, a_, vl, s_, v0, g_, faaaa,
                                    misc_a, ln_w, ln_b, z_h, z_l);

    // output projection directly into d_out
    hgemm<0><<<dim3(CC/128, BT/128), 256, HSMEM>>>(
        z_h, z_l, Wo_h, Wo_l, (float*)d_out, CC, CC, CC, nullptr);
}

// round 11
// speedup vs baseline: 3.0687x; 1.0010x over previous
#include <cuda_runtime.h>
#include <cuda_bf16.h>
#include <math.h>
#include <stdint.h>

// ---------------------------------------------------------------------------
// RWKV-7 Tmix forward. B=4, T=2048, C=2048, H=32, N=64.
// R11: R9's proven hgemm geometry (PADK=40, 2-stage, 2 CTA/SM) + term-major
// MMA ordering + gate merged into stage-2 batch. Single stream.
// ---------------------------------------------------------------------------

#define BB 4
#define TT 2048
#define CC 2048
#define HH 32
#define NN 64
#define BT (BB*TT)                       // 8192
#define BTC ((size_t)BT*(size_t)CC)      // 16777216

__device__ float g_pool[23ull * 16777216ull];

#define SL_XR 0
#define SL_XW 1
#define SL_XK 2
#define SL_XV 3
#define SL_XA 4
#define SL_XG 5
#define SL_R  6
#define SL_K  7
#define SL_VL 8
#define SL_G  9
#define SL_WD 10
#define SL_A  11
#define SL_S  12
#define SL_Y  19
#define SL_ZS 20
#define SL_SMALL 21
#define SL_WB  22

// ===========================================================================
// helpers
// ===========================================================================
__device__ __forceinline__ uint32_t smem_u32(const void* p) {
    uint32_t a;
    asm("{ .reg .u64 t; cvta.to.shared.u64 t, %1; cvt.u32.u64 %0, t; }"
        : "=r"(a) : "l"(p));
    return a;
}
__device__ __forceinline__ void cpasync16(uint32_t dst, const void* src) {
    asm volatile("cp.async.cg.shared.global [%0], [%1], 16;" :: "r"(dst), "l"(src));
}
__device__ __forceinline__ void ldsm4(uint32_t* r, uint32_t addr) {
    asm volatile("ldmatrix.sync.aligned.m8n8.x4.shared.b16 {%0,%1,%2,%3}, [%4];"
        : "=r"(r[0]), "=r"(r[1]), "=r"(r[2]), "=r"(r[3]) : "r"(addr));
}
__device__ __forceinline__ void mma16816(float* d, const uint32_t* a, const uint32_t* b) {
    asm volatile(
        "mma.sync.aligned.m16n8k16.row.col.f32.bf16.bf16.f32 "
        "{%0,%1,%2,%3}, {%4,%5,%6,%7}, {%8,%9}, {%0,%1,%2,%3};"
        : "+f"(d[0]), "+f"(d[1]), "+f"(d[2]), "+f"(d[3])
        : "r"(a[0]), "r"(a[1]), "r"(a[2]), "r"(a[3]), "r"(b[0]), "r"(b[1]));
}
__device__ __forceinline__ uint32_t pack_bf2(float a, float b) {
    __nv_bfloat162 t = __floats2bfloat162_rn(a, b);
    return *reinterpret_cast<uint32_t*>(&t);
}

// EPI: 0=none, 3=sigmoid(v+bias[n]), 4=decay transform with bias[n]
__device__ __forceinline__ float epi_rt(int epi, float v, float b) {
    if (epi == 3) {
        return 1.f / (1.f + expf(-(v + b)));
    } else if (epi == 4) {
        float z  = v + b;
        float sp = (z < -20.f) ? (-z) : log1pf(expf(-z));
        float w  = -sp - 0.5f;
        return expf(-expf(w));
    }
    return v;
}

// ===========================================================================
// GEMM core: CTA 128x128x32, 2-stage double buffer (R9 proven), warp 64x32,
// 2 CTAs/SM. D = Ah*Bh + Ah*Bl + Al*Bh, fp32 accum. Term-major MMA order.
// ===========================================================================
#define PADK 40
#define TILE_B (128*PADK*2)              // 10240
#define STG_B  (4*TILE_B)                // 40960
#define HSTAGES 2
#define HSMEM  (HSTAGES*STG_B)           // 81920

template<int EPI_T>
__device__ __forceinline__ void hgemm_body(
    const __nv_bfloat16* __restrict__ Ah, const __nv_bfloat16* __restrict__ Al,
    const __nv_bfloat16* __restrict__ Bh, const __nv_bfloat16* __restrict__ Bl,
    float* __restrict__ C, int K, int lda, int Ntot,
    const float* __restrict__ bias, int epi_rt_code, char* sm)
{
    const int tid  = threadIdx.x;
    const int lane = tid & 31;
    const int wid  = tid >> 5;
    const int m0 = blockIdx.y * 128;
    const int n0 = blockIdx.x * 128;
    const int mw = (wid >> 2) * 64;
    const int nw = (wid & 3) * 32;
    const uint32_t sbase = smem_u32(sm);
    const int KT = K >> 5;

    float acc[4][4][4];
#pragma unroll
    for (int mt = 0; mt < 4; mt++)
#pragma unroll
        for (int nt = 0; nt < 4; nt++)
#pragma unroll
            for (int q = 0; q < 4; q++) acc[mt][nt][q] = 0.f;

    auto issue = [&](int kt, int stage) {
        const int k0 = kt << 5;
        const uint32_t sdst = sbase + stage * STG_B;
#pragma unroll
        for (int u = 0; u < 8; u++) {
            int i  = tid + u * 256;
            int op = i >> 9;
            int r  = (i & 511) >> 2;
            int c  = i & 3;
            const __nv_bfloat16* src;
            if (op == 0)      src = Ah + (size_t)(m0 + r) * lda + k0 + c * 8;
            else if (op == 1) src = Al + (size_t)(m0 + r) * lda + k0 + c * 8;
            else if (op == 2) src = Bh + (size_t)(n0 + r) * K + k0 + c * 8;
            else              src = Bl + (size_t)(n0 + r) * K + k0 + c * 8;
            cpasync16(sdst + op * TILE_B + r * (PADK*2) + c * 16, src);
        }
    };

    // prologue: stage 0
    issue(0, 0);
    asm volatile("cp.async.commit_group;" ::: "memory");

    const int grp = lane >> 3;
    const int l7  = lane & 7;

    for (int kt = 0; kt < KT; kt++) {
        asm volatile("cp.async.wait_group 0;" ::: "memory");
        __syncthreads();

        // prefetch next stage (overlaps with compute below)
        if (kt + 1 < KT) issue(kt + 1, (kt + 1) & 1);
        asm volatile("cp.async.commit_group;" ::: "memory");

        const int st = kt & 1;
        const uint32_t sAh = sbase + st * STG_B;
        const uint32_t sAl = sAh + TILE_B;
        const uint32_t sBh = sAh + 2 * TILE_B;
        const uint32_t sBl = sAh + 3 * TILE_B;

#pragma unroll
        for (int kk = 0; kk < 2; kk++) {
            const int ko = kk * 16;
            uint32_t ahf[4][4], alf[4][4];
#pragma unroll
            for (int mt = 0; mt < 4; mt++) {
                int row = mw + mt * 16 + ((grp & 1) << 3) + l7;
                int kof = ko + ((grp & 2) << 2);
                uint32_t a = row * (PADK*2) + kof * 2;
                ldsm4(ahf[mt], sAh + a);
                ldsm4(alf[mt], sAl + a);
            }
#pragma unroll
            for (int np = 0; np < 2; np++) {
                int row = nw + np * 16 + ((grp >> 1) << 3) + l7;
                int kof = ko + ((grp & 1) << 3);
                uint32_t a = row * (PADK*2) + kof * 2;
                uint32_t th[4], tl[4];
                ldsm4(th, sBh + a);
                ldsm4(tl, sBl + a);
                // term-major: accumulator reuse distance = 8 MMAs
#pragma unroll
                for (int mt = 0; mt < 4; mt++) mma16816(acc[mt][np*2],   ahf[mt], th);
#pragma unroll
                for (int mt = 0; mt < 4; mt++) mma16816(acc[mt][np*2+1], ahf[mt], th + 2);
#pragma unroll
                for (int mt = 0; mt < 4; mt++) mma16816(acc[mt][np*2],   ahf[mt], tl);
#pragma unroll
                for (int mt = 0; mt < 4; mt++) mma16816(acc[mt][np*2+1], ahf[mt], tl + 2);
#pragma unroll
                for (int mt = 0; mt < 4; mt++) mma16816(acc[mt][np*2],   alf[mt], th);
#pragma unroll
                for (int mt = 0; mt < 4; mt++) mma16816(acc[mt][np*2+1], alf[mt], th + 2);
            }
        }
        __syncthreads();
    }

    const int r0 = lane >> 2;
    const int c0 = (lane & 3) * 2;
    const int epi = (EPI_T >= 0) ? EPI_T : epi_rt_code;
#pragma unroll
    for (int mt = 0; mt < 4; mt++) {
#pragma unroll
        for (int nt = 0; nt < 4; nt++) {
            int row = m0 + mw + mt * 16 + r0;
            int col = n0 + nw + nt * 8 + c0;
            float b0 = 0.f, b1 = 0.f;
            if (epi != 0) { b0 = bias[col]; b1 = bias[col + 1]; }
            float v0 = epi_rt(epi, acc[mt][nt][0], b0);
            float v1 = epi_rt(epi, acc[mt][nt][1], b1);
            float v2 = epi_rt(epi, acc[mt][nt][2], b0);
            float v3 = epi_rt(epi, acc[mt][nt][3], b1);
            *(float2*)(C + (size_t)row * Ntot + col)       = make_float2(v0, v1);
            *(float2*)(C + (size_t)(row + 8) * Ntot + col) = make_float2(v2, v3);
        }
    }
}

// single GEMM (Wo)
template<int EPI>
__global__ void __launch_bounds__(256, 2)
hgemm(const __nv_bfloat16* __restrict__ Ah, const __nv_bfloat16* __restrict__ Al,
      const __nv_bfloat16* __restrict__ Bh, const __nv_bfloat16* __restrict__ Bl,
      float* __restrict__ C, int K, int lda, int Ntot, const float* __restrict__ bias)
{
    extern __shared__ char sm[];
    hgemm_body<EPI>(Ah, Al, Bh, Bl, C, K, lda, Ntot, bias, EPI, sm);
}

// batched r/k/v projections: z selects operand set. All K=lda=Ntot=CC, EPI=0.
__global__ void __launch_bounds__(256, 2)
hgemm_batch3(const __nv_bfloat16* Ah0, const __nv_bfloat16* Al0, float* C0,
             const __nv_bfloat16* Ah1, const __nv_bfloat16* Al1, float* C1,
             const __nv_bfloat16* Ah2, const __nv_bfloat16* Al2, float* C2,
             const __nv_bfloat16* Bh0, const __nv_bfloat16* Bl0,
             const __nv_bfloat16* Bh1, const __nv_bfloat16* Bl1,
             const __nv_bfloat16* Bh2, const __nv_bfloat16* Bl2)
{
    extern __shared__ char sm[];
    const __nv_bfloat16 *Ah, *Al, *Bh, *Bl; float* C;
    if (blockIdx.z == 0)      { Ah=Ah0; Al=Al0; Bh=Bh0; Bl=Bl0; C=C0; }
    else if (blockIdx.z == 1) { Ah=Ah1; Al=Al1; Bh=Bh1; Bl=Bl1; C=C1; }
    else                      { Ah=Ah2; Al=Al2; Bh=Bh2; Bl=Bl2; C=C2; }
    hgemm_body<0>(Ah, Al, Bh, Bl, C, CC, CC, CC, nullptr, 0, sm);
}

// batched stage-2 (td/aaa/mv/gate): z selects K, epi, A col-offset, B, C, bias.
#define HCATN 320
__global__ void __launch_bounds__(256, 2)
hgemm_s2(const __nv_bfloat16* hcat_h, const __nv_bfloat16* hcat_l,
         const __nv_bfloat16* B0h, const __nv_bfloat16* B0l,
         const __nv_bfloat16* B1h, const __nv_bfloat16* B1l,
         const __nv_bfloat16* B2h, const __nv_bfloat16* B2l,
         const __nv_bfloat16* B3h, const __nv_bfloat16* B3l,
         float* C0, float* C1, float* C2, float* C3,
         const float* bias0, const float* bias1, const float* bias2)
{
    extern __shared__ char sm[];
    int K, epi, aoff;
    const __nv_bfloat16 *Bh, *Bl; float* C; const float* bias;
    if (blockIdx.z == 0)      { K=64;  epi=4; aoff=0;   Bh=B0h; Bl=B0l; C=C0; bias=bias0; }
    else if (blockIdx.z == 1) { K=64;  epi=3; aoff=64;  Bh=B1h; Bl=B1l; C=C1; bias=bias1; }
    else if (blockIdx.z == 2) { K=32;  epi=3; aoff=256; Bh=B2h; Bl=B2l; C=C2; bias=bias2; }
    else                      { K=128; epi=0; aoff=128; Bh=B3h; Bl=B3l; C=C3; bias=nullptr; }
    hgemm_body<-1>(hcat_h + aoff, hcat_l + aoff, Bh, Bl, C, K, HCATN, CC, bias, epi, sm);
}

// ===========================================================================
// Stage-1 fused LoRA GEMM: 5 column segments of W1cat[320][2048].
// 3-stage pipeline, 2 CTAs/SM. (stage = 30720B, 3 stages = 92160B)
// ===========================================================================
#define S1_ATILE (128*PADK*2)
#define S1_BTILE (64*PADK*2)
#define S1_STG   (2*S1_ATILE + 2*S1_BTILE)
#define S1_SMEM  (3*S1_STG)

__global__ void __launch_bounds__(256, 2)
hgemm_s1(const __nv_bfloat16* __restrict__ xw_h, const __nv_bfloat16* __restrict__ xw_l,
         const __nv_bfloat16* __restrict__ xa_h, const __nv_bfloat16* __restrict__ xa_l,
         const __nv_bfloat16* __restrict__ xg_h, const __nv_bfloat16* __restrict__ xg_l,
         const __nv_bfloat16* __restrict__ xv_h, const __nv_bfloat16* __restrict__ xv_l,
         const __nv_bfloat16* __restrict__ W1h, const __nv_bfloat16* __restrict__ W1l,
         __nv_bfloat16* __restrict__ Hh, __nv_bfloat16* __restrict__ Hl)
{
    extern __shared__ char sm[];
    const int tid  = threadIdx.x;
    const int lane = tid & 31;
    const int wid  = tid >> 5;
    const int seg  = blockIdx.x;
    const int m0   = blockIdx.y * 128;
    const int n0w  = seg * 64;
    const uint32_t sbase = smem_u32(sm);

    const __nv_bfloat16* Ah;
    const __nv_bfloat16* Al;
    if (seg == 0)      { Ah = xw_h; Al = xw_l; }
    else if (seg == 1) { Ah = xa_h; Al = xa_l; }
    else if (seg <= 3) { Ah = xg_h; Al = xg_l; }
    else               { Ah = xv_h; Al = xv_l; }

    const int mw = (wid >> 1) * 32;
    const int nw = (wid & 1) * 32;

    float acc[2][4][4];
#pragma unroll
    for (int mt = 0; mt < 2; mt++)
#pragma unroll
        for (int nt = 0; nt < 4; nt++)
#pragma unroll
            for (int q = 0; q < 4; q++) acc[mt][nt][q] = 0.f;

    auto issue = [&](int kt, int stage) {
        const int k0 = kt << 5;
        const uint32_t sdst = sbase + stage * S1_STG;
#pragma unroll
        for (int u = 0; u < 6; u++) {
            int i = tid + u * 256;
            if (i < 1024) {
                int sp = i >> 9, r = (i >> 2) & 127, c = i & 3;
                const __nv_bfloat16* src = (sp ? Al : Ah) + (size_t)(m0 + r) * CC + k0 + c * 8;
                cpasync16(sdst + sp * S1_ATILE + r * (PADK*2) + c * 16, src);
            } else {
                int j = i - 1024;
                int sp = j >> 8, r = (j >> 2) & 63, c = j & 3;
                const __nv_bfloat16* src = (sp ? W1l : W1h) + (size_t)(n0w + r) * CC + k0 + c * 8;
                cpasync16(sdst + 2*S1_ATILE + sp * S1_BTILE + r * (PADK*2) + c * 16, src);
            }
        }
    };

#pragma unroll
    for (int s = 0; s < 2; s++) {
        issue(s, s);
        asm volatile("cp.async.commit_group;" ::: "memory");
    }

    const int grp = lane >> 3;
    const int l7  = lane & 7;
    const int KT = CC >> 5;

    for (int kt = 0; kt < KT; kt++) {
        asm volatile("cp.async.wait_group 1;" ::: "memory");
        __syncthreads();

        const int st = kt % 3;
        const uint32_t sAh = sbase + st * S1_STG;
        const uint32_t sAl = sAh + S1_ATILE;
        const uint32_t sBh = sAh + 2 * S1_ATILE;
        const uint32_t sBl = sBh + S1_BTILE;

#pragma unroll
        for (int kk = 0; kk < 2; kk++) {
            const int ko = kk * 16;
            uint32_t ahf[2][4], alf[2][4];
#pragma unroll
            for (int mt = 0; mt < 2; mt++) {
                int row = mw + mt * 16 + ((grp & 1) << 3) + l7;
                int kof = ko + ((grp & 2) << 2);
                uint32_t a = row * (PADK*2) + kof * 2;
                ldsm4(ahf[mt], sAh + a);
                ldsm4(alf[mt], sAl + a);
            }
#pragma unroll
            for (int np = 0; np < 2; np++) {
                int row = nw + np * 16 + ((grp >> 1) << 3) + l7;
                int kof = ko + ((grp & 1) << 3);
                uint32_t a = row * (PADK*2) + kof * 2;
                uint32_t th[4], tl[4];
                ldsm4(th, sBh + a);
                ldsm4(tl, sBl + a);
#pragma unroll
                for (int mt = 0; mt < 2; mt++) mma16816(acc[mt][np*2],   ahf[mt], th);
#pragma unroll
                for (int mt = 0; mt < 2; mt++) mma16816(acc[mt][np*2+1], ahf[mt], th + 2);
#pragma unroll
                for (int mt = 0; mt < 2; mt++) mma16816(acc[mt][np*2],   ahf[mt], tl);
#pragma unroll
                for (int mt = 0; mt < 2; mt++) mma16816(acc[mt][np*2+1], ahf[mt], tl + 2);
#pragma unroll
                for (int mt = 0; mt < 2; mt++) mma16816(acc[mt][np*2],   alf[mt], th);
#pragma unroll
                for (int mt = 0; mt < 2; mt++) mma16816(acc[mt][np*2+1], alf[mt], th + 2);
            }
        }

        int nkt = kt + 2;
        if (nkt < KT) issue(nkt, nkt % 3);
        asm volatile("cp.async.commit_group;" ::: "memory");
    }

    const int r0 = lane >> 2;
    const int c0 = (lane & 3) * 2;
#pragma unroll
    for (int mt = 0; mt < 2; mt++) {
#pragma unroll
        for (int nt = 0; nt < 4; nt++) {
            float v[4];
#pragma unroll
            for (int q = 0; q < 4; q++) {
                float t = acc[mt][nt][q];
                if (seg == 0)              t = tanhf(t);
                else if (seg == 2 || seg == 3) t = 1.f / (1.f + expf(-t));
                v[q] = t;
            }
            int row = m0 + mw + mt * 16 + r0;
            int col = seg * 64 + nw + nt * 8 + c0;
            float h0 = __bfloat162float(__float2bfloat16(v[0]));
            float h1 = __bfloat162float(__float2bfloat16(v[1]));
            float h2 = __bfloat162float(__float2bfloat16(v[2]));
            float h3 = __bfloat162float(__float2bfloat16(v[3]));
            *(uint32_t*)&Hh[(size_t)row * HCATN + col]       = pack_bf2(v[0], v[1]);
            *(uint32_t*)&Hl[(size_t)row * HCATN + col]       = pack_bf2(v[0]-h0, v[1]-h1);
            *(uint32_t*)&Hh[(size_t)(row+8) * HCATN + col]   = pack_bf2(v[2], v[3]);
            *(uint32_t*)&Hl[(size_t)(row+8) * HCATN + col]   = pack_bf2(v[2]-h2, v[3]-h3);
        }
    }
}

// ===========================================================================
// Weight transpose + split: W[K][N] fp32 -> Th/Tl[N][K] bf16
// ===========================================================================
__device__ __forceinline__ void transpose_body(const float* __restrict__ W,
                                               __nv_bfloat16* __restrict__ Th,
                                               __nv_bfloat16* __restrict__ Tl,
                                               int K, int N)
{
    __shared__ float tile[32][33];
    int bx = blockIdx.x * 32;
    int by = blockIdx.y * 32;
#pragma unroll
    for (int j = 0; j < 32; j += 8)
        tile[threadIdx.y + j][threadIdx.x] =
            W[(size_t)(by + threadIdx.y + j) * N + bx + threadIdx.x];
    __syncthreads();
#pragma unroll
    for (int j = 0; j < 32; j += 8) {
        float v = tile[threadIdx.x][threadIdx.y + j];
        int n = bx + threadIdx.y + j;
        int k = by + threadIdx.x;
        __nv_bfloat16 h = __float2bfloat16(v);
        Th[(size_t)n * K + k] = h;
        Tl[(size_t)n * K + k] = __float2bfloat16(v - __bfloat162float(h));
    }
}

__global__ void transpose_split(const float* __restrict__ W,
                                __nv_bfloat16* __restrict__ Th,
                                __nv_bfloat16* __restrict__ Tl, int K, int N)
{
    transpose_body(W, Th, Tl, K, N);
}

// merged 4 big 2048x2048 weight transposes, z-select
__global__ void transpose_big4(const float* W0, const float* W1_, const float* W2_, const float* W3_,
                               __nv_bfloat16* h0, __nv_bfloat16* l0,
                               __nv_bfloat16* h1, __nv_bfloat16* l1,
                               __nv_bfloat16* h2, __nv_bfloat16* l2,
                               __nv_bfloat16* h3, __nv_bfloat16* l3)
{
    const float* W; __nv_bfloat16 *Th, *Tl;
    if (blockIdx.z == 0)      { W = W0;  Th = h0; Tl = l0; }
    else if (blockIdx.z == 1) { W = W1_; Th = h1; Tl = l1; }
    else if (blockIdx.z == 2) { W = W2_; Th = h2; Tl = l2; }
    else                      { W = W3_; Th = h3; Tl = l3; }
    transpose_body(W, Th, Tl, CC, CC);
}

// ---------------------------------------------------------------------------
// Token-shift mixing, fused bf16 hi/lo split output for all 6 streams.
// ---------------------------------------------------------------------------
__global__ void mix_split_kernel(const float* __restrict__ x,
    const float* __restrict__ mr, const float* __restrict__ mw,
    const float* __restrict__ mk, const float* __restrict__ mv,
    const float* __restrict__ ma, const float* __restrict__ mg,
    __nv_bfloat16* __restrict__ rh, __nv_bfloat16* __restrict__ rl,
    __nv_bfloat16* __restrict__ wh, __nv_bfloat16* __restrict__ wl,
    __nv_bfloat16* __restrict__ kh, __nv_bfloat16* __restrict__ kl,
    __nv_bfloat16* __restrict__ vh, __nv_bfloat16* __restrict__ vl,
    __nv_bfloat16* __restrict__ ah, __nv_bfloat16* __restrict__ al,
    __nv_bfloat16* __restrict__ gh, __nv_bfloat16* __restrict__ gl)
{
    size_t i = (size_t)blockIdx.x * blockDim.x + threadIdx.x;
    size_t n4 = BTC / 4;
    if (i >= n4) return;
    size_t e = i * 4;
    int c  = (int)(e % CC);
    int bt = (int)(e / CC);
    int t  = bt % TT;

    float4 xc = ((const float4*)x)[i];
    float4 xp = make_float4(0.f, 0.f, 0.f, 0.f);
    if (t > 0) xp = ((const float4*)x)[i - CC/4];
    float4 xx = make_float4(xp.x-xc.x, xp.y-xc.y, xp.z-xc.z, xp.w-xc.w);

    int c4 = c / 4;
#define DOMIX(MV, OH, OL) { \
        float4 m = ((const float4*)MV)[c4]; \
        float4 o = make_float4(xc.x + xx.x*m.x, xc.y + xx.y*m.y, \
                               xc.z + xx.z*m.z, xc.w + xx.w*m.w); \
        float h0 = __bfloat162float(__float2bfloat16(o.x)); \
        float h1 = __bfloat162float(__float2bfloat16(o.y)); \
        float h2 = __bfloat162float(__float2bfloat16(o.z)); \
        float h3 = __bfloat162float(__float2bfloat16(o.w)); \
        ((uint2*)OH)[i] = make_uint2(pack_bf2(o.x, o.y), pack_bf2(o.z, o.w)); \
        ((uint2*)OL)[i] = make_uint2(pack_bf2(o.x-h0, o.y-h1), pack_bf2(o.z-h2, o.w-h3)); }
    DOMIX(mr, rh, rl); DOMIX(mw, wh, wl); DOMIX(mk, kh, kl);
    DOMIX(mv, vh, vl); DOMIX(ma, ah, al); DOMIX(mg, gh, gl);
#undef DOMIX
}

// ---------------------------------------------------------------------------
__device__ __forceinline__ float warp_sum(float v) {
#pragma unroll
    for (int o = 16; o > 0; o >>= 1) v += __shfl_xor_sync(0xffffffffu, v, o);
    return v;
}

// ---------------------------------------------------------------------------
// WKV7 recurrence with fused prep. 256 threads/block, one block per (b,h).
// ---------------------------------------------------------------------------
__global__ void __launch_bounds__(256)
wkv7_kernel(const float* __restrict__ r_,  const float* __restrict__ wd_,
            const float* __restrict__ k_,  const float* __restrict__ a_,
            const float* __restrict__ vl_, const float* __restrict__ s_,
            const float* __restrict__ v0_,
            const float* __restrict__ misc_kkk, const float* __restrict__ misc_a,
            float* __restrict__ yT)
{
    __shared__ __align__(16) float sb[2*392];
    const int bh  = blockIdx.x;
    const int b   = bh >> 5, h = bh & 31;
    const int tid = threadIdx.x;
    const int tg  = tid >> 6;
    const int n   = tid & 63;
    const int row = tid >> 2;
    const int cg  = tid & 3;
    const int cb  = cg * 16;
    const size_t src0  = ((size_t)b * TT) * CC + (size_t)h * NN + n;
    const size_t ybase = (size_t)bh * TT * NN;

    const float* pA;
    const float* pB = nullptr;
    const float* pC = nullptr;
    float ma = 0.f, mkk = 0.f;
    if (tg == 0)      pA = r_  + src0;
    else if (tg == 1) pA = wd_ + src0;
    else if (tg == 2) { pA = k_ + src0; pB = a_ + src0;
                        mkk = misc_kkk[h*NN+n]; ma = misc_a[h*NN+n]; }
    else              { pA = vl_ + src0; pB = s_ + src0; pC = v0_ + src0; }

    float st[16];
#pragma unroll
    for (int j = 0; j < 16; j++) st[j] = 0.f;

    {
        float va = pA[0];
        if (tg == 0)      sb[0*64+n] = va;
        else if (tg == 1) sb[1*64+n] = va;
        else if (tg == 2) {
            float vb = pB[0];
            float kk = va * mkk;
            sb[2*64+n] = va * fmaf(vb - 1.f, ma, 1.f);
            sb[4*64+n] = -kk;
            sb[5*64+n] = kk * vb;
            float wsum = warp_sum(kk*kk);
            if ((tid & 31) == 0) sb[384 + ((tid >> 5) & 1)] = wsum;
        } else {
            float vb = pB[0], vc = pC[0];
            sb[3*64+n] = va + (vc - va) * vb;
        }
    }
    __syncthreads();

    int cur = 0;
    for (int t = 0; t < TT; t++) {
        float fa = 0.f, fb = 0.f, fc = 0.f;
        if (t + 1 < TT) {
            size_t o = (size_t)(t + 1) * CC;
            fa = pA[o];
            if (tg >= 2) fb = pB[o];
            if (tg == 3) fc = pC[o];
        }

        const float* base = &sb[cur * 392];
        float ssq  = base[384] + base[385];
        float invn = 1.f / fmaxf(sqrtf(ssq), 1e-12f);
        float f2   = invn * invn;

        const float4* r4p = (const float4*)(base + 0*64 + cb);
        const float4* w4p = (const float4*)(base + 1*64 + cb);
        const float4* k4p = (const float4*)(base + 2*64 + cb);
        const float4* a4p = (const float4*)(base + 4*64 + cb);
        const float4* b4p = (const float4*)(base + 5*64 + cb);
        const float vi = base[3*64 + row];

        float c0=0.f, c1=0.f, c2=0.f, c3=0.f;
#pragma unroll
        for (int q = 0; q < 4; q++) {
            float4 a4 = a4p[q];
            c0 = fmaf(st[q*4+0], a4.x, c0);
            c1 = fmaf(st[q*4+1], a4.y, c1);
            c2 = fmaf(st[q*4+2], a4.z, c2);
            c3 = fmaf(st[q*4+3], a4.w, c3);
        }
        float sai = (c0 + c1) + (c2 + c3);
        sai += __shfl_xor_sync(0xffffffffu, sai, 1);
        sai += __shfl_xor_sync(0xffffffffu, sai, 2);
        sai *= f2;

        float y0=0.f, y1=0.f, y2=0.f, y3=0.f;
#pragma unroll
        for (int q = 0; q < 4; q++) {
            float4 w4 = w4p[q], b4 = b4p[q], k4 = k4p[q], r4 = r4p[q];
            float t0 = fmaf(sai, b4.x, fmaf(vi, k4.x, st[q*4+0]*w4.x));
            float t1 = fmaf(sai, b4.y, fmaf(vi, k4.y, st[q*4+1]*w4.y));
            float t2 = fmaf(sai, b4.z, fmaf(vi, k4.z, st[q*4+2]*w4.z));
            float t3 = fmaf(sai, b4.w, fmaf(vi, k4.w, st[q*4+3]*w4.w));
            st[q*4+0] = t0; st[q*4+1] = t1; st[q*4+2] = t2; st[q*4+3] = t3;
            y0 = fmaf(t0, r4.x, y0);
            y1 = fmaf(t1, r4.y, y1);
            y2 = fmaf(t2, r4.z, y2);
            y3 = fmaf(t3, r4.w, y3);
        }
        float yp = (y0 + y1) + (y2 + y3);
        yp += __shfl_xor_sync(0xffffffffu, yp, 1);
        yp += __shfl_xor_sync(0xffffffffu, yp, 2);
        if (cg == 0) yT[ybase + (size_t)t * NN + row] = yp;

        int nxt = cur ^ 1;
        if (t + 1 < TT) {
            float* d = &sb[nxt * 392];
            if (tg == 0)      d[0*64+n] = fa;
            else if (tg == 1) d[1*64+n] = fa;
            else if (tg == 2) {
                float kk = fa * mkk;
                d[2*64+n] = fa * fmaf(fb - 1.f, ma, 1.f);
                d[4*64+n] = -kk;
                d[5*64+n] = kk * fb;
                float wsum = warp_sum(kk*kk);
                if ((tid & 31) == 0) d[384 + ((tid >> 5) & 1)] = wsum;
            } else {
                d[3*64+n] = fa + (fc - fa) * fb;
            }
        }
        __syncthreads();
        cur = nxt;
    }
}

// ---------------------------------------------------------------------------
// GroupNorm + bonus + gate (prep transforms recomputed inline).
// ---------------------------------------------------------------------------
__global__ void post_kernel(const float* __restrict__ yT,
                            const float* __restrict__ r_, const float* __restrict__ k_,
                            const float* __restrict__ a_, const float* __restrict__ vl_,
                            const float* __restrict__ s_, const float* __restrict__ v0_,
                            const float* __restrict__ g,  const float* __restrict__ faaaa,
                            const float* __restrict__ misc_a,
                            const float* __restrict__ lnw, const float* __restrict__ lnb,
                            __nv_bfloat16* __restrict__ zh, __nv_bfloat16* __restrict__ zl)
{
    int gw   = (blockIdx.x * blockDim.x + threadIdx.x) >> 5;
    int lane = threadIdx.x & 31;
    if (gw >= BT * HH) return;
    int h  = gw % HH;
    int bt = gw / HH;
    int b  = bt / TT, t = bt % TT;

    size_t src = (size_t)bt * CC + (size_t)h * NN;
    size_t dst = (((size_t)(b*HH + h)) * TT + t) * NN;
    int n0 = lane, n1 = lane + 32;
    int c0 = h*NN + n0, c1 = h*NN + n1;

    float y0 = yT[dst+n0], y1 = yT[dst+n1];
    float sum = warp_sum(y0 + y1);
    float sq  = warp_sum(y0*y0 + y1*y1);
    float mu  = sum * (1.f/64.f);
    float var = sq * (1.f/64.f) - mu*mu;
    float rs  = rsqrtf(var + 6.4e-4f);

    float k0 = k_[src+n0], k1 = k_[src+n1];
    float a0 = a_[src+n0], a1 = a_[src+n1];
    float fk0 = k0 * fmaf(a0 - 1.f, misc_a[c0], 1.f);
    float fk1 = k1 * fmaf(a1 - 1.f, misc_a[c1], 1.f);
    float rk = r_[src+n0]*fk0*faaaa[c0] + r_[src+n1]*fk1*faaaa[c1];
    float srk = warp_sum(rk);

    float vv0 = vl_[src+n0], vv1 = vl_[src+n1];
    float fv0 = vv0 + (v0_[src+n0] - vv0) * s_[src+n0];
    float fv1 = vv1 + (v0_[src+n1] - vv1) * s_[src+n1];

    float z0 = ((y0 - mu)*rs*lnw[c0] + lnb[c0] + srk*fv0) * g[src+n0];
    float z1 = ((y1 - mu)*rs*lnw[c1] + lnb[c1] + srk*fv1) * g[src+n1];
    __nv_bfloat16 h0 = __float2bfloat16(z0);
    __nv_bfloat16 h1 = __float2bfloat16(z1);
    zh[src+n0] = h0; zh[src+n1] = h1;
    zl[src+n0] = __float2bfloat16(z0 - __bfloat162float(h0));
    zl[src+n1] = __float2bfloat16(z1 - __bfloat162float(h1));
}

__global__ void copy4_kernel(const float* __restrict__ src, float* __restrict__ dst,
                             size_t n4)
{
    size_t i = (size_t)blockIdx.x * blockDim.x + threadIdx.x;
    if (i < n4) ((float4*)dst)[i] = ((const float4*)src)[i];
}

// ---------------------------------------------------------------------------
// launch (single stream)
// ---------------------------------------------------------------------------
extern "C" void kernel_launch(void* const* d_in, const int* in_sizes, int n_in,
                              void* d_out, int out_size)
{
    const float* x         = (const float*)d_in[0];
    const float* v0        = (const float*)d_in[1];
    const float* maa_r     = (const float*)d_in[2];
    const float* maa_w     = (const float*)d_in[3];
    const float* maa_k     = (const float*)d_in[4];
    const float* maa_v     = (const float*)d_in[5];
    const float* maa_a     = (const float*)d_in[6];
    const float* maa_g     = (const float*)d_in[7];
    const float* time_decay= (const float*)d_in[8];
    const float* faaaa     = (const float*)d_in[9];
    const float* time_aaaaa= (const float*)d_in[10];
    const float* td_w1     = (const float*)d_in[11];
    const float* td_w2     = (const float*)d_in[12];
    const float* aaa_w1    = (const float*)d_in[13];
    const float* aaa_w2    = (const float*)d_in[14];
    const float* gate_w1   = (const float*)d_in[15];
    const float* gate_w2   = (const float*)d_in[16];
    const float* mv_w1     = (const float*)d_in[17];
    const float* mv_w2     = (const float*)d_in[18];
    const float* misc_v    = (const float*)d_in[19];
    const float* misc_kkk  = (const float*)d_in[20];
    const float* misc_a    = (const float*)d_in[21];
    const float* Wr        = (const float*)d_in[22];
    const float* Wk        = (const float*)d_in[23];
    const float* Wv        = (const float*)d_in[24];
    const float* Wo        = (const float*)d_in[25];
    const float* ln_w      = (const float*)d_in[26];
    const float* ln_b      = (const float*)d_in[27];

    float* pool = nullptr;
    cudaGetSymbolAddress((void**)&pool, g_pool);

    __nv_bfloat16* xr_h = (__nv_bfloat16*)(pool + (size_t)SL_XR * BTC);
    __nv_bfloat16* xr_l = xr_h + BTC;
    __nv_bfloat16* xw_h = (__nv_bfloat16*)(pool + (size_t)SL_XW * BTC);
    __nv_bfloat16* xw_l = xw_h + BTC;
    __nv_bfloat16* xk_h = (__nv_bfloat16*)(pool + (size_t)SL_XK * BTC);
    __nv_bfloat16* xk_l = xk_h + BTC;
    __nv_bfloat16* xv_h = (__nv_bfloat16*)(pool + (size_t)SL_XV * BTC);
    __nv_bfloat16* xv_l = xv_h + BTC;
    __nv_bfloat16* xa_h = (__nv_bfloat16*)(pool + (size_t)SL_XA * BTC);
    __nv_bfloat16* xa_l = xa_h + BTC;
    __nv_bfloat16* xg_h = (__nv_bfloat16*)(pool + (size_t)SL_XG * BTC);
    __nv_bfloat16* xg_l = xg_h + BTC;

    float* r_ = pool + (size_t)SL_R  * BTC;
    float* k_ = pool + (size_t)SL_K  * BTC;
    float* vl = pool + (size_t)SL_VL * BTC;
    float* g_ = pool + (size_t)SL_G  * BTC;
    float* wd = pool + (size_t)SL_WD * BTC;
    float* a_ = pool + (size_t)SL_A  * BTC;
    float* s_ = pool + (size_t)SL_S  * BTC;
    float* yT = pool + (size_t)SL_Y  * BTC;
    __nv_bfloat16* z_h = (__nv_bfloat16*)(pool + (size_t)SL_ZS * BTC);
    __nv_bfloat16* z_l = z_h + BTC;

    __nv_bfloat16* sb16 = (__nv_bfloat16*)(pool + (size_t)SL_SMALL * BTC);
    __nv_bfloat16* hcat_h = sb16;
    __nv_bfloat16* hcat_l = hcat_h + (size_t)BT * HCATN;
    __nv_bfloat16* W1h    = hcat_l + (size_t)BT * HCATN;
    __nv_bfloat16* W1l    = W1h + (size_t)HCATN * CC;
    __nv_bfloat16* tdw_h  = W1l + (size_t)HCATN * CC;
    __nv_bfloat16* tdw_l  = tdw_h  + (size_t)CC * 64;
    __nv_bfloat16* aaaw_h = tdw_l  + (size_t)CC * 64;
    __nv_bfloat16* aaaw_l = aaaw_h + (size_t)CC * 64;
    __nv_bfloat16* gatew_h= aaaw_l + (size_t)CC * 64;
    __nv_bfloat16* gatew_l= gatew_h+ (size_t)CC * 128;
    __nv_bfloat16* mvw_h  = gatew_l+ (size_t)CC * 128;
    __nv_bfloat16* mvw_l  = mvw_h  + (size_t)CC * 32;

    __nv_bfloat16* wb = (__nv_bfloat16*)(pool + (size_t)SL_WB * BTC);
    const size_t WSZ = (size_t)CC * CC;
    __nv_bfloat16* Wr_h = wb;            __nv_bfloat16* Wr_l = wb + WSZ;
    __nv_bfloat16* Wk_h = wb + 2*WSZ;    __nv_bfloat16* Wk_l = wb + 3*WSZ;
    __nv_bfloat16* Wv_h = wb + 4*WSZ;    __nv_bfloat16* Wv_l = wb + 5*WSZ;
    __nv_bfloat16* Wo_h = wb + 6*WSZ;    __nv_bfloat16* Wo_l = wb + 7*WSZ;

    cudaFuncSetAttribute(hgemm<0>, cudaFuncAttributeMaxDynamicSharedMemorySize, HSMEM);
    cudaFuncSetAttribute(hgemm_batch3, cudaFuncAttributeMaxDynamicSharedMemorySize, HSMEM);
    cudaFuncSetAttribute(hgemm_s2, cudaFuncAttributeMaxDynamicSharedMemorySize, HSMEM);
    cudaFuncSetAttribute(hgemm_s1, cudaFuncAttributeMaxDynamicSharedMemorySize, S1_SMEM);

    dim3 tb(32, 8);
    size_t n4 = BTC / 4;

    // k0: merged big weight transposes (Wr, Wk, Wv, Wo)
    transpose_big4<<<dim3(CC/32, CC/32, 4), tb>>>(
        Wr, Wk, Wv, Wo,
        Wr_h, Wr_l, Wk_h, Wk_l, Wv_h, Wv_l, Wo_h, Wo_l);

    // k1: token-shift mixing + split
    mix_split_kernel<<<(unsigned)((n4 + 255) / 256), 256>>>(
        x, maa_r, maa_w, maa_k, maa_v, maa_a, maa_g,
        xr_h, xr_l, xw_h, xw_l, xk_h, xk_l, xv_h, xv_l, xa_h, xa_l, xg_h, xg_l);

    // k2: v0 passthrough into second output half
    if ((size_t)out_size >= 2 * BTC) {
        copy4_kernel<<<(unsigned)((n4 + 255) / 256), 256>>>(
            v0, (float*)d_out + BTC, n4);
    } else {
        copy4_kernel<<<1, 256>>>(v0, pool + (size_t)SL_R * BTC, 0);
    }

    // k3: merged big projections r/k/v  (ncu -s 5 lands here)
    hgemm_batch3<<<dim3(CC/128, BT/128, 3), 256, HSMEM>>>(
        xr_h, xr_l, r_,  xk_h, xk_l, k_,  xv_h, xv_l, vl,
        Wr_h, Wr_l, Wk_h, Wk_l, Wv_h, Wv_l);

    // small weight transposes
    transpose_split<<<dim3(64/32,  CC/32), tb>>>(td_w1,   W1h,                 W1l,                 CC, 64);
    transpose_split<<<dim3(64/32,  CC/32), tb>>>(aaa_w1,  W1h + (size_t)64*CC, W1l + (size_t)64*CC, CC, 64);
    transpose_split<<<dim3(128/32, CC/32), tb>>>(gate_w1, W1h + (size_t)128*CC,W1l + (size_t)128*CC,CC, 128);
    transpose_split<<<dim3(32/32,  CC/32), tb>>>(mv_w1,   W1h + (size_t)256*CC,W1l + (size_t)256*CC,CC, 32);
    transpose_split<<<dim3(CC/32, 64/32),  tb>>>(td_w2,  tdw_h,  tdw_l,  64,  CC);
    transpose_split<<<dim3(CC/32, 64/32),  tb>>>(aaa_w2, aaaw_h, aaaw_l, 64,  CC);
    transpose_split<<<dim3(CC/32, 128/32), tb>>>(gate_w2,gatew_h,gatew_l,128, CC);
    transpose_split<<<dim3(CC/32, 32/32),  tb>>>(mv_w2,  mvw_h,  mvw_l,  32,  CC);

    // stage-1 fused LoRA GEMM
    hgemm_s1<<<dim3(5, BT/128), 256, S1_SMEM>>>(
        xw_h, xw_l, xa_h, xa_l, xg_h, xg_l, xv_h, xv_l, W1h, W1l, hcat_h, hcat_l);

    // merged stage-2 (td, aaa, mv, gate) -> wd, a_, s_, g_
    hgemm_s2<<<dim3(CC/128, BT/128, 4), 256, HSMEM>>>(
        hcat_h, hcat_l,
        tdw_h, tdw_l, aaaw_h, aaaw_l, mvw_h, mvw_l, gatew_h, gatew_l,
        wd, a_, s_, g_, time_decay, time_aaaaa, misc_v);

    // WKV7 recurrence (prep fused into staging)
    wkv7_kernel<<<BB*HH, 256>>>(r_, wd, k_, a_, vl, s_, v0, misc_kkk, misc_a, yT);

    // groupnorm + bonus + gate -> z split
    post_kernel<<<(BT*HH)/8, 256>>>(yT, r_, k_, a_, vl, s_, v0, g_, faaaa,
                                    misc_a, ln_w, ln_b, z_h, z_l);

    // output projection directly into d_out
    hgemm<0><<<dim3(CC/128, BT/128), 256, HSMEM>>>(
        z_h, z_l, Wo_h, Wo_l, (float*)d_out, CC, CC, CC, nullptr);
}

// round 12
// speedup vs baseline: 3.5921x; 1.1706x over previous
#include <cuda_runtime.h>
#include <cuda_fp16.h>
#include <math.h>
#include <stdint.h>

// ---------------------------------------------------------------------------
// RWKV-7 Tmix forward. B=4, T=2048, C=2048, H=32, N=64.
// R12: fp16 2-MMA scheme: D = A_fp16 * (Bh + Bl), B split in fp16 (residual in
// subnormals). 33% fewer MMAs than bf16 3-term. Geometry = R9/R11 proven
// (128x128x32, 2-stage, 2 CTA/SM). Single stream.
// ---------------------------------------------------------------------------

#define BB 4
#define TT 2048
#define CC 2048
#define HH 32
#define NN 64
#define BT (BB*TT)                       // 8192
#define BTC ((size_t)BT*(size_t)CC)      // 16777216

__device__ float g_pool[23ull * 16777216ull];

#define SL_XR 0
#define SL_XW 1
#define SL_XK 2
#define SL_XV 3
#define SL_XA 4
#define SL_XG 5
#define SL_R  6
#define SL_K  7
#define SL_VL 8
#define SL_G  9
#define SL_WD 10
#define SL_A  11
#define SL_S  12
#define SL_Y  19
#define SL_ZS 20
#define SL_SMALL 21
#define SL_WB  22

// ===========================================================================
// helpers
// ===========================================================================
__device__ __forceinline__ uint32_t smem_u32(const void* p) {
    uint32_t a;
    asm("{ .reg .u64 t; cvta.to.shared.u64 t, %1; cvt.u32.u64 %0, t; }"
        : "=r"(a) : "l"(p));
    return a;
}
__device__ __forceinline__ void cpasync16(uint32_t dst, const void* src) {
    asm volatile("cp.async.cg.shared.global [%0], [%1], 16;" :: "r"(dst), "l"(src));
}
__device__ __forceinline__ void ldsm4(uint32_t* r, uint32_t addr) {
    asm volatile("ldmatrix.sync.aligned.m8n8.x4.shared.b16 {%0,%1,%2,%3}, [%4];"
        : "=r"(r[0]), "=r"(r[1]), "=r"(r[2]), "=r"(r[3]) : "r"(addr));
}
__device__ __forceinline__ void mma16816(float* d, const uint32_t* a, const uint32_t* b) {
    asm volatile(
        "mma.sync.aligned.m16n8k16.row.col.f32.f16.f16.f32 "
        "{%0,%1,%2,%3}, {%4,%5,%6,%7}, {%8,%9}, {%0,%1,%2,%3};"
        : "+f"(d[0]), "+f"(d[1]), "+f"(d[2]), "+f"(d[3])
        : "r"(a[0]), "r"(a[1]), "r"(a[2]), "r"(a[3]), "r"(b[0]), "r"(b[1]));
}
__device__ __forceinline__ uint32_t pack_h2(float a, float b) {
    __half2 t = __floats2half2_rn(a, b);
    return *reinterpret_cast<uint32_t*>(&t);
}

// EPI: 0=none, 3=sigmoid(v+bias[n]), 4=decay transform with bias[n]
__device__ __forceinline__ float epi_rt(int epi, float v, float b) {
    if (epi == 3) {
        return 1.f / (1.f + expf(-(v + b)));
    } else if (epi == 4) {
        float z  = v + b;
        float sp = (z < -20.f) ? (-z) : log1pf(expf(-z));
        float w  = -sp - 0.5f;
        return expf(-expf(w));
    }
    return v;
}

// ===========================================================================
// GEMM core: C[M,Ntot] = A_fp16[M,K(lda)] @ (Bh+Bl)[Ntot,K]^T, fp32 accum.
// CTA 128x128x32, 2-stage double buffer, warp 64x32 (2x4 warps), 2 CTAs/SM.
// ===========================================================================
#define PADK 40
#define TILE_B (128*PADK*2)              // 10240
#define STG_B  (3*TILE_B)                // 30720  (A, Bh, Bl)
#define HSTAGES 2
#define HSMEM  (HSTAGES*STG_B)           // 61440

template<int EPI_T>
__device__ __forceinline__ void hgemm_body(
    const __half* __restrict__ A,
    const __half* __restrict__ Bh, const __half* __restrict__ Bl,
    float* __restrict__ C, int K, int lda, int Ntot,
    const float* __restrict__ bias, int epi_rt_code, char* sm)
{
    const int tid  = threadIdx.x;
    const int lane = tid & 31;
    const int wid  = tid >> 5;
    const int m0 = blockIdx.y * 128;
    const int n0 = blockIdx.x * 128;
    const int mw = (wid >> 2) * 64;
    const int nw = (wid & 3) * 32;
    const uint32_t sbase = smem_u32(sm);
    const int KT = K >> 5;

    float acc[4][4][4];
#pragma unroll
    for (int mt = 0; mt < 4; mt++)
#pragma unroll
        for (int nt = 0; nt < 4; nt++)
#pragma unroll
            for (int q = 0; q < 4; q++) acc[mt][nt][q] = 0.f;

    auto issue = [&](int kt, int stage) {
        const int k0 = kt << 5;
        const uint32_t sdst = sbase + stage * STG_B;
#pragma unroll
        for (int u = 0; u < 6; u++) {
            int i  = tid + u * 256;         // 0..1535
            int op = i >> 9;                // 0=A, 1=Bh, 2=Bl
            int r  = (i >> 2) & 127;
            int c  = i & 3;
            const __half* src;
            if (op == 0)      src = A  + (size_t)(m0 + r) * lda + k0 + c * 8;
            else if (op == 1) src = Bh + (size_t)(n0 + r) * K + k0 + c * 8;
            else              src = Bl + (size_t)(n0 + r) * K + k0 + c * 8;
            cpasync16(sdst + op * TILE_B + r * (PADK*2) + c * 16, src);
        }
    };

    issue(0, 0);
    asm volatile("cp.async.commit_group;" ::: "memory");

    const int grp = lane >> 3;
    const int l7  = lane & 7;

    for (int kt = 0; kt < KT; kt++) {
        asm volatile("cp.async.wait_group 0;" ::: "memory");
        __syncthreads();

        if (kt + 1 < KT) issue(kt + 1, (kt + 1) & 1);
        asm volatile("cp.async.commit_group;" ::: "memory");

        const int st = kt & 1;
        const uint32_t sA  = sbase + st * STG_B;
        const uint32_t sBh = sA + TILE_B;
        const uint32_t sBl = sA + 2 * TILE_B;

#pragma unroll
        for (int kk = 0; kk < 2; kk++) {
            const int ko = kk * 16;
            uint32_t af[4][4];
#pragma unroll
            for (int mt = 0; mt < 4; mt++) {
                int row = mw + mt * 16 + ((grp & 1) << 3) + l7;
                int kof = ko + ((grp & 2) << 2);
                uint32_t a = row * (PADK*2) + kof * 2;
                ldsm4(af[mt], sA + a);
            }
#pragma unroll
            for (int np = 0; np < 2; np++) {
                int row = nw + np * 16 + ((grp >> 1) << 3) + l7;
                int kof = ko + ((grp & 1) << 3);
                uint32_t a = row * (PADK*2) + kof * 2;
                uint32_t th[4], tl[4];
                ldsm4(th, sBh + a);
                ldsm4(tl, sBl + a);
#pragma unroll
                for (int mt = 0; mt < 4; mt++) mma16816(acc[mt][np*2],   af[mt], th);
#pragma unroll
                for (int mt = 0; mt < 4; mt++) mma16816(acc[mt][np*2+1], af[mt], th + 2);
#pragma unroll
                for (int mt = 0; mt < 4; mt++) mma16816(acc[mt][np*2],   af[mt], tl);
#pragma unroll
                for (int mt = 0; mt < 4; mt++) mma16816(acc[mt][np*2+1], af[mt], tl + 2);
            }
        }
        __syncthreads();
    }

    const int r0 = lane >> 2;
    const int c0 = (lane & 3) * 2;
    const int epi = (EPI_T >= 0) ? EPI_T : epi_rt_code;
#pragma unroll
    for (int mt = 0; mt < 4; mt++) {
#pragma unroll
        for (int nt = 0; nt < 4; nt++) {
            int row = m0 + mw + mt * 16 + r0;
            int col = n0 + nw + nt * 8 + c0;
            float b0 = 0.f, b1 = 0.f;
            if (epi != 0) { b0 = bias[col]; b1 = bias[col + 1]; }
            float v0 = epi_rt(epi, acc[mt][nt][0], b0);
            float v1 = epi_rt(epi, acc[mt][nt][1], b1);
            float v2 = epi_rt(epi, acc[mt][nt][2], b0);
            float v3 = epi_rt(epi, acc[mt][nt][3], b1);
            *(float2*)(C + (size_t)row * Ntot + col)       = make_float2(v0, v1);
            *(float2*)(C + (size_t)(row + 8) * Ntot + col) = make_float2(v2, v3);
        }
    }
}

// single GEMM (Wo)
template<int EPI>
__global__ void __launch_bounds__(256, 2)
hgemm(const __half* __restrict__ A,
      const __half* __restrict__ Bh, const __half* __restrict__ Bl,
      float* __restrict__ C, int K, int lda, int Ntot, const float* __restrict__ bias)
{
    extern __shared__ char sm[];
    hgemm_body<EPI>(A, Bh, Bl, C, K, lda, Ntot, bias, EPI, sm);
}

// batched r/k/v projections: z selects operand set.
__global__ void __launch_bounds__(256, 2)
hgemm_batch3(const __half* A0, float* C0, const __half* A1, float* C1,
             const __half* A2, float* C2,
             const __half* Bh0, const __half* Bl0,
             const __half* Bh1, const __half* Bl1,
             const __half* Bh2, const __half* Bl2)
{
    extern __shared__ char sm[];
    const __half *A, *Bh, *Bl; float* C;
    if (blockIdx.z == 0)      { A=A0; Bh=Bh0; Bl=Bl0; C=C0; }
    else if (blockIdx.z == 1) { A=A1; Bh=Bh1; Bl=Bl1; C=C1; }
    else                      { A=A2; Bh=Bh2; Bl=Bl2; C=C2; }
    hgemm_body<0>(A, Bh, Bl, C, CC, CC, CC, nullptr, 0, sm);
}

// batched stage-2 (td/aaa/mv/gate)
#define HCATN 320
__global__ void __launch_bounds__(256, 2)
hgemm_s2(const __half* hcat,
         const __half* B0h, const __half* B0l,
         const __half* B1h, const __half* B1l,
         const __half* B2h, const __half* B2l,
         const __half* B3h, const __half* B3l,
         float* C0, float* C1, float* C2, float* C3,
         const float* bias0, const float* bias1, const float* bias2)
{
    extern __shared__ char sm[];
    int K, epi, aoff;
    const __half *Bh, *Bl; float* C; const float* bias;
    if (blockIdx.z == 0)      { K=64;  epi=4; aoff=0;   Bh=B0h; Bl=B0l; C=C0; bias=bias0; }
    else if (blockIdx.z == 1) { K=64;  epi=3; aoff=64;  Bh=B1h; Bl=B1l; C=C1; bias=bias1; }
    else if (blockIdx.z == 2) { K=32;  epi=3; aoff=256; Bh=B2h; Bl=B2l; C=C2; bias=bias2; }
    else                      { K=128; epi=0; aoff=128; Bh=B3h; Bl=B3l; C=C3; bias=nullptr; }
    hgemm_body<-1>(hcat + aoff, Bh, Bl, C, K, HCATN, CC, bias, epi, sm);
}

// ===========================================================================
// Stage-1 fused LoRA GEMM: 5 column segments of W1cat[320][2048].
// A single fp16, W1 split fp16. 3-stage, 2 CTAs/SM.
// ===========================================================================
#define S1_ATILE (128*PADK*2)            // 10240
#define S1_BTILE (64*PADK*2)             // 5120
#define S1_STG   (S1_ATILE + 2*S1_BTILE) // 20480
#define S1_SMEM  (3*S1_STG)              // 61440

__global__ void __launch_bounds__(256, 2)
hgemm_s1(const __half* __restrict__ xw, const __half* __restrict__ xa,
         const __half* __restrict__ xg, const __half* __restrict__ xv,
         const __half* __restrict__ W1h, const __half* __restrict__ W1l,
         __half* __restrict__ H)
{
    extern __shared__ char sm[];
    const int tid  = threadIdx.x;
    const int lane = tid & 31;
    const int wid  = tid >> 5;
    const int seg  = blockIdx.x;
    const int m0   = blockIdx.y * 128;
    const int n0w  = seg * 64;
    const uint32_t sbase = smem_u32(sm);

    const __half* A;
    if (seg == 0)      A = xw;
    else if (seg == 1) A = xa;
    else if (seg <= 3) A = xg;
    else               A = xv;

    const int mw = (wid >> 1) * 32;
    const int nw = (wid & 1) * 32;

    float acc[2][4][4];
#pragma unroll
    for (int mt = 0; mt < 2; mt++)
#pragma unroll
        for (int nt = 0; nt < 4; nt++)
#pragma unroll
            for (int q = 0; q < 4; q++) acc[mt][nt][q] = 0.f;

    auto issue = [&](int kt, int stage) {
        const int k0 = kt << 5;
        const uint32_t sdst = sbase + stage * S1_STG;
#pragma unroll
        for (int u = 0; u < 4; u++) {
            int i = tid + u * 256;          // 0..1023
            if (i < 512) {
                int r = i >> 2, c = i & 3;
                const __half* src = A + (size_t)(m0 + r) * CC + k0 + c * 8;
                cpasync16(sdst + r * (PADK*2) + c * 16, src);
            } else {
                int j = i - 512;
                int sp = j >> 8, r = (j >> 2) & 63, c = j & 3;
                const __half* src = (sp ? W1l : W1h) + (size_t)(n0w + r) * CC + k0 + c * 8;
                cpasync16(sdst + S1_ATILE + sp * S1_BTILE + r * (PADK*2) + c * 16, src);
            }
        }
    };

#pragma unroll
    for (int s = 0; s < 2; s++) {
        issue(s, s);
        asm volatile("cp.async.commit_group;" ::: "memory");
    }

    const int grp = lane >> 3;
    const int l7  = lane & 7;
    const int KT = CC >> 5;

    for (int kt = 0; kt < KT; kt++) {
        asm volatile("cp.async.wait_group 1;" ::: "memory");
        __syncthreads();

        const int st = kt % 3;
        const uint32_t sA  = sbase + st * S1_STG;
        const uint32_t sBh = sA + S1_ATILE;
        const uint32_t sBl = sBh + S1_BTILE;

#pragma unroll
        for (int kk = 0; kk < 2; kk++) {
            const int ko = kk * 16;
            uint32_t af[2][4];
#pragma unroll
            for (int mt = 0; mt < 2; mt++) {
                int row = mw + mt * 16 + ((grp & 1) << 3) + l7;
                int kof = ko + ((grp & 2) << 2);
                uint32_t a = row * (PADK*2) + kof * 2;
                ldsm4(af[mt], sA + a);
            }
#pragma unroll
            for (int np = 0; np < 2; np++) {
                int row = nw + np * 16 + ((grp >> 1) << 3) + l7;
                int kof = ko + ((grp & 1) << 3);
                uint32_t a = row * (PADK*2) + kof * 2;
                uint32_t th[4], tl[4];
                ldsm4(th, sBh + a);
                ldsm4(tl, sBl + a);
#pragma unroll
                for (int mt = 0; mt < 2; mt++) mma16816(acc[mt][np*2],   af[mt], th);
#pragma unroll
                for (int mt = 0; mt < 2; mt++) mma16816(acc[mt][np*2+1], af[mt], th + 2);
#pragma unroll
                for (int mt = 0; mt < 2; mt++) mma16816(acc[mt][np*2],   af[mt], tl);
#pragma unroll
                for (int mt = 0; mt < 2; mt++) mma16816(acc[mt][np*2+1], af[mt], tl + 2);
            }
        }

        int nkt = kt + 2;
        if (nkt < KT) issue(nkt, nkt % 3);
        asm volatile("cp.async.commit_group;" ::: "memory");
    }

    const int r0 = lane >> 2;
    const int c0 = (lane & 3) * 2;
#pragma unroll
    for (int mt = 0; mt < 2; mt++) {
#pragma unroll
        for (int nt = 0; nt < 4; nt++) {
            float v[4];
#pragma unroll
            for (int q = 0; q < 4; q++) {
                float t = acc[mt][nt][q];
                if (seg == 0)              t = tanhf(t);
                else if (seg == 2 || seg == 3) t = 1.f / (1.f + expf(-t));
                v[q] = t;
            }
            int row = m0 + mw + mt * 16 + r0;
            int col = seg * 64 + nw + nt * 8 + c0;
            *(uint32_t*)&H[(size_t)row * HCATN + col]     = pack_h2(v[0], v[1]);
            *(uint32_t*)&H[(size_t)(row+8) * HCATN + col] = pack_h2(v[2], v[3]);
        }
    }
}

// ===========================================================================
// Weight transpose + split: W[K][N] fp32 -> Th/Tl[N][K] fp16 (residual in Tl)
// ===========================================================================
__device__ __forceinline__ void transpose_body(const float* __restrict__ W,
                                               __half* __restrict__ Th,
                                               __half* __restrict__ Tl,
                                               int K, int N)
{
    __shared__ float tile[32][33];
    int bx = blockIdx.x * 32;
    int by = blockIdx.y * 32;
#pragma unroll
    for (int j = 0; j < 32; j += 8)
        tile[threadIdx.y + j][threadIdx.x] =
            W[(size_t)(by + threadIdx.y + j) * N + bx + threadIdx.x];
    __syncthreads();
#pragma unroll
    for (int j = 0; j < 32; j += 8) {
        float v = tile[threadIdx.x][threadIdx.y + j];
        int n = bx + threadIdx.y + j;
        int k = by + threadIdx.x;
        __half h = __float2half(v);
        Th[(size_t)n * K + k] = h;
        Tl[(size_t)n * K + k] = __float2half(v - __half2float(h));
    }
}

__global__ void transpose_split(const float* __restrict__ W,
                                __half* __restrict__ Th,
                                __half* __restrict__ Tl, int K, int N)
{
    transpose_body(W, Th, Tl, K, N);
}

__global__ void transpose_big4(const float* W0, const float* W1_, const float* W2_, const float* W3_,
                               __half* h0, __half* l0, __half* h1, __half* l1,
                               __half* h2, __half* l2, __half* h3, __half* l3)
{
    const float* W; __half *Th, *Tl;
    if (blockIdx.z == 0)      { W = W0;  Th = h0; Tl = l0; }
    else if (blockIdx.z == 1) { W = W1_; Th = h1; Tl = l1; }
    else if (blockIdx.z == 2) { W = W2_; Th = h2; Tl = l2; }
    else                      { W = W3_; Th = h3; Tl = l3; }
    transpose_body(W, Th, Tl, CC, CC);
}

// ---------------------------------------------------------------------------
// Token-shift mixing, single fp16 output per stream (A operand only).
// ---------------------------------------------------------------------------
__global__ void mix_split_kernel(const float* __restrict__ x,
    const float* __restrict__ mr, const float* __restrict__ mw,
    const float* __restrict__ mk, const float* __restrict__ mv,
    const float* __restrict__ ma, const float* __restrict__ mg,
    __half* __restrict__ xr, __half* __restrict__ xw,
    __half* __restrict__ xk, __half* __restrict__ xv,
    __half* __restrict__ xa, __half* __restrict__ xg)
{
    size_t i = (size_t)blockIdx.x * blockDim.x + threadIdx.x;
    size_t n4 = BTC / 4;
    if (i >= n4) return;
    size_t e = i * 4;
    int c  = (int)(e % CC);
    int bt = (int)(e / CC);
    int t  = bt % TT;

    float4 xc = ((const float4*)x)[i];
    float4 xp = make_float4(0.f, 0.f, 0.f, 0.f);
    if (t > 0) xp = ((const float4*)x)[i - CC/4];
    float4 xx = make_float4(xp.x-xc.x, xp.y-xc.y, xp.z-xc.z, xp.w-xc.w);

    int c4 = c / 4;
#define DOMIX(MV, OUT) { \
        float4 m = ((const float4*)MV)[c4]; \
        float4 o = make_float4(xc.x + xx.x*m.x, xc.y + xx.y*m.y, \
                               xc.z + xx.z*m.z, xc.w + xx.w*m.w); \
        ((uint2*)OUT)[i] = make_uint2(pack_h2(o.x, o.y), pack_h2(o.z, o.w)); }
    DOMIX(mr, xr); DOMIX(mw, xw); DOMIX(mk, xk);
    DOMIX(mv, xv); DOMIX(ma, xa); DOMIX(mg, xg);
#undef DOMIX
}

// ---------------------------------------------------------------------------
__device__ __forceinline__ float warp_sum(float v) {
#pragma unroll
    for (int o = 16; o > 0; o >>= 1) v += __shfl_xor_sync(0xffffffffu, v, o);
    return v;
}

// ---------------------------------------------------------------------------
// WKV7 recurrence with fused prep. 256 threads/block, one block per (b,h).
// ---------------------------------------------------------------------------
__global__ void __launch_bounds__(256)
wkv7_kernel(const float* __restrict__ r_,  const float* __restrict__ wd_,
            const float* __restrict__ k_,  const float* __restrict__ a_,
            const float* __restrict__ vl_, const float* __restrict__ s_,
            const float* __restrict__ v0_,
            const float* __restrict__ misc_kkk, const float* __restrict__ misc_a,
            float* __restrict__ yT)
{
    __shared__ __align__(16) float sb[2*392];
    const int bh  = blockIdx.x;
    const int b   = bh >> 5, h = bh & 31;
    const int tid = threadIdx.x;
    const int tg  = tid >> 6;
    const int n   = tid & 63;
    const int row = tid >> 2;
    const int cg  = tid & 3;
    const int cb  = cg * 16;
    const size_t src0  = ((size_t)b * TT) * CC + (size_t)h * NN + n;
    const size_t ybase = (size_t)bh * TT * NN;

    const float* pA;
    const float* pB = nullptr;
    const float* pC = nullptr;
    float ma = 0.f, mkk = 0.f;
    if (tg == 0)      pA = r_  + src0;
    else if (tg == 1) pA = wd_ + src0;
    else if (tg == 2) { pA = k_ + src0; pB = a_ + src0;
                        mkk = misc_kkk[h*NN+n]; ma = misc_a[h*NN+n]; }
    else              { pA = vl_ + src0; pB = s_ + src0; pC = v0_ + src0; }

    float st[16];
#pragma unroll
    for (int j = 0; j < 16; j++) st[j] = 0.f;

    {
        float va = pA[0];
        if (tg == 0)      sb[0*64+n] = va;
        else if (tg == 1) sb[1*64+n] = va;
        else if (tg == 2) {
            float vb = pB[0];
            float kk = va * mkk;
            sb[2*64+n] = va * fmaf(vb - 1.f, ma, 1.f);
            sb[4*64+n] = -kk;
            sb[5*64+n] = kk * vb;
            float wsum = warp_sum(kk*kk);
            if ((tid & 31) == 0) sb[384 + ((tid >> 5) & 1)] = wsum;
        } else {
            float vb = pB[0], vc = pC[0];
            sb[3*64+n] = va + (vc - va) * vb;
        }
    }
    __syncthreads();

    int cur = 0;
    for (int t = 0; t < TT; t++) {
        float fa = 0.f, fb = 0.f, fc = 0.f;
        if (t + 1 < TT) {
            size_t o = (size_t)(t + 1) * CC;
            fa = pA[o];
            if (tg >= 2) fb = pB[o];
            if (tg == 3) fc = pC[o];
        }

        const float* base = &sb[cur * 392];
        float ssq  = base[384] + base[385];
        float invn = 1.f / fmaxf(sqrtf(ssq), 1e-12f);
        float f2   = invn * invn;

        const float4* r4p = (const float4*)(base + 0*64 + cb);
        const float4* w4p = (const float4*)(base + 1*64 + cb);
        const float4* k4p = (const float4*)(base + 2*64 + cb);
        const float4* a4p = (const float4*)(base + 4*64 + cb);
        const float4* b4p = (const float4*)(base + 5*64 + cb);
        const float vi = base[3*64 + row];

        float c0=0.f, c1=0.f, c2=0.f, c3=0.f;
#pragma unroll
        for (int q = 0; q < 4; q++) {
            float4 a4 = a4p[q];
            c0 = fmaf(st[q*4+0], a4.x, c0);
            c1 = fmaf(st[q*4+1], a4.y, c1);
            c2 = fmaf(st[q*4+2], a4.z, c2);
            c3 = fmaf(st[q*4+3], a4.w, c3);
        }
        float sai = (c0 + c1) + (c2 + c3);
        sai += __shfl_xor_sync(0xffffffffu, sai, 1);
        sai += __shfl_xor_sync(0xffffffffu, sai, 2);
        sai *= f2;

        float y0=0.f, y1=0.f, y2=0.f, y3=0.f;
#pragma unroll
        for (int q = 0; q < 4; q++) {
            float4 w4 = w4p[q], b4 = b4p[q], k4 = k4p[q], r4 = r4p[q];
            float t0 = fmaf(sai, b4.x, fmaf(vi, k4.x, st[q*4+0]*w4.x));
            float t1 = fmaf(sai, b4.y, fmaf(vi, k4.y, st[q*4+1]*w4.y));
            float t2 = fmaf(sai, b4.z, fmaf(vi, k4.z, st[q*4+2]*w4.z));
            float t3 = fmaf(sai, b4.w, fmaf(vi, k4.w, st[q*4+3]*w4.w));
            st[q*4+0] = t0; st[q*4+1] = t1; st[q*4+2] = t2; st[q*4+3] = t3;
            y0 = fmaf(t0, r4.x, y0);
            y1 = fmaf(t1, r4.y, y1);
            y2 = fmaf(t2, r4.z, y2);
            y3 = fmaf(t3, r4.w, y3);
        }
        float yp = (y0 + y1) + (y2 + y3);
        yp += __shfl_xor_sync(0xffffffffu, yp, 1);
        yp += __shfl_xor_sync(0xffffffffu, yp, 2);
        if (cg == 0) yT[ybase + (size_t)t * NN + row] = yp;

        int nxt = cur ^ 1;
        if (t + 1 < TT) {
            float* d = &sb[nxt * 392];
            if (tg == 0)      d[0*64+n] = fa;
            else if (tg == 1) d[1*64+n] = fa;
            else if (tg == 2) {
                float kk = fa * mkk;
                d[2*64+n] = fa * fmaf(fb - 1.f, ma, 1.f);
                d[4*64+n] = -kk;
                d[5*64+n] = kk * fb;
                float wsum = warp_sum(kk*kk);
                if ((tid & 31) == 0) d[384 + ((tid >> 5) & 1)] = wsum;
            } else {
                d[3*64+n] = fa + (fc - fa) * fb;
            }
        }
        __syncthreads();
        cur = nxt;
    }
}

// ---------------------------------------------------------------------------
// GroupNorm + bonus + gate -> z single fp16
// ---------------------------------------------------------------------------
__global__ void post_kernel(const float* __restrict__ yT,
                            const float* __restrict__ r_, const float* __restrict__ k_,
                            const float* __restrict__ a_, const float* __restrict__ vl_,
                            const float* __restrict__ s_, const float* __restrict__ v0_,
                            const float* __restrict__ g,  const float* __restrict__ faaaa,
                            const float* __restrict__ misc_a,
                            const float* __restrict__ lnw, const float* __restrict__ lnb,
                            __half* __restrict__ z)
{
    int gw   = (blockIdx.x * blockDim.x + threadIdx.x) >> 5;
    int lane = threadIdx.x & 31;
    if (gw >= BT * HH) return;
    int h  = gw % HH;
    int bt = gw / HH;
    int b  = bt / TT, t = bt % TT;

    size_t src = (size_t)bt * CC + (size_t)h * NN;
    size_t dst = (((size_t)(b*HH + h)) * TT + t) * NN;
    int n0 = lane, n1 = lane + 32;
    int c0 = h*NN + n0, c1 = h*NN + n1;

    float y0 = yT[dst+n0], y1 = yT[dst+n1];
    float sum = warp_sum(y0 + y1);
    float sq  = warp_sum(y0*y0 + y1*y1);
    float mu  = sum * (1.f/64.f);
    float var = sq * (1.f/64.f) - mu*mu;
    float rs  = rsqrtf(var + 6.4e-4f);

    float k0 = k_[src+n0], k1 = k_[src+n1];
    float a0 = a_[src+n0], a1 = a_[src+n1];
    float fk0 = k0 * fmaf(a0 - 1.f, misc_a[c0], 1.f);
    float fk1 = k1 * fmaf(a1 - 1.f, misc_a[c1], 1.f);
    float rk = r_[src+n0]*fk0*faaaa[c0] + r_[src+n1]*fk1*faaaa[c1];
    float srk = warp_sum(rk);

    float vv0 = vl_[src+n0], vv1 = vl_[src+n1];
    float fv0 = vv0 + (v0_[src+n0] - vv0) * s_[src+n0];
    float fv1 = vv1 + (v0_[src+n1] - vv1) * s_[src+n1];

    float z0 = ((y0 - mu)*rs*lnw[c0] + lnb[c0] + srk*fv0) * g[src+n0];
    float z1 = ((y1 - mu)*rs*lnw[c1] + lnb[c1] + srk*fv1) * g[src+n1];
    z[src+n0] = __float2half(z0);
    z[src+n1] = __float2half(z1);
}

__global__ void copy4_kernel(const float* __restrict__ src, float* __restrict__ dst,
                             size_t n4)
{
    size_t i = (size_t)blockIdx.x * blockDim.x + threadIdx.x;
    if (i < n4) ((float4*)dst)[i] = ((const float4*)src)[i];
}

// ---------------------------------------------------------------------------
// launch (single stream)
// ---------------------------------------------------------------------------
extern "C" void kernel_launch(void* const* d_in, const int* in_sizes, int n_in,
                              void* d_out, int out_size)
{
    const float* x         = (const float*)d_in[0];
    const float* v0        = (const float*)d_in[1];
    const float* maa_r     = (const float*)d_in[2];
    const float* maa_w     = (const float*)d_in[3];
    const float* maa_k     = (const float*)d_in[4];
    const float* maa_v     = (const float*)d_in[5];
    const float* maa_a     = (const float*)d_in[6];
    const float* maa_g     = (const float*)d_in[7];
    const float* time_decay= (const float*)d_in[8];
    const float* faaaa     = (const float*)d_in[9];
    const float* time_aaaaa= (const float*)d_in[10];
    const float* td_w1     = (const float*)d_in[11];
    const float* td_w2     = (const float*)d_in[12];
    const float* aaa_w1    = (const float*)d_in[13];
    const float* aaa_w2    = (const float*)d_in[14];
    const float* gate_w1   = (const float*)d_in[15];
    const float* gate_w2   = (const float*)d_in[16];
    const float* mv_w1     = (const float*)d_in[17];
    const float* mv_w2     = (const float*)d_in[18];
    const float* misc_v    = (const float*)d_in[19];
    const float* misc_kkk  = (const float*)d_in[20];
    const float* misc_a    = (const float*)d_in[21];
    const float* Wr        = (const float*)d_in[22];
    const float* Wk        = (const float*)d_in[23];
    const float* Wv        = (const float*)d_in[24];
    const float* Wo        = (const float*)d_in[25];
    const float* ln_w      = (const float*)d_in[26];
    const float* ln_b      = (const float*)d_in[27];

    float* pool = nullptr;
    cudaGetSymbolAddress((void**)&pool, g_pool);

    __half* xr = (__half*)(pool + (size_t)SL_XR * BTC);
    __half* xw = (__half*)(pool + (size_t)SL_XW * BTC);
    __half* xk = (__half*)(pool + (size_t)SL_XK * BTC);
    __half* xv = (__half*)(pool + (size_t)SL_XV * BTC);
    __half* xa = (__half*)(pool + (size_t)SL_XA * BTC);
    __half* xg = (__half*)(pool + (size_t)SL_XG * BTC);

    float* r_ = pool + (size_t)SL_R  * BTC;
    float* k_ = pool + (size_t)SL_K  * BTC;
    float* vl = pool + (size_t)SL_VL * BTC;
    float* g_ = pool + (size_t)SL_G  * BTC;
    float* wd = pool + (size_t)SL_WD * BTC;
    float* a_ = pool + (size_t)SL_A  * BTC;
    float* s_ = pool + (size_t)SL_S  * BTC;
    float* yT = pool + (size_t)SL_Y  * BTC;
    __half* z_ = (__half*)(pool + (size_t)SL_ZS * BTC);

    __half* sb16 = (__half*)(pool + (size_t)SL_SMALL * BTC);
    __half* hcat   = sb16;                               // BT*320
    __half* W1h    = hcat + (size_t)BT * HCATN;          // 320*2048
    __half* W1l    = W1h + (size_t)HCATN * CC;
    __half* tdw_h  = W1l + (size_t)HCATN * CC;
    __half* tdw_l  = tdw_h  + (size_t)CC * 64;
    __half* aaaw_h = tdw_l  + (size_t)CC * 64;
    __half* aaaw_l = aaaw_h + (size_t)CC * 64;
    __half* gatew_h= aaaw_l + (size_t)CC * 64;
    __half* gatew_l= gatew_h+ (size_t)CC * 128;
    __half* mvw_h  = gatew_l+ (size_t)CC * 128;
    __half* mvw_l  = mvw_h  + (size_t)CC * 32;

    __half* wb = (__half*)(pool + (size_t)SL_WB * BTC);
    const size_t WSZ = (size_t)CC * CC;
    __half* Wr_h = wb;            __half* Wr_l = wb + WSZ;
    __half* Wk_h = wb + 2*WSZ;    __half* Wk_l = wb + 3*WSZ;
    __half* Wv_h = wb + 4*WSZ;    __half* Wv_l = wb + 5*WSZ;
    __half* Wo_h = wb + 6*WSZ;    __half* Wo_l = wb + 7*WSZ;

    cudaFuncSetAttribute(hgemm<0>, cudaFuncAttributeMaxDynamicSharedMemorySize, HSMEM);
    cudaFuncSetAttribute(hgemm_batch3, cudaFuncAttributeMaxDynamicSharedMemorySize, HSMEM);
    cudaFuncSetAttribute(hgemm_s2, cudaFuncAttributeMaxDynamicSharedMemorySize, HSMEM);
    cudaFuncSetAttribute(hgemm_s1, cudaFuncAttributeMaxDynamicSharedMemorySize, S1_SMEM);

    dim3 tb(32, 8);
    size_t n4 = BTC / 4;

    // k0: merged big weight transposes (Wr, Wk, Wv, Wo)
    transpose_big4<<<dim3(CC/32, CC/32, 4), tb>>>(
        Wr, Wk, Wv, Wo,
        Wr_h, Wr_l, Wk_h, Wk_l, Wv_h, Wv_l, Wo_h, Wo_l);

    // k1: token-shift mixing -> fp16
    mix_split_kernel<<<(unsigned)((n4 + 255) / 256), 256>>>(
        x, maa_r, maa_w, maa_k, maa_v, maa_a, maa_g,
        xr, xw, xk, xv, xa, xg);

    // k2: v0 passthrough into second output half
    if ((size_t)out_size >= 2 * BTC) {
        copy4_kernel<<<(unsigned)((n4 + 255) / 256), 256>>>(
            v0, (float*)d_out + BTC, n4);
    } else {
        copy4_kernel<<<1, 256>>>(v0, pool + (size_t)SL_R * BTC, 0);
    }

    // k3: merged big projections r/k/v  (ncu -s 5 lands here)
    hgemm_batch3<<<dim3(CC/128, BT/128, 3), 256, HSMEM>>>(
        xr, r_,  xk, k_,  xv, vl,
        Wr_h, Wr_l, Wk_h, Wk_l, Wv_h, Wv_l);

    // small weight transposes
    transpose_split<<<dim3(64/32,  CC/32), tb>>>(td_w1,   W1h,                 W1l,                 CC, 64);
    transpose_split<<<dim3(64/32,  CC/32), tb>>>(aaa_w1,  W1h + (size_t)64*CC, W1l + (size_t)64*CC, CC, 64);
    transpose_split<<<dim3(128/32, CC/32), tb>>>(gate_w1, W1h + (size_t)128*CC,W1l + (size_t)128*CC,CC, 128);
    transpose_split<<<dim3(32/32,  CC/32), tb>>>(mv_w1,   W1h + (size_t)256*CC,W1l + (size_t)256*CC,CC, 32);
    transpose_split<<<dim3(CC/32, 64/32),  tb>>>(td_w2,  tdw_h,  tdw_l,  64,  CC);
    transpose_split<<<dim3(CC/32, 64/32),  tb>>>(aaa_w2, aaaw_h, aaaw_l, 64,  CC);
    transpose_split<<<dim3(CC/32, 128/32), tb>>>(gate_w2,gatew_h,gatew_l,128, CC);
    transpose_split<<<dim3(CC/32, 32/32),  tb>>>(mv_w2,  mvw_h,  mvw_l,  32,  CC);

    // stage-1 fused LoRA GEMM
    hgemm_s1<<<dim3(5, BT/128), 256, S1_SMEM>>>(
        xw, xa, xg, xv, W1h, W1l, hcat);

    // merged stage-2 (td, aaa, mv, gate) -> wd, a_, s_, g_
    hgemm_s2<<<dim3(CC/128, BT/128, 4), 256, HSMEM>>>(
        hcat,
        tdw_h, tdw_l, aaaw_h, aaaw_l, mvw_h, mvw_l, gatew_h, gatew_l,
        wd, a_, s_, g_, time_decay, time_aaaaa, misc_v);

    // WKV7 recurrence (prep fused into staging)
    wkv7_kernel<<<BB*HH, 256>>>(r_, wd, k_, a_, vl, s_, v0, misc_kkk, misc_a, yT);

    // groupnorm + bonus + gate -> z fp16
    post_kernel<<<(BT*HH)/8, 256>>>(yT, r_, k_, a_, vl, s_, v0, g_, faaaa,
                                    misc_a, ln_w, ln_b, z_);

    // output projection directly into d_out
    hgemm<0><<<dim3(CC/128, BT/128), 256, HSMEM>>>(
        z_, Wo_h, Wo_l, (float*)d_out, CC, CC, CC, nullptr);
}

// round 13
// speedup vs baseline: 4.3034x; 1.1980x over previous
#include <cuda_runtime.h>
#include <cuda_fp16.h>
#include <math.h>
#include <stdint.h>

// ---------------------------------------------------------------------------
// RWKV-7 Tmix forward. B=4, T=2048, C=2048, H=32, N=64.
// R13: fp16 1-MMA GEMMs (A and B both single fp16, fp32 accum). Geometry =
// proven 128x128x32, 2-stage, 2 CTA/SM. Single stream.
// ---------------------------------------------------------------------------

#define BB 4
#define TT 2048
#define CC 2048
#define HH 32
#define NN 64
#define BT (BB*TT)                       // 8192
#define BTC ((size_t)BT*(size_t)CC)      // 16777216

__device__ float g_pool[23ull * 16777216ull];

#define SL_XR 0
#define SL_XW 1
#define SL_XK 2
#define SL_XV 3
#define SL_XA 4
#define SL_XG 5
#define SL_R  6
#define SL_K  7
#define SL_VL 8
#define SL_G  9
#define SL_WD 10
#define SL_A  11
#define SL_S  12
#define SL_Y  19
#define SL_ZS 20
#define SL_SMALL 21
#define SL_WB  22

// ===========================================================================
// helpers
// ===========================================================================
__device__ __forceinline__ uint32_t smem_u32(const void* p) {
    uint32_t a;
    asm("{ .reg .u64 t; cvta.to.shared.u64 t, %1; cvt.u32.u64 %0, t; }"
        : "=r"(a) : "l"(p));
    return a;
}
__device__ __forceinline__ void cpasync16(uint32_t dst, const void* src) {
    asm volatile("cp.async.cg.shared.global [%0], [%1], 16;" :: "r"(dst), "l"(src));
}
__device__ __forceinline__ void ldsm4(uint32_t* r, uint32_t addr) {
    asm volatile("ldmatrix.sync.aligned.m8n8.x4.shared.b16 {%0,%1,%2,%3}, [%4];"
        : "=r"(r[0]), "=r"(r[1]), "=r"(r[2]), "=r"(r[3]) : "r"(addr));
}
__device__ __forceinline__ void mma16816(float* d, const uint32_t* a, const uint32_t* b) {
    asm volatile(
        "mma.sync.aligned.m16n8k16.row.col.f32.f16.f16.f32 "
        "{%0,%1,%2,%3}, {%4,%5,%6,%7}, {%8,%9}, {%0,%1,%2,%3};"
        : "+f"(d[0]), "+f"(d[1]), "+f"(d[2]), "+f"(d[3])
        : "r"(a[0]), "r"(a[1]), "r"(a[2]), "r"(a[3]), "r"(b[0]), "r"(b[1]));
}
__device__ __forceinline__ uint32_t pack_h2(float a, float b) {
    __half2 t = __floats2half2_rn(a, b);
    return *reinterpret_cast<uint32_t*>(&t);
}

// EPI: 0=none, 3=sigmoid(v+bias[n]), 4=decay transform with bias[n]
__device__ __forceinline__ float epi_rt(int epi, float v, float b) {
    if (epi == 3) {
        return 1.f / (1.f + expf(-(v + b)));
    } else if (epi == 4) {
        float z  = v + b;
        float sp = (z < -20.f) ? (-z) : log1pf(expf(-z));
        float w  = -sp - 0.5f;
        return expf(-expf(w));
    }
    return v;
}

// ===========================================================================
// GEMM core: C[M,Ntot] = A_fp16[M,K(lda)] @ B_fp16[Ntot,K]^T, fp32 accum.
// CTA 128x128x32, 2-stage double buffer, warp 64x32 (2x4 warps), 2 CTAs/SM.
// ===========================================================================
#define PADK 40
#define TILE_B (128*PADK*2)              // 10240
#define STG_B  (2*TILE_B)                // 20480  (A, B)
#define HSTAGES 2
#define HSMEM  (HSTAGES*STG_B)           // 40960

template<int EPI_T>
__device__ __forceinline__ void hgemm_body(
    const __half* __restrict__ A, const __half* __restrict__ B,
    float* __restrict__ C, int K, int lda, int Ntot,
    const float* __restrict__ bias, int epi_rt_code, char* sm)
{
    const int tid  = threadIdx.x;
    const int lane = tid & 31;
    const int wid  = tid >> 5;
    const int m0 = blockIdx.y * 128;
    const int n0 = blockIdx.x * 128;
    const int mw = (wid >> 2) * 64;
    const int nw = (wid & 3) * 32;
    const uint32_t sbase = smem_u32(sm);
    const int KT = K >> 5;

    float acc[4][4][4];
#pragma unroll
    for (int mt = 0; mt < 4; mt++)
#pragma unroll
        for (int nt = 0; nt < 4; nt++)
#pragma unroll
            for (int q = 0; q < 4; q++) acc[mt][nt][q] = 0.f;

    auto issue = [&](int kt, int stage) {
        const int k0 = kt << 5;
        const uint32_t sdst = sbase + stage * STG_B;
#pragma unroll
        for (int u = 0; u < 4; u++) {
            int i  = tid + u * 256;         // 0..1023
            int op = i >> 9;                // 0=A, 1=B
            int r  = (i >> 2) & 127;
            int c  = i & 3;
            const __half* src = (op == 0)
                ? A + (size_t)(m0 + r) * lda + k0 + c * 8
                : B + (size_t)(n0 + r) * K   + k0 + c * 8;
            cpasync16(sdst + op * TILE_B + r * (PADK*2) + c * 16, src);
        }
    };

    issue(0, 0);
    asm volatile("cp.async.commit_group;" ::: "memory");

    const int grp = lane >> 3;
    const int l7  = lane & 7;

    for (int kt = 0; kt < KT; kt++) {
        asm volatile("cp.async.wait_group 0;" ::: "memory");
        __syncthreads();

        if (kt + 1 < KT) issue(kt + 1, (kt + 1) & 1);
        asm volatile("cp.async.commit_group;" ::: "memory");

        const int st = kt & 1;
        const uint32_t sA = sbase + st * STG_B;
        const uint32_t sB = sA + TILE_B;

#pragma unroll
        for (int kk = 0; kk < 2; kk++) {
            const int ko = kk * 16;
            uint32_t af[4][4];
#pragma unroll
            for (int mt = 0; mt < 4; mt++) {
                int row = mw + mt * 16 + ((grp & 1) << 3) + l7;
                int kof = ko + ((grp & 2) << 2);
                uint32_t a = row * (PADK*2) + kof * 2;
                ldsm4(af[mt], sA + a);
            }
#pragma unroll
            for (int np = 0; np < 2; np++) {
                int row = nw + np * 16 + ((grp >> 1) << 3) + l7;
                int kof = ko + ((grp & 1) << 3);
                uint32_t a = row * (PADK*2) + kof * 2;
                uint32_t tb[4];
                ldsm4(tb, sB + a);
#pragma unroll
                for (int mt = 0; mt < 4; mt++) mma16816(acc[mt][np*2],   af[mt], tb);
#pragma unroll
                for (int mt = 0; mt < 4; mt++) mma16816(acc[mt][np*2+1], af[mt], tb + 2);
            }
        }
        __syncthreads();
    }

    const int r0 = lane >> 2;
    const int c0 = (lane & 3) * 2;
    const int epi = (EPI_T >= 0) ? EPI_T : epi_rt_code;
#pragma unroll
    for (int mt = 0; mt < 4; mt++) {
#pragma unroll
        for (int nt = 0; nt < 4; nt++) {
            int row = m0 + mw + mt * 16 + r0;
            int col = n0 + nw + nt * 8 + c0;
            float b0 = 0.f, b1 = 0.f;
            if (epi != 0) { b0 = bias[col]; b1 = bias[col + 1]; }
            float v0 = epi_rt(epi, acc[mt][nt][0], b0);
            float v1 = epi_rt(epi, acc[mt][nt][1], b1);
            float v2 = epi_rt(epi, acc[mt][nt][2], b0);
            float v3 = epi_rt(epi, acc[mt][nt][3], b1);
            *(float2*)(C + (size_t)row * Ntot + col)       = make_float2(v0, v1);
            *(float2*)(C + (size_t)(row + 8) * Ntot + col) = make_float2(v2, v3);
        }
    }
}

// single GEMM (Wo)
template<int EPI>
__global__ void __launch_bounds__(256, 2)
hgemm(const __half* __restrict__ A, const __half* __restrict__ B,
      float* __restrict__ C, int K, int lda, int Ntot, const float* __restrict__ bias)
{
    extern __shared__ char sm[];
    hgemm_body<EPI>(A, B, C, K, lda, Ntot, bias, EPI, sm);
}

// batched r/k/v projections: z selects operand set.
__global__ void __launch_bounds__(256, 2)
hgemm_batch3(const __half* A0, float* C0, const __half* A1, float* C1,
             const __half* A2, float* C2,
             const __half* B0, const __half* B1, const __half* B2)
{
    extern __shared__ char sm[];
    const __half *A, *B; float* C;
    if (blockIdx.z == 0)      { A=A0; B=B0; C=C0; }
    else if (blockIdx.z == 1) { A=A1; B=B1; C=C1; }
    else                      { A=A2; B=B2; C=C2; }
    hgemm_body<0>(A, B, C, CC, CC, CC, nullptr, 0, sm);
}

// batched stage-2 (td/aaa/mv/gate)
#define HCATN 320
__global__ void __launch_bounds__(256, 2)
hgemm_s2(const __half* hcat,
         const __half* B0, const __half* B1, const __half* B2, const __half* B3,
         float* C0, float* C1, float* C2, float* C3,
         const float* bias0, const float* bias1, const float* bias2)
{
    extern __shared__ char sm[];
    int K, epi, aoff;
    const __half* B; float* C; const float* bias;
    if (blockIdx.z == 0)      { K=64;  epi=4; aoff=0;   B=B0; C=C0; bias=bias0; }
    else if (blockIdx.z == 1) { K=64;  epi=3; aoff=64;  B=B1; C=C1; bias=bias1; }
    else if (blockIdx.z == 2) { K=32;  epi=3; aoff=256; B=B2; C=C2; bias=bias2; }
    else                      { K=128; epi=0; aoff=128; B=B3; C=C3; bias=nullptr; }
    hgemm_body<-1>(hcat + aoff, B, C, K, HCATN, CC, bias, epi, sm);
}

// ===========================================================================
// Stage-1 fused LoRA GEMM: 5 column segments of W1cat[320][2048].
// A fp16, W1 fp16 (single). 3-stage, 2 CTAs/SM.
// ===========================================================================
#define S1_ATILE (128*PADK*2)            // 10240
#define S1_BTILE (64*PADK*2)             // 5120
#define S1_STG   (S1_ATILE + S1_BTILE)   // 15360
#define S1_SMEM  (3*S1_STG)              // 46080

__global__ void __launch_bounds__(256, 2)
hgemm_s1(const __half* __restrict__ xw, const __half* __restrict__ xa,
         const __half* __restrict__ xg, const __half* __restrict__ xv,
         const __half* __restrict__ W1, __half* __restrict__ H)
{
    extern __shared__ char sm[];
    const int tid  = threadIdx.x;
    const int lane = tid & 31;
    const int wid  = tid >> 5;
    const int seg  = blockIdx.x;
    const int m0   = blockIdx.y * 128;
    const int n0w  = seg * 64;
    const uint32_t sbase = smem_u32(sm);

    const __half* A;
    if (seg == 0)      A = xw;
    else if (seg == 1) A = xa;
    else if (seg <= 3) A = xg;
    else               A = xv;

    const int mw = (wid >> 1) * 32;
    const int nw = (wid & 1) * 32;

    float acc[2][4][4];
#pragma unroll
    for (int mt = 0; mt < 2; mt++)
#pragma unroll
        for (int nt = 0; nt < 4; nt++)
#pragma unroll
            for (int q = 0; q < 4; q++) acc[mt][nt][q] = 0.f;

    auto issue = [&](int kt, int stage) {
        const int k0 = kt << 5;
        const uint32_t sdst = sbase + stage * S1_STG;
#pragma unroll
        for (int u = 0; u < 3; u++) {
            int i = tid + u * 256;          // 0..767
            if (i < 512) {
                int r = i >> 2, c = i & 3;
                const __half* src = A + (size_t)(m0 + r) * CC + k0 + c * 8;
                cpasync16(sdst + r * (PADK*2) + c * 16, src);
            } else {
                int j = i - 512;
                int r = j >> 2, c = j & 3;  // r 0..63
                const __half* src = W1 + (size_t)(n0w + r) * CC + k0 + c * 8;
                cpasync16(sdst + S1_ATILE + r * (PADK*2) + c * 16, src);
            }
        }
    };

#pragma unroll
    for (int s = 0; s < 2; s++) {
        issue(s, s);
        asm volatile("cp.async.commit_group;" ::: "memory");
    }

    const int grp = lane >> 3;
    const int l7  = lane & 7;
    const int KT = CC >> 5;

    for (int kt = 0; kt < KT; kt++) {
        asm volatile("cp.async.wait_group 1;" ::: "memory");
        __syncthreads();

        const int st = kt % 3;
        const uint32_t sA = sbase + st * S1_STG;
        const uint32_t sB = sA + S1_ATILE;

#pragma unroll
        for (int kk = 0; kk < 2; kk++) {
            const int ko = kk * 16;
            uint32_t af[2][4];
#pragma unroll
            for (int mt = 0; mt < 2; mt++) {
                int row = mw + mt * 16 + ((grp & 1) << 3) + l7;
                int kof = ko + ((grp & 2) << 2);
                uint32_t a = row * (PADK*2) + kof * 2;
                ldsm4(af[mt], sA + a);
            }
#pragma unroll
            for (int np = 0; np < 2; np++) {
                int row = nw + np * 16 + ((grp >> 1) << 3) + l7;
                int kof = ko + ((grp & 1) << 3);
                uint32_t a = row * (PADK*2) + kof * 2;
                uint32_t tb[4];
                ldsm4(tb, sB + a);
#pragma unroll
                for (int mt = 0; mt < 2; mt++) mma16816(acc[mt][np*2],   af[mt], tb);
#pragma unroll
                for (int mt = 0; mt < 2; mt++) mma16816(acc[mt][np*2+1], af[mt], tb + 2);
            }
        }

        int nkt = kt + 2;
        if (nkt < KT) issue(nkt, nkt % 3);
        asm volatile("cp.async.commit_group;" ::: "memory");
    }

    const int r0 = lane >> 2;
    const int c0 = (lane & 3) * 2;
#pragma unroll
    for (int mt = 0; mt < 2; mt++) {
#pragma unroll
        for (int nt = 0; nt < 4; nt++) {
            float v[4];
#pragma unroll
            for (int q = 0; q < 4; q++) {
                float t = acc[mt][nt][q];
                if (seg == 0)              t = tanhf(t);
                else if (seg == 2 || seg == 3) t = 1.f / (1.f + expf(-t));
                v[q] = t;
            }
            int row = m0 + mw + mt * 16 + r0;
            int col = seg * 64 + nw + nt * 8 + c0;
            *(uint32_t*)&H[(size_t)row * HCATN + col]     = pack_h2(v[0], v[1]);
            *(uint32_t*)&H[(size_t)(row+8) * HCATN + col] = pack_h2(v[2], v[3]);
        }
    }
}

// ===========================================================================
// Weight transpose: W[K][N] fp32 -> T[N][K] fp16 (single)
// ===========================================================================
__device__ __forceinline__ void transpose_body(const float* __restrict__ W,
                                               __half* __restrict__ T,
                                               int K, int N)
{
    __shared__ float tile[32][33];
    int bx = blockIdx.x * 32;
    int by = blockIdx.y * 32;
#pragma unroll
    for (int j = 0; j < 32; j += 8)
        tile[threadIdx.y + j][threadIdx.x] =
            W[(size_t)(by + threadIdx.y + j) * N + bx + threadIdx.x];
    __syncthreads();
#pragma unroll
    for (int j = 0; j < 32; j += 8) {
        float v = tile[threadIdx.x][threadIdx.y + j];
        int n = bx + threadIdx.y + j;
        int k = by + threadIdx.x;
        T[(size_t)n * K + k] = __float2half(v);
    }
}

__global__ void transpose_split(const float* __restrict__ W,
                                __half* __restrict__ T, int K, int N)
{
    transpose_body(W, T, K, N);
}

__global__ void transpose_big4(const float* W0, const float* W1_, const float* W2_, const float* W3_,
                               __half* t0, __half* t1, __half* t2, __half* t3)
{
    const float* W; __half* T;
    if (blockIdx.z == 0)      { W = W0;  T = t0; }
    else if (blockIdx.z == 1) { W = W1_; T = t1; }
    else if (blockIdx.z == 2) { W = W2_; T = t2; }
    else                      { W = W3_; T = t3; }
    transpose_body(W, T, CC, CC);
}

// ---------------------------------------------------------------------------
// Token-shift mixing, single fp16 output per stream.
// ---------------------------------------------------------------------------
__global__ void mix_split_kernel(const float* __restrict__ x,
    const float* __restrict__ mr, const float* __restrict__ mw,
    const float* __restrict__ mk, const float* __restrict__ mv,
    const float* __restrict__ ma, const float* __restrict__ mg,
    __half* __restrict__ xr, __half* __restrict__ xw,
    __half* __restrict__ xk, __half* __restrict__ xv,
    __half* __restrict__ xa, __half* __restrict__ xg)
{
    size_t i = (size_t)blockIdx.x * blockDim.x + threadIdx.x;
    size_t n4 = BTC / 4;
    if (i >= n4) return;
    size_t e = i * 4;
    int c  = (int)(e % CC);
    int bt = (int)(e / CC);
    int t  = bt % TT;

    float4 xc = ((const float4*)x)[i];
    float4 xp = make_float4(0.f, 0.f, 0.f, 0.f);
    if (t > 0) xp = ((const float4*)x)[i - CC/4];
    float4 xx = make_float4(xp.x-xc.x, xp.y-xc.y, xp.z-xc.z, xp.w-xc.w);

    int c4 = c / 4;
#define DOMIX(MV, OUT) { \
        float4 m = ((const float4*)MV)[c4]; \
        float4 o = make_float4(xc.x + xx.x*m.x, xc.y + xx.y*m.y, \
                               xc.z + xx.z*m.z, xc.w + xx.w*m.w); \
        ((uint2*)OUT)[i] = make_uint2(pack_h2(o.x, o.y), pack_h2(o.z, o.w)); }
    DOMIX(mr, xr); DOMIX(mw, xw); DOMIX(mk, xk);
    DOMIX(mv, xv); DOMIX(ma, xa); DOMIX(mg, xg);
#undef DOMIX
}

// ---------------------------------------------------------------------------
__device__ __forceinline__ float warp_sum(float v) {
#pragma unroll
    for (int o = 16; o > 0; o >>= 1) v += __shfl_xor_sync(0xffffffffu, v, o);
    return v;
}

// ---------------------------------------------------------------------------
// WKV7 recurrence with fused prep. 256 threads/block, one block per (b,h).
// ---------------------------------------------------------------------------
__global__ void __launch_bounds__(256)
wkv7_kernel(const float* __restrict__ r_,  const float* __restrict__ wd_,
            const float* __restrict__ k_,  const float* __restrict__ a_,
            const float* __restrict__ vl_, const float* __restrict__ s_,
            const float* __restrict__ v0_,
            const float* __restrict__ misc_kkk, const float* __restrict__ misc_a,
            float* __restrict__ yT)
{
    __shared__ __align__(16) float sb[2*392];
    const int bh  = blockIdx.x;
    const int b   = bh >> 5, h = bh & 31;
    const int tid = threadIdx.x;
    const int tg  = tid >> 6;
    const int n   = tid & 63;
    const int row = tid >> 2;
    const int cg  = tid & 3;
    const int cb  = cg * 16;
    const size_t src0  = ((size_t)b * TT) * CC + (size_t)h * NN + n;
    const size_t ybase = (size_t)bh * TT * NN;

    const float* pA;
    const float* pB = nullptr;
    const float* pC = nullptr;
    float ma = 0.f, mkk = 0.f;
    if (tg == 0)      pA = r_  + src0;
    else if (tg == 1) pA = wd_ + src0;
    else if (tg == 2) { pA = k_ + src0; pB = a_ + src0;
                        mkk = misc_kkk[h*NN+n]; ma = misc_a[h*NN+n]; }
    else              { pA = vl_ + src0; pB = s_ + src0; pC = v0_ + src0; }

    float st[16];
#pragma unroll
    for (int j = 0; j < 16; j++) st[j] = 0.f;

    {
        float va = pA[0];
        if (tg == 0)      sb[0*64+n] = va;
        else if (tg == 1) sb[1*64+n] = va;
        else if (tg == 2) {
            float vb = pB[0];
            float kk = va * mkk;
            sb[2*64+n] = va * fmaf(vb - 1.f, ma, 1.f);
            sb[4*64+n] = -kk;
            sb[5*64+n] = kk * vb;
            float wsum = warp_sum(kk*kk);
            if ((tid & 31) == 0) sb[384 + ((tid >> 5) & 1)] = wsum;
        } else {
            float vb = pB[0], vc = pC[0];
            sb[3*64+n] = va + (vc - va) * vb;
        }
    }
    __syncthreads();

    int cur = 0;
    for (int t = 0; t < TT; t++) {
        float fa = 0.f, fb = 0.f, fc = 0.f;
        if (t + 1 < TT) {
            size_t o = (size_t)(t + 1) * CC;
            fa = pA[o];
            if (tg >= 2) fb = pB[o];
            if (tg == 3) fc = pC[o];
        }

        const float* base = &sb[cur * 392];
        float ssq  = base[384] + base[385];
        float invn = 1.f / fmaxf(sqrtf(ssq), 1e-12f);
        float f2   = invn * invn;

        const float4* r4p = (const float4*)(base + 0*64 + cb);
        const float4* w4p = (const float4*)(base + 1*64 + cb);
        const float4* k4p = (const float4*)(base + 2*64 + cb);
        const float4* a4p = (const float4*)(base + 4*64 + cb);
        const float4* b4p = (const float4*)(base + 5*64 + cb);
        const float vi = base[3*64 + row];

        float c0=0.f, c1=0.f, c2=0.f, c3=0.f;
#pragma unroll
        for (int q = 0; q < 4; q++) {
            float4 a4 = a4p[q];
            c0 = fmaf(st[q*4+0], a4.x, c0);
            c1 = fmaf(st[q*4+1], a4.y, c1);
            c2 = fmaf(st[q*4+2], a4.z, c2);
            c3 = fmaf(st[q*4+3], a4.w, c3);
        }
        float sai = (c0 + c1) + (c2 + c3);
        sai += __shfl_xor_sync(0xffffffffu, sai, 1);
        sai += __shfl_xor_sync(0xffffffffu, sai, 2);
        sai *= f2;

        float y0=0.f, y1=0.f, y2=0.f, y3=0.f;
#pragma unroll
        for (int q = 0; q < 4; q++) {
            float4 w4 = w4p[q], b4 = b4p[q], k4 = k4p[q], r4 = r4p[q];
            float t0 = fmaf(sai, b4.x, fmaf(vi, k4.x, st[q*4+0]*w4.x));
            float t1 = fmaf(sai, b4.y, fmaf(vi, k4.y, st[q*4+1]*w4.y));
            float t2 = fmaf(sai, b4.z, fmaf(vi, k4.z, st[q*4+2]*w4.z));
            float t3 = fmaf(sai, b4.w, fmaf(vi, k4.w, st[q*4+3]*w4.w));
            st[q*4+0] = t0; st[q*4+1] = t1; st[q*4+2] = t2; st[q*4+3] = t3;
            y0 = fmaf(t0, r4.x, y0);
            y1 = fmaf(t1, r4.y, y1);
            y2 = fmaf(t2, r4.z, y2);
            y3 = fmaf(t3, r4.w, y3);
        }
        float yp = (y0 + y1) + (y2 + y3);
        yp += __shfl_xor_sync(0xffffffffu, yp, 1);
        yp += __shfl_xor_sync(0xffffffffu, yp, 2);
        if (cg == 0) yT[ybase + (size_t)t * NN + row] = yp;

        int nxt = cur ^ 1;
        if (t + 1 < TT) {
            float* d = &sb[nxt * 392];
            if (tg == 0)      d[0*64+n] = fa;
            else if (tg == 1) d[1*64+n] = fa;
            else if (tg == 2) {
                float kk = fa * mkk;
                d[2*64+n] = fa * fmaf(fb - 1.f, ma, 1.f);
                d[4*64+n] = -kk;
                d[5*64+n] = kk * fb;
                float wsum = warp_sum(kk*kk);
                if ((tid & 31) == 0) d[384 + ((tid >> 5) & 1)] = wsum;
            } else {
                d[3*64+n] = fa + (fc - fa) * fb;
            }
        }
        __syncthreads();
        cur = nxt;
    }
}

// ---------------------------------------------------------------------------
// GroupNorm + bonus + gate -> z fp16
// ---------------------------------------------------------------------------
__global__ void post_kernel(const float* __restrict__ yT,
                            const float* __restrict__ r_, const float* __restrict__ k_,
                            const float* __restrict__ a_, const float* __restrict__ vl_,
                            const float* __restrict__ s_, const float* __restrict__ v0_,
                            const float* __restrict__ g,  const float* __restrict__ faaaa,
                            const float* __restrict__ misc_a,
                            const float* __restrict__ lnw, const float* __restrict__ lnb,
                            __half* __restrict__ z)
{
    int gw   = (blockIdx.x * blockDim.x + threadIdx.x) >> 5;
    int lane = threadIdx.x & 31;
    if (gw >= BT * HH) return;
    int h  = gw % HH;
    int bt = gw / HH;
    int b  = bt / TT, t = bt % TT;

    size_t src = (size_t)bt * CC + (size_t)h * NN;
    size_t dst = (((size_t)(b*HH + h)) * TT + t) * NN;
    int n0 = lane, n1 = lane + 32;
    int c0 = h*NN + n0, c1 = h*NN + n1;

    float y0 = yT[dst+n0], y1 = yT[dst+n1];
    float sum = warp_sum(y0 + y1);
    float sq  = warp_sum(y0*y0 + y1*y1);
    float mu  = sum * (1.f/64.f);
    float var = sq * (1.f/64.f) - mu*mu;
    float rs  = rsqrtf(var + 6.4e-4f);

    float k0 = k_[src+n0], k1 = k_[src+n1];
    float a0 = a_[src+n0], a1 = a_[src+n1];
    float fk0 = k0 * fmaf(a0 - 1.f, misc_a[c0], 1.f);
    float fk1 = k1 * fmaf(a1 - 1.f, misc_a[c1], 1.f);
    float rk = r_[src+n0]*fk0*faaaa[c0] + r_[src+n1]*fk1*faaaa[c1];
    float srk = warp_sum(rk);

    float vv0 = vl_[src+n0], vv1 = vl_[src+n1];
    float fv0 = vv0 + (v0_[src+n0] - vv0) * s_[src+n0];
    float fv1 = vv1 + (v0_[src+n1] - vv1) * s_[src+n1];

    float z0 = ((y0 - mu)*rs*lnw[c0] + lnb[c0] + srk*fv0) * g[src+n0];
    float z1 = ((y1 - mu)*rs*lnw[c1] + lnb[c1] + srk*fv1) * g[src+n1];
    z[src+n0] = __float2half(z0);
    z[src+n1] = __float2half(z1);
}

__global__ void copy4_kernel(const float* __restrict__ src, float* __restrict__ dst,
                             size_t n4)
{
    size_t i = (size_t)blockIdx.x * blockDim.x + threadIdx.x;
    if (i < n4) ((float4*)dst)[i] = ((const float4*)src)[i];
}

// ---------------------------------------------------------------------------
// launch (single stream)
// ---------------------------------------------------------------------------
extern "C" void kernel_launch(void* const* d_in, const int* in_sizes, int n_in,
                              void* d_out, int out_size)
{
    const float* x         = (const float*)d_in[0];
    const float* v0        = (const float*)d_in[1];
    const float* maa_r     = (const float*)d_in[2];
    const float* maa_w     = (const float*)d_in[3];
    const float* maa_k     = (const float*)d_in[4];
    const float* maa_v     = (const float*)d_in[5];
    const float* maa_a     = (const float*)d_in[6];
    const float* maa_g     = (const float*)d_in[7];
    const float* time_decay= (const float*)d_in[8];
    const float* faaaa     = (const float*)d_in[9];
    const float* time_aaaaa= (const float*)d_in[10];
    const float* td_w1     = (const float*)d_in[11];
    const float* td_w2     = (const float*)d_in[12];
    const float* aaa_w1    = (const float*)d_in[13];
    const float* aaa_w2    = (const float*)d_in[14];
    const float* gate_w1   = (const float*)d_in[15];
    const float* gate_w2   = (const float*)d_in[16];
    const float* mv_w1     = (const float*)d_in[17];
    const float* mv_w2     = (const float*)d_in[18];
    const float* misc_v    = (const float*)d_in[19];
    const float* misc_kkk  = (const float*)d_in[20];
    const float* misc_a    = (const float*)d_in[21];
    const float* Wr        = (const float*)d_in[22];
    const float* Wk        = (const float*)d_in[23];
    const float* Wv        = (const float*)d_in[24];
    const float* Wo        = (const float*)d_in[25];
    const float* ln_w      = (const float*)d_in[26];
    const float* ln_b      = (const float*)d_in[27];

    float* pool = nullptr;
    cudaGetSymbolAddress((void**)&pool, g_pool);

    __half* xr = (__half*)(pool + (size_t)SL_XR * BTC);
    __half* xw = (__half*)(pool + (size_t)SL_XW * BTC);
    __half* xk = (__half*)(pool + (size_t)SL_XK * BTC);
    __half* xv = (__half*)(pool + (size_t)SL_XV * BTC);
    __half* xa = (__half*)(pool + (size_t)SL_XA * BTC);
    __half* xg = (__half*)(pool + (size_t)SL_XG * BTC);

    float* r_ = pool + (size_t)SL_R  * BTC;
    float* k_ = pool + (size_t)SL_K  * BTC;
    float* vl = pool + (size_t)SL_VL * BTC;
    float* g_ = pool + (size_t)SL_G  * BTC;
    float* wd = pool + (size_t)SL_WD * BTC;
    float* a_ = pool + (size_t)SL_A  * BTC;
    float* s_ = pool + (size_t)SL_S  * BTC;
    float* yT = pool + (size_t)SL_Y  * BTC;
    __half* z_ = (__half*)(pool + (size_t)SL_ZS * BTC);

    __half* sb16 = (__half*)(pool + (size_t)SL_SMALL * BTC);
    __half* hcat  = sb16;                               // BT*320
    __half* W1    = hcat + (size_t)BT * HCATN;          // 320*2048
    __half* tdw   = W1   + (size_t)HCATN * CC;          // 2048*64
    __half* aaaw  = tdw  + (size_t)CC * 64;
    __half* gatew = aaaw + (size_t)CC * 64;             // 2048*128
    __half* mvw   = gatew+ (size_t)CC * 128;            // 2048*32

    __half* wb = (__half*)(pool + (size_t)SL_WB * BTC);
    const size_t WSZ = (size_t)CC * CC;
    __half* WrT = wb;
    __half* WkT = wb + WSZ;
    __half* WvT = wb + 2*WSZ;
    __half* WoT = wb + 3*WSZ;

    cudaFuncSetAttribute(hgemm<0>, cudaFuncAttributeMaxDynamicSharedMemorySize, HSMEM);
    cudaFuncSetAttribute(hgemm_batch3, cudaFuncAttributeMaxDynamicSharedMemorySize, HSMEM);
    cudaFuncSetAttribute(hgemm_s2, cudaFuncAttributeMaxDynamicSharedMemorySize, HSMEM);
    cudaFuncSetAttribute(hgemm_s1, cudaFuncAttributeMaxDynamicSharedMemorySize, S1_SMEM);

    dim3 tb(32, 8);
    size_t n4 = BTC / 4;

    // k0: merged big weight transposes (Wr, Wk, Wv, Wo)
    transpose_big4<<<dim3(CC/32, CC/32, 4), tb>>>(
        Wr, Wk, Wv, Wo, WrT, WkT, WvT, WoT);

    // k1: token-shift mixing -> fp16
    mix_split_kernel<<<(unsigned)((n4 + 255) / 256), 256>>>(
        x, maa_r, maa_w, maa_k, maa_v, maa_a, maa_g,
        xr, xw, xk, xv, xa, xg);

    // k2: v0 passthrough into second output half
    if ((size_t)out_size >= 2 * BTC) {
        copy4_kernel<<<(unsigned)((n4 + 255) / 256), 256>>>(
            v0, (float*)d_out + BTC, n4);
    } else {
        copy4_kernel<<<1, 256>>>(v0, pool + (size_t)SL_R * BTC, 0);
    }

    // k3: merged big projections r/k/v  (ncu -s 5 lands here)
    hgemm_batch3<<<dim3(CC/128, BT/128, 3), 256, HSMEM>>>(
        xr, r_,  xk, k_,  xv, vl, WrT, WkT, WvT);

    // small weight transposes
    transpose_split<<<dim3(64/32,  CC/32), tb>>>(td_w1,   W1,                 CC, 64);
    transpose_split<<<dim3(64/32,  CC/32), tb>>>(aaa_w1,  W1 + (size_t)64*CC, CC, 64);
    transpose_split<<<dim3(128/32, CC/32), tb>>>(gate_w1, W1 + (size_t)128*CC,CC, 128);
    transpose_split<<<dim3(32/32,  CC/32), tb>>>(mv_w1,   W1 + (size_t)256*CC,CC, 32);
    transpose_split<<<dim3(CC/32, 64/32),  tb>>>(td_w2,  tdw,  64,  CC);
    transpose_split<<<dim3(CC/32, 64/32),  tb>>>(aaa_w2, aaaw, 64,  CC);
    transpose_split<<<dim3(CC/32, 128/32), tb>>>(gate_w2,gatew,128, CC);
    transpose_split<<<dim3(CC/32, 32/32),  tb>>>(mv_w2,  mvw,  32,  CC);

    // stage-1 fused LoRA GEMM
    hgemm_s1<<<dim3(5, BT/128), 256, S1_SMEM>>>(
        xw, xa, xg, xv, W1, hcat);

    // merged stage-2 (td, aaa, mv, gate) -> wd, a_, s_, g_
    hgemm_s2<<<dim3(CC/128, BT/128, 4), 256, HSMEM>>>(
        hcat, tdw, aaaw, mvw, gatew,
        wd, a_, s_, g_, time_decay, time_aaaaa, misc_v);

    // WKV7 recurrence (prep fused into staging)
    wkv7_kernel<<<BB*HH, 256>>>(r_, wd, k_, a_, vl, s_, v0, misc_kkk, misc_a, yT);

    // groupnorm + bonus + gate -> z fp16
    post_kernel<<<(BT*HH)/8, 256>>>(yT, r_, k_, a_, vl, s_, v0, g_, faaaa,
                                    misc_a, ln_w, ln_b, z_);

    // output projection directly into d_out
    hgemm<0><<<dim3(CC/128, BT/128), 256, HSMEM>>>(
        z_, WoT, (float*)d_out, CC, CC, CC, nullptr);
}